// round 10
// baseline (speedup 1.0000x reference)
#include <cuda_runtime.h>

#define NODES 50000
#define NE    800000
#define HID   128
#define NPART 32
#define BN_EPS 1e-5f
#define SBLK  512
#define NSB   ((NODES + SBLK - 1) / SBLK)   // 98

typedef unsigned long long ull;

// ---------------- scratch (device globals; no runtime alloc) ----------------
__device__ float g_deg[NODES];
__device__ int   g_cnt[NODES];
__device__ int   g_off[NODES + 1];
__device__ int   g_cur[NODES];
__device__ float g_dinv[NODES];
__device__ int   g_aggv[NSB];
__device__ volatile int g_flag[NSB];
__device__ int2  g_csr[NE];                 // {src, float_as_int(norm)}
__device__ float g_hw[NODES * HID];
__device__ float g_agg[NODES * HID];
__device__ float g_stats[3 * 2 * HID];      // per layer: [0:128) sum, [128:256) sumsq
__device__ float g_base[HID];
__device__ float g_we[HID];

// ---------------- f32x2 helpers ----------------
__device__ __forceinline__ ull pk2(float lo, float hi) {
    ull r;
    asm("mov.b64 %0, {%1, %2};" : "=l"(r) : "f"(lo), "f"(hi));
    return r;
}
__device__ __forceinline__ void fma2(ull& d, ull a, ull b) {
    asm("fma.rn.f32x2 %0, %1, %2, %0;" : "+l"(d) : "l"(a), "l"(b));
}
__device__ __forceinline__ float2 upk2(ull v) {
    float2 f;
    asm("mov.b64 {%0, %1}, %2;" : "=f"(f.x), "=f"(f.y) : "l"(v));
    return f;
}
// ---------------- cp.async helpers ----------------
__device__ __forceinline__ void cpasync16(void* smem_ptr, const void* gptr) {
    unsigned s = (unsigned)__cvta_generic_to_shared(smem_ptr);
    asm volatile("cp.async.cg.shared.global [%0], [%1], 16;"
                 :: "r"(s), "l"(gptr) : "memory");
}
__device__ __forceinline__ void cpasync_commit() {
    asm volatile("cp.async.commit_group;" ::: "memory");
}
__device__ __forceinline__ void cpasync_wait_all() {
    asm volatile("cp.async.wait_group 0;" ::: "memory");
}
__device__ __forceinline__ void cpasync_wait_one() {
    asm volatile("cp.async.wait_group 1;" ::: "memory");
}

// ---------------- init ----------------
__global__ void zero_init_kernel(float* out) {
    int i = blockIdx.x * blockDim.x + threadIdx.x;
    if (i < NODES) { g_deg[i] = 0.f; g_cnt[i] = 0; g_cur[i] = 0; }
    if (i < NPART) out[i] = 0.f;
    if (i < 3 * 2 * HID) g_stats[i] = 0.f;
    if (i < NSB) g_flag[i] = 0;
}

// ---------------- degree + count ----------------
__global__ void deg_count_kernel(const int* __restrict__ ei,
                                 const float* __restrict__ ew) {
    int e = blockIdx.x * blockDim.x + threadIdx.x;
    if (e >= NE) return;
    int dst = ei[NE + e];
    atomicAdd(&g_deg[dst], ew[e]);
    atomicAdd(&g_cnt[dst], 1);
}

// ---------------- single-kernel scan (decoupled lookback) + dinv fused ----------------
__global__ __launch_bounds__(SBLK) void scan_kernel2() {
    __shared__ int ws[SBLK / 32];
    __shared__ int s_prefix;
    int t = threadIdx.x, lane = t & 31, w = t >> 5;
    int bid = blockIdx.x;
    int i = bid * SBLK + t;
    int v = (i < NODES) ? g_cnt[i] : 0;
    if (i < NODES) g_dinv[i] = rsqrtf(g_deg[i] + 1.0f);

    int inc = v;
    #pragma unroll
    for (int o = 1; o < 32; o <<= 1) {
        int u = __shfl_up_sync(0xffffffffu, inc, o);
        if (lane >= o) inc += u;
    }
    if (lane == 31) ws[w] = inc;
    __syncthreads();

    if (w == 0 && lane < SBLK / 32) {
        int x = ws[lane];
        int xi = x;
        #pragma unroll
        for (int o = 1; o < 16; o <<= 1) {
            int u = __shfl_up_sync(0x0000ffffu, xi, o);
            if (lane >= o) xi += u;
        }
        ws[lane] = xi - x;                 // exclusive warp offsets
        if (lane == SBLK / 32 - 1) {       // xi = block total
            g_aggv[bid] = xi;
            __threadfence();
            g_flag[bid] = 1;
        }
    }
    __syncthreads();

    if (w == 0) {
        int sum = 0;
        for (int base = 0; base < bid; base += 32) {
            int p = base + lane;
            int a = 0;
            if (p < bid) {
                while (g_flag[p] == 0) { }
                __threadfence();
                a = g_aggv[p];
            }
            #pragma unroll
            for (int o = 16; o; o >>= 1) a += __shfl_down_sync(0xffffffffu, a, o);
            if (lane == 0) sum += a;
        }
        if (lane == 0) s_prefix = sum;
    }
    __syncthreads();

    int pref = s_prefix;
    if (i < NODES) g_off[i] = pref + ws[w] + inc - v;
    if (bid == NSB - 1 && t == SBLK - 1) g_off[NODES] = pref + ws[w] + inc;
}

// ---------------- CSR fill (interleaved) ----------------
__global__ void csr_fill_kernel(const int* __restrict__ ei,
                                const float* __restrict__ ew) {
    int e = blockIdx.x * blockDim.x + threadIdx.x;
    if (e >= NE) return;
    int src = ei[e];
    int dst = ei[NE + e];
    int pos = g_off[dst] + atomicAdd(&g_cur[dst], 1);
    float norm = g_dinv[src] * ew[e] * g_dinv[dst];
    g_csr[pos] = make_int2(src, __float_as_int(norm));
}

// ==================== pipelined GEMM: triple-buffered B (wait_group 1) ====================
#define KC 16
#define NCHUNK (HID / KC)   // 8
__global__ __launch_bounds__(256) void gemm_kernel(
    const float* __restrict__ A, const float* __restrict__ W,
    const float* __restrict__ bias, int layer, int nrows)
{
    __shared__ float As[2][KC * 132];   // [k][row], padded
    __shared__ float Bs[3][KC * 128];   // [k][col], triple-buffered
    __shared__ float smean[HID], sscale[HID];
    const bool bn = (layer >= 0);
    const float* __restrict__ src = bn ? (const float*)g_agg : A;
    int tid = threadIdx.x;
    int tr = tid >> 4, tc = tid & 15;
    int row0 = blockIdx.x * 128;

    if (bn && tid < HID) {
        float m = g_stats[layer * 256 + tid] * (1.0f / NODES);
        float v = g_stats[layer * 256 + HID + tid] * (1.0f / NODES) - m * m;
        smean[tid]  = m;
        sscale[tid] = rsqrtf(v + BN_EPS);
    }

    int rA[2], k4A[2];
    bool okA[2];
    #pragma unroll
    for (int i = 0; i < 2; i++) {
        int slot = tid + i * 256;
        rA[i]  = slot >> 2;
        k4A[i] = slot & 3;
        okA[i] = (row0 + rA[i]) < nrows;
    }
    int kB[2], c4B[2];
    #pragma unroll
    for (int i = 0; i < 2; i++) {
        int slot = tid + i * 256;
        kB[i]  = slot >> 5;
        c4B[i] = slot & 31;
    }

    ull acc[4][8];
    #pragma unroll
    for (int i = 0; i < 4; i++)
        #pragma unroll
        for (int j = 0; j < 8; j++) acc[i][j] = 0ull;

    float4 pa[2];
    // ---- prologue: A chunk0 regs; B chunk0 + chunk1 in flight ----
    #pragma unroll
    for (int i = 0; i < 2; i++)
        pa[i] = okA[i]
              ? *(const float4*)(src + (size_t)(row0 + rA[i]) * HID + k4A[i] * 4)
              : make_float4(0.f, 0.f, 0.f, 0.f);
    #pragma unroll
    for (int i = 0; i < 2; i++)
        cpasync16(&Bs[0][kB[i] * 128 + c4B[i] * 4],
                  W + (size_t)kB[i] * HID + c4B[i] * 4);
    cpasync_commit();
    #pragma unroll
    for (int i = 0; i < 2; i++)
        cpasync16(&Bs[1][kB[i] * 128 + c4B[i] * 4],
                  W + (size_t)(KC + kB[i]) * HID + c4B[i] * 4);
    cpasync_commit();
    __syncthreads();   // smean/sscale visible
    // STS chunk 0 (with transform)
    #pragma unroll
    for (int i = 0; i < 2; i++) {
        float v4[4] = { pa[i].x, pa[i].y, pa[i].z, pa[i].w };
        #pragma unroll
        for (int j = 0; j < 4; j++) {
            float v = v4[j];
            if (bn) {
                int col = k4A[i] * 4 + j;
                v = fmaxf((v - smean[col]) * sscale[col], 0.f);
            }
            As[0][(k4A[i] * 4 + j) * 132 + rA[i]] = v;
        }
    }
    // LDG chunk 1
    #pragma unroll
    for (int i = 0; i < 2; i++)
        pa[i] = okA[i]
              ? *(const float4*)(src + (size_t)(row0 + rA[i]) * HID + KC + k4A[i] * 4)
              : make_float4(0.f, 0.f, 0.f, 0.f);

    // ---- main pipeline: B_c guaranteed done; B_{c+1} in flight; issue B_{c+2} ----
    #pragma unroll 1
    for (int c = 0; c < NCHUNK; c++) {
        if (c + 1 < NCHUNK) cpasync_wait_one();   // B_c done, B_{c+1} may fly
        else                cpasync_wait_all();   // last chunk: drain
        __syncthreads();                          // As[c&1] visible; old buffers free
        if (c + 2 < NCHUNK) {
            int b3 = (c + 2) % 3;
            #pragma unroll
            for (int i = 0; i < 2; i++)
                cpasync16(&Bs[b3][kB[i] * 128 + c4B[i] * 4],
                          W + (size_t)((c + 2) * KC + kB[i]) * HID + c4B[i] * 4);
            cpasync_commit();
        }
        if (c + 1 < NCHUNK) {
            int nb = (c + 1) & 1;
            #pragma unroll
            for (int i = 0; i < 2; i++) {
                float v4[4] = { pa[i].x, pa[i].y, pa[i].z, pa[i].w };
                #pragma unroll
                for (int j = 0; j < 4; j++) {
                    float v = v4[j];
                    if (bn) {
                        int col = (c + 1) * KC + k4A[i] * 4 + j;
                        v = fmaxf((v - smean[col]) * sscale[col], 0.f);
                    }
                    As[nb][(k4A[i] * 4 + j) * 132 + rA[i]] = v;
                }
            }
        }
        if (c + 2 < NCHUNK) {
            #pragma unroll
            for (int i = 0; i < 2; i++)
                pa[i] = okA[i]
                      ? *(const float4*)(src + (size_t)(row0 + rA[i]) * HID
                                         + (c + 2) * KC + k4A[i] * 4)
                      : make_float4(0.f, 0.f, 0.f, 0.f);
        }
        const float* as = As[c & 1];
        const float* bs = Bs[c % 3];
        #pragma unroll
        for (int k = 0; k < KC; k++) {
            float4 a0 = *(const float4*)(as + k * 132 + tr * 8);
            float4 a1 = *(const float4*)(as + k * 132 + tr * 8 + 4);
            float4 b0 = *(const float4*)(bs + k * 128 + tc * 8);
            float4 b1 = *(const float4*)(bs + k * 128 + tc * 8 + 4);
            ull ap[4] = { pk2(a0.x, a0.y), pk2(a0.z, a0.w),
                          pk2(a1.x, a1.y), pk2(a1.z, a1.w) };
            ull bd[8] = { pk2(b0.x, b0.x), pk2(b0.y, b0.y),
                          pk2(b0.z, b0.z), pk2(b0.w, b0.w),
                          pk2(b1.x, b1.x), pk2(b1.y, b1.y),
                          pk2(b1.z, b1.z), pk2(b1.w, b1.w) };
            #pragma unroll
            for (int i = 0; i < 4; i++)
                #pragma unroll
                for (int j = 0; j < 8; j++)
                    fma2(acc[i][j], ap[i], bd[j]);
        }
    }

    float bv[8];
    #pragma unroll
    for (int j = 0; j < 8; j++) bv[j] = bias[tc * 8 + j];
    #pragma unroll
    for (int i2 = 0; i2 < 4; i2++) {
        float2 v[8];
        #pragma unroll
        for (int j = 0; j < 8; j++) v[j] = upk2(acc[i2][j]);
        int r0 = row0 + tr * 8 + i2 * 2;
        if (r0 < nrows) {
            float4 o0 = make_float4(v[0].x + bv[0], v[1].x + bv[1],
                                    v[2].x + bv[2], v[3].x + bv[3]);
            float4 o1 = make_float4(v[4].x + bv[4], v[5].x + bv[5],
                                    v[6].x + bv[6], v[7].x + bv[7]);
            *(float4*)(g_hw + (size_t)r0 * HID + tc * 8)     = o0;
            *(float4*)(g_hw + (size_t)r0 * HID + tc * 8 + 4) = o1;
        }
        if (r0 + 1 < nrows) {
            float4 o0 = make_float4(v[0].y + bv[0], v[1].y + bv[1],
                                    v[2].y + bv[2], v[3].y + bv[3]);
            float4 o1 = make_float4(v[4].y + bv[4], v[5].y + bv[5],
                                    v[6].y + bv[6], v[7].y + bv[7]);
            *(float4*)(g_hw + (size_t)(r0 + 1) * HID + tc * 8)     = o0;
            *(float4*)(g_hw + (size_t)(r0 + 1) * HID + tc * 8 + 4) = o1;
        }
    }
}

// ---------------- aggregation (warp per node, gather unrolled x4) + BN stats ----------------
__global__ __launch_bounds__(256) void agg_kernel(int layer) {
    __shared__ float bsum[HID];
    __shared__ float bss[HID];
    int tid = threadIdx.x;
    for (int i = tid; i < HID; i += blockDim.x) { bsum[i] = 0.f; bss[i] = 0.f; }
    __syncthreads();

    int lane = tid & 31;
    int wglobal = (blockIdx.x * blockDim.x + tid) >> 5;
    int nwarps  = (gridDim.x * blockDim.x) >> 5;

    float ls0 = 0.f, ls1 = 0.f, ls2 = 0.f, ls3 = 0.f;
    float lq0 = 0.f, lq1 = 0.f, lq2 = 0.f, lq3 = 0.f;

    for (int n = wglobal; n < NODES; n += nwarps) {
        float dv = g_dinv[n];
        float sn = dv * dv;
        float4 a = ((const float4*)(g_hw + (size_t)n * HID))[lane];
        float4 acc = make_float4(a.x * sn, a.y * sn, a.z * sn, a.w * sn);
        int beg = g_off[n], end = g_off[n + 1];
        int i = beg;
        for (; i + 4 <= end; i += 4) {
            int2 e0 = g_csr[i],     e1 = g_csr[i + 1];
            int2 e2 = g_csr[i + 2], e3 = g_csr[i + 3];
            float w0 = __int_as_float(e0.y), w1 = __int_as_float(e1.y);
            float w2 = __int_as_float(e2.y), w3 = __int_as_float(e3.y);
            float4 v0 = ((const float4*)(g_hw + (size_t)e0.x * HID))[lane];
            float4 v1 = ((const float4*)(g_hw + (size_t)e1.x * HID))[lane];
            float4 v2 = ((const float4*)(g_hw + (size_t)e2.x * HID))[lane];
            float4 v3 = ((const float4*)(g_hw + (size_t)e3.x * HID))[lane];
            acc.x += w0 * v0.x + w1 * v1.x + w2 * v2.x + w3 * v3.x;
            acc.y += w0 * v0.y + w1 * v1.y + w2 * v2.y + w3 * v3.y;
            acc.z += w0 * v0.z + w1 * v1.z + w2 * v2.z + w3 * v3.z;
            acc.w += w0 * v0.w + w1 * v1.w + w2 * v2.w + w3 * v3.w;
        }
        for (; i + 2 <= end; i += 2) {
            int2 e0 = g_csr[i], e1 = g_csr[i + 1];
            float w0 = __int_as_float(e0.y), w1 = __int_as_float(e1.y);
            float4 v0 = ((const float4*)(g_hw + (size_t)e0.x * HID))[lane];
            float4 v1 = ((const float4*)(g_hw + (size_t)e1.x * HID))[lane];
            acc.x += w0 * v0.x + w1 * v1.x;
            acc.y += w0 * v0.y + w1 * v1.y;
            acc.z += w0 * v0.z + w1 * v1.z;
            acc.w += w0 * v0.w + w1 * v1.w;
        }
        if (i < end) {
            int2 e0 = g_csr[i];
            float w = __int_as_float(e0.y);
            float4 v = ((const float4*)(g_hw + (size_t)e0.x * HID))[lane];
            acc.x += w * v.x; acc.y += w * v.y;
            acc.z += w * v.z; acc.w += w * v.w;
        }
        ((float4*)(g_agg + (size_t)n * HID))[lane] = acc;
        ls0 += acc.x; ls1 += acc.y; ls2 += acc.z; ls3 += acc.w;
        lq0 += acc.x * acc.x; lq1 += acc.y * acc.y;
        lq2 += acc.z * acc.z; lq3 += acc.w * acc.w;
    }
    int c = lane * 4;
    atomicAdd(&bsum[c + 0], ls0); atomicAdd(&bsum[c + 1], ls1);
    atomicAdd(&bsum[c + 2], ls2); atomicAdd(&bsum[c + 3], ls3);
    atomicAdd(&bss[c + 0], lq0);  atomicAdd(&bss[c + 1], lq1);
    atomicAdd(&bss[c + 2], lq2);  atomicAdd(&bss[c + 3], lq3);
    __syncthreads();
    for (int i = tid; i < HID; i += blockDim.x) {
        atomicAdd(&g_stats[layer * 256 + i],       bsum[i]);
        atomicAdd(&g_stats[layer * 256 + HID + i], bss[i]);
    }
}

// ---------------- prep split: g_we has NO dependencies -> overlapped early ----------------
__global__ void prep_we_kernel(const float* __restrict__ l1w) {
    int j = threadIdx.x;   // 128
    float we = 0.f;
    #pragma unroll 8
    for (int k = 2 * HID; k < 4 * HID; k++)
        we += l1w[(size_t)k * HID + j];
    g_we[j] = we;
}

__global__ void prep_base_kernel(const float* __restrict__ l1w,
                                 const float* __restrict__ l1b,
                                 const int* __restrict__ curr) {
    __shared__ float xs[HID];
    int j = threadIdx.x;   // 128
    int c = *curr;
    float m = g_stats[2 * 256 + j] * (1.0f / NODES);
    float v = g_stats[2 * 256 + HID + j] * (1.0f / NODES) - m * m;
    float sc = rsqrtf(v + BN_EPS);
    xs[j] = fmaxf((g_agg[(size_t)c * HID + j] - m) * sc, 0.f);
    __syncthreads();
    float acc = 0.f;
    #pragma unroll 8
    for (int k = 0; k < HID; k++)
        acc += xs[k] * l1w[(size_t)(HID + k) * HID + j];
    g_base[j] = l1b[j] + acc;
}

// ==================== pipelined scoring: triple-buffered B ====================
__global__ __launch_bounds__(256, 2) void score_kernel(
    const float* __restrict__ W,    // lin1_w rows 0..127
    const float* __restrict__ l2w, const float* __restrict__ l2b,
    const float* __restrict__ ecn, const float* __restrict__ parts,
    float* __restrict__ h, float* __restrict__ out)
{
    __shared__ float As[2][KC * 132];
    __shared__ float Bs[3][KC * 128];
    __shared__ float smean[HID], sscale[HID];
    __shared__ float sarr[128];
    __shared__ float pp[NPART];
    int tid = threadIdx.x;
    int tr = tid >> 4, tc = tid & 15;
    int row0 = blockIdx.x * 128;

    if (tid < HID) {
        float m = g_stats[2 * 256 + tid] * (1.0f / NODES);
        float v = g_stats[2 * 256 + HID + tid] * (1.0f / NODES) - m * m;
        smean[tid]  = m;
        sscale[tid] = rsqrtf(v + BN_EPS);
    }

    int rA[2], k4A[2];
    bool okA[2];
    #pragma unroll
    for (int i = 0; i < 2; i++) {
        int slot = tid + i * 256;
        rA[i]  = slot >> 2;
        k4A[i] = slot & 3;
        okA[i] = (row0 + rA[i]) < NODES;
    }
    int kB[2], c4B[2];
    #pragma unroll
    for (int i = 0; i < 2; i++) {
        int slot = tid + i * 256;
        kB[i]  = slot >> 5;
        c4B[i] = slot & 31;
    }

    ull acc[4][8];
    #pragma unroll
    for (int i = 0; i < 4; i++)
        #pragma unroll
        for (int j = 0; j < 8; j++) acc[i][j] = 0ull;

    float4 pa[2];
    #pragma unroll
    for (int i = 0; i < 2; i++)
        pa[i] = okA[i]
              ? *(const float4*)(g_agg + (size_t)(row0 + rA[i]) * HID + k4A[i] * 4)
              : make_float4(0.f, 0.f, 0.f, 0.f);
    #pragma unroll
    for (int i = 0; i < 2; i++)
        cpasync16(&Bs[0][kB[i] * 128 + c4B[i] * 4],
                  W + (size_t)kB[i] * HID + c4B[i] * 4);
    cpasync_commit();
    #pragma unroll
    for (int i = 0; i < 2; i++)
        cpasync16(&Bs[1][kB[i] * 128 + c4B[i] * 4],
                  W + (size_t)(KC + kB[i]) * HID + c4B[i] * 4);
    cpasync_commit();
    __syncthreads();   // smean/sscale ready
    #pragma unroll
    for (int i = 0; i < 2; i++) {
        float v4[4] = { pa[i].x, pa[i].y, pa[i].z, pa[i].w };
        float o4[4];
        #pragma unroll
        for (int j = 0; j < 4; j++) {
            int col = k4A[i] * 4 + j;
            o4[j] = fmaxf((v4[j] - smean[col]) * sscale[col], 0.f);
            As[0][col * 132 + rA[i]] = o4[j];
        }
        if (okA[i])
            *(float4*)(h + (size_t)(row0 + rA[i]) * HID + k4A[i] * 4) =
                make_float4(o4[0], o4[1], o4[2], o4[3]);
    }
    #pragma unroll
    for (int i = 0; i < 2; i++)
        pa[i] = okA[i]
              ? *(const float4*)(g_agg + (size_t)(row0 + rA[i]) * HID + KC + k4A[i] * 4)
              : make_float4(0.f, 0.f, 0.f, 0.f);

    #pragma unroll 1
    for (int c = 0; c < NCHUNK; c++) {
        if (c + 1 < NCHUNK) cpasync_wait_one();
        else                cpasync_wait_all();
        __syncthreads();
        if (c + 2 < NCHUNK) {
            int b3 = (c + 2) % 3;
            #pragma unroll
            for (int i = 0; i < 2; i++)
                cpasync16(&Bs[b3][kB[i] * 128 + c4B[i] * 4],
                          W + (size_t)((c + 2) * KC + kB[i]) * HID + c4B[i] * 4);
            cpasync_commit();
        }
        if (c + 1 < NCHUNK) {
            int nb = (c + 1) & 1;
            #pragma unroll
            for (int i = 0; i < 2; i++) {
                float v4[4] = { pa[i].x, pa[i].y, pa[i].z, pa[i].w };
                float o4[4];
                #pragma unroll
                for (int j = 0; j < 4; j++) {
                    int col = (c + 1) * KC + k4A[i] * 4 + j;
                    o4[j] = fmaxf((v4[j] - smean[col]) * sscale[col], 0.f);
                    As[nb][(k4A[i] * 4 + j) * 132 + rA[i]] = o4[j];
                }
                if (okA[i])
                    *(float4*)(h + (size_t)(row0 + rA[i]) * HID
                               + (c + 1) * KC + k4A[i] * 4) =
                        make_float4(o4[0], o4[1], o4[2], o4[3]);
            }
        }
        if (c + 2 < NCHUNK) {
            #pragma unroll
            for (int i = 0; i < 2; i++)
                pa[i] = okA[i]
                      ? *(const float4*)(g_agg + (size_t)(row0 + rA[i]) * HID
                                         + (c + 2) * KC + k4A[i] * 4)
                      : make_float4(0.f, 0.f, 0.f, 0.f);
        }
        const float* as = As[c & 1];
        const float* bs = Bs[c % 3];
        #pragma unroll
        for (int k = 0; k < KC; k++) {
            float4 a0 = *(const float4*)(as + k * 132 + tr * 8);
            float4 a1 = *(const float4*)(as + k * 132 + tr * 8 + 4);
            float4 b0 = *(const float4*)(bs + k * 128 + tc * 8);
            float4 b1 = *(const float4*)(bs + k * 128 + tc * 8 + 4);
            ull ap[4] = { pk2(a0.x, a0.y), pk2(a0.z, a0.w),
                          pk2(a1.x, a1.y), pk2(a1.z, a1.w) };
            ull bd[8] = { pk2(b0.x, b0.x), pk2(b0.y, b0.y),
                          pk2(b0.z, b0.z), pk2(b0.w, b0.w),
                          pk2(b1.x, b1.x), pk2(b1.y, b1.y),
                          pk2(b1.z, b1.z), pk2(b1.w, b1.w) };
            #pragma unroll
            for (int i = 0; i < 4; i++)
                #pragma unroll
                for (int j = 0; j < 8; j++)
                    fma2(acc[i][j], ap[i], bd[j]);
        }
    }

    float w2[8], bb[8], wev[8];
    #pragma unroll
    for (int j = 0; j < 8; j++) {
        w2[j]  = l2w[tc * 8 + j];
        bb[j]  = g_base[tc * 8 + j];
        wev[j] = g_we[tc * 8 + j];
    }
    float b2 = l2b[0];
    #pragma unroll
    for (int i2 = 0; i2 < 4; i2++) {
        float2 v[8];
        #pragma unroll
        for (int j = 0; j < 8; j++) v[j] = upk2(acc[i2][j]);
        #pragma unroll
        for (int half = 0; half < 2; half++) {
            int row = row0 + tr * 8 + i2 * 2 + half;
            float e = (row < NODES) ? ecn[row] : 0.f;
            float s = 0.f;
            #pragma unroll
            for (int j = 0; j < 8; j++) {
                float val = half ? v[j].y : v[j].x;
                float t = val + bb[j] + e * wev[j];
                s += fmaxf(t, 0.f) * w2[j];
            }
            s += __shfl_xor_sync(0xffffffffu, s, 8, 16);
            s += __shfl_xor_sync(0xffffffffu, s, 4, 16);
            s += __shfl_xor_sync(0xffffffffu, s, 2, 16);
            s += __shfl_xor_sync(0xffffffffu, s, 1, 16);
            if (tc == 0) sarr[tr * 8 + i2 * 2 + half] = (row < NODES) ? (s + b2) : 0.f;
        }
    }
    if (tid < NPART) pp[tid] = 0.f;
    __syncthreads();
    int p = tid & 31, g = tid >> 5;
    float psum = 0.f;
    for (int r = g * 16; r < g * 16 + 16; r++) {
        int row = row0 + r;
        if (row < NODES) psum += sarr[r] * parts[(size_t)row * NPART + p];
    }
    atomicAdd(&pp[p], psum);
    __syncthreads();
    if (tid < NPART) atomicAdd(&out[tid], pp[tid]);
}

// ---------------- launcher ----------------
extern "C" void kernel_launch(void* const* d_in, const int* in_sizes, int n_in,
                              void* d_out, int out_size) {
    const float* x      = (const float*)d_in[0];
    const int*   ei     = (const int*)d_in[1];
    const float* ew     = (const float*)d_in[2];
    const float* parts  = (const float*)d_in[3];
    // d_in[4] = node_weights (unused by reference)
    const float* ecn    = (const float*)d_in[5];
    const float* conv_w = (const float*)d_in[6];
    const float* conv_b = (const float*)d_in[7];
    const float* l1w    = (const float*)d_in[8];
    const float* l1b    = (const float*)d_in[9];
    const float* l2w    = (const float*)d_in[10];
    const float* l2b    = (const float*)d_in[11];
    const int*   curr   = (const int*)d_in[12];

    float* out = (float*)d_out;          // [0:32) partition scores
    float* h   = out + NPART;            // [32 : 32+N*H) final h

    cudaStream_t sG;
    cudaStreamCreateWithFlags(&sG, cudaStreamNonBlocking);
    cudaEvent_t evFork, evJoin;
    cudaEventCreateWithFlags(&evFork, cudaEventDisableTiming);
    cudaEventCreateWithFlags(&evJoin, cudaEventDisableTiming);

    const int gemm_blocks = (NODES + 127) / 128;   // 391
    const int agg_blocks  = 1184;

    cudaEventRecord(evFork, 0);
    cudaStreamWaitEvent(sG, evFork, 0);

    // ---- setup chain on default stream; gemm0 is the 4th created node -> ncu target ----
    zero_init_kernel<<<(NODES + 255) / 256, 256>>>(out);         // 1
    deg_count_kernel<<<(NE + 255) / 256, 256>>>(ei, ew);         // 2
    scan_kernel2<<<NSB, SBLK>>>();                               // 3
    gemm_kernel<<<gemm_blocks, 256, 0, sG>>>(x, conv_w, conv_b, -1, NODES);  // 4 <- ncu
    prep_we_kernel<<<1, 128, 0, sG>>>(l1w);                      // 5
    csr_fill_kernel<<<(NE + 255) / 256, 256>>>(ei, ew);          // 6

    cudaEventRecord(evJoin, sG);
    cudaStreamWaitEvent(0, evJoin, 0);

    agg_kernel<<<agg_blocks, 256>>>(0);
    gemm_kernel<<<gemm_blocks, 256>>>(nullptr, conv_w + 1 * HID * HID,
                                      conv_b + 1 * HID, 0, NODES);
    agg_kernel<<<agg_blocks, 256>>>(1);
    gemm_kernel<<<gemm_blocks, 256>>>(nullptr, conv_w + 2 * HID * HID,
                                      conv_b + 2 * HID, 1, NODES);
    agg_kernel<<<agg_blocks, 256>>>(2);

    prep_base_kernel<<<1, 128>>>(l1w, l1b, curr);
    score_kernel<<<gemm_blocks, 256>>>(l1w, l2w, l2b, ecn, parts, h, out);
}

// round 11
// speedup vs baseline: 1.0003x; 1.0003x over previous
#include <cuda_runtime.h>

#define NODES 50000
#define NE    800000
#define HID   128
#define NPART 32
#define BN_EPS 1e-5f
#define SBLK  512
#define NSB   ((NODES + SBLK - 1) / SBLK)   // 98

typedef unsigned long long ull;

// ---------------- scratch (device globals; no runtime alloc) ----------------
__device__ float g_deg[NODES];
__device__ int   g_cnt[NODES];
__device__ int   g_off[NODES + 1];
__device__ int   g_cur[NODES];
__device__ float g_dinv[NODES];
__device__ int   g_aggv[NSB];
__device__ volatile int g_flag[NSB];
__device__ int2  g_csr[NE];                 // {src, float_as_int(norm)}
__device__ float g_hw[NODES * HID];
__device__ float g_agg[NODES * HID];
__device__ float g_stats[3 * 2 * HID];      // per layer: [0:128) sum, [128:256) sumsq
__device__ float g_we[HID];

// ---------------- f32x2 helpers ----------------
__device__ __forceinline__ ull pk2(float lo, float hi) {
    ull r;
    asm("mov.b64 %0, {%1, %2};" : "=l"(r) : "f"(lo), "f"(hi));
    return r;
}
__device__ __forceinline__ void fma2(ull& d, ull a, ull b) {
    asm("fma.rn.f32x2 %0, %1, %2, %0;" : "+l"(d) : "l"(a), "l"(b));
}
__device__ __forceinline__ float2 upk2(ull v) {
    float2 f;
    asm("mov.b64 {%0, %1}, %2;" : "=f"(f.x), "=f"(f.y) : "l"(v));
    return f;
}
// ---------------- cp.async helpers ----------------
__device__ __forceinline__ void cpasync16(void* smem_ptr, const void* gptr) {
    unsigned s = (unsigned)__cvta_generic_to_shared(smem_ptr);
    asm volatile("cp.async.cg.shared.global [%0], [%1], 16;"
                 :: "r"(s), "l"(gptr) : "memory");
}
__device__ __forceinline__ void cpasync_commit() {
    asm volatile("cp.async.commit_group;" ::: "memory");
}
__device__ __forceinline__ void cpasync_wait_all() {
    asm volatile("cp.async.wait_group 0;" ::: "memory");
}

// ---------------- init ----------------
__global__ void zero_init_kernel(float* out) {
    int i = blockIdx.x * blockDim.x + threadIdx.x;
    if (i < NODES) { g_deg[i] = 0.f; g_cnt[i] = 0; g_cur[i] = 0; }
    if (i < NPART) out[i] = 0.f;
    if (i < 3 * 2 * HID) g_stats[i] = 0.f;
    if (i < NSB) g_flag[i] = 0;
}

// ---------------- degree + count ----------------
__global__ void deg_count_kernel(const int* __restrict__ ei,
                                 const float* __restrict__ ew) {
    int e = blockIdx.x * blockDim.x + threadIdx.x;
    if (e >= NE) return;
    int dst = ei[NE + e];
    atomicAdd(&g_deg[dst], ew[e]);
    atomicAdd(&g_cnt[dst], 1);
}

// ---------------- single-kernel scan (decoupled lookback) + dinv fused ----------------
__global__ __launch_bounds__(SBLK) void scan_kernel2() {
    __shared__ int ws[SBLK / 32];
    __shared__ int s_prefix;
    int t = threadIdx.x, lane = t & 31, w = t >> 5;
    int bid = blockIdx.x;
    int i = bid * SBLK + t;
    int v = (i < NODES) ? g_cnt[i] : 0;
    if (i < NODES) g_dinv[i] = rsqrtf(g_deg[i] + 1.0f);

    int inc = v;
    #pragma unroll
    for (int o = 1; o < 32; o <<= 1) {
        int u = __shfl_up_sync(0xffffffffu, inc, o);
        if (lane >= o) inc += u;
    }
    if (lane == 31) ws[w] = inc;
    __syncthreads();

    if (w == 0 && lane < SBLK / 32) {
        int x = ws[lane];
        int xi = x;
        #pragma unroll
        for (int o = 1; o < 16; o <<= 1) {
            int u = __shfl_up_sync(0x0000ffffu, xi, o);
            if (lane >= o) xi += u;
        }
        ws[lane] = xi - x;                 // exclusive warp offsets
        if (lane == SBLK / 32 - 1) {       // xi = block total
            g_aggv[bid] = xi;
            __threadfence();
            g_flag[bid] = 1;
        }
    }
    __syncthreads();

    if (w == 0) {
        int sum = 0;
        for (int base = 0; base < bid; base += 32) {
            int p = base + lane;
            int a = 0;
            if (p < bid) {
                while (g_flag[p] == 0) { }
                __threadfence();
                a = g_aggv[p];
            }
            #pragma unroll
            for (int o = 16; o; o >>= 1) a += __shfl_down_sync(0xffffffffu, a, o);
            if (lane == 0) sum += a;
        }
        if (lane == 0) s_prefix = sum;
    }
    __syncthreads();

    int pref = s_prefix;
    if (i < NODES) g_off[i] = pref + ws[w] + inc - v;
    if (bid == NSB - 1 && t == SBLK - 1) g_off[NODES] = pref + ws[w] + inc;
}

// ---------------- CSR fill (interleaved) ----------------
__global__ void csr_fill_kernel(const int* __restrict__ ei,
                                const float* __restrict__ ew) {
    int e = blockIdx.x * blockDim.x + threadIdx.x;
    if (e >= NE) return;
    int src = ei[e];
    int dst = ei[NE + e];
    int pos = g_off[dst] + atomicAdd(&g_cur[dst], 1);
    float norm = g_dinv[src] * ew[e] * g_dinv[dst];
    g_csr[pos] = make_int2(src, __float_as_int(norm));
}

// ==================== pipelined GEMM (R9-proven: double-buffered, wait_group 0) ====================
#define KC 16
#define NCHUNK (HID / KC)   // 8
__global__ __launch_bounds__(256) void gemm_kernel(
    const float* __restrict__ A, const float* __restrict__ W,
    const float* __restrict__ bias, int layer, int nrows)
{
    __shared__ float As[2][KC * 132];   // [k][row], padded
    __shared__ float Bs[2][KC * 128];   // [k][col]
    __shared__ float smean[HID], sscale[HID];
    const bool bn = (layer >= 0);
    const float* __restrict__ src = bn ? (const float*)g_agg : A;
    int tid = threadIdx.x;
    int tr = tid >> 4, tc = tid & 15;
    int row0 = blockIdx.x * 128;

    if (bn && tid < HID) {
        float m = g_stats[layer * 256 + tid] * (1.0f / NODES);
        float v = g_stats[layer * 256 + HID + tid] * (1.0f / NODES) - m * m;
        smean[tid]  = m;
        sscale[tid] = rsqrtf(v + BN_EPS);
    }

    int rA[2], k4A[2];
    bool okA[2];
    #pragma unroll
    for (int i = 0; i < 2; i++) {
        int slot = tid + i * 256;
        rA[i]  = slot >> 2;
        k4A[i] = slot & 3;
        okA[i] = (row0 + rA[i]) < nrows;
    }
    int kB[2], c4B[2];
    #pragma unroll
    for (int i = 0; i < 2; i++) {
        int slot = tid + i * 256;
        kB[i]  = slot >> 5;
        c4B[i] = slot & 31;
    }

    ull acc[4][8];
    #pragma unroll
    for (int i = 0; i < 4; i++)
        #pragma unroll
        for (int j = 0; j < 8; j++) acc[i][j] = 0ull;

    float4 pa[2];
    #pragma unroll
    for (int i = 0; i < 2; i++)
        pa[i] = okA[i]
              ? *(const float4*)(src + (size_t)(row0 + rA[i]) * HID + k4A[i] * 4)
              : make_float4(0.f, 0.f, 0.f, 0.f);
    #pragma unroll
    for (int i = 0; i < 2; i++)
        cpasync16(&Bs[0][kB[i] * 128 + c4B[i] * 4],
                  W + (size_t)kB[i] * HID + c4B[i] * 4);
    cpasync_commit();
    __syncthreads();
    #pragma unroll
    for (int i = 0; i < 2; i++) {
        float v4[4] = { pa[i].x, pa[i].y, pa[i].z, pa[i].w };
        #pragma unroll
        for (int j = 0; j < 4; j++) {
            float v = v4[j];
            if (bn) {
                int col = k4A[i] * 4 + j;
                v = fmaxf((v - smean[col]) * sscale[col], 0.f);
            }
            As[0][(k4A[i] * 4 + j) * 132 + rA[i]] = v;
        }
    }
    #pragma unroll
    for (int i = 0; i < 2; i++)
        pa[i] = okA[i]
              ? *(const float4*)(src + (size_t)(row0 + rA[i]) * HID + KC + k4A[i] * 4)
              : make_float4(0.f, 0.f, 0.f, 0.f);

    #pragma unroll 1
    for (int c = 0; c < NCHUNK; c++) {
        cpasync_wait_all();
        __syncthreads();
        int nb = (c + 1) & 1;
        if (c + 1 < NCHUNK) {
            #pragma unroll
            for (int i = 0; i < 2; i++)
                cpasync16(&Bs[nb][kB[i] * 128 + c4B[i] * 4],
                          W + (size_t)((c + 1) * KC + kB[i]) * HID + c4B[i] * 4);
            cpasync_commit();
            #pragma unroll
            for (int i = 0; i < 2; i++) {
                float v4[4] = { pa[i].x, pa[i].y, pa[i].z, pa[i].w };
                #pragma unroll
                for (int j = 0; j < 4; j++) {
                    float v = v4[j];
                    if (bn) {
                        int col = (c + 1) * KC + k4A[i] * 4 + j;
                        v = fmaxf((v - smean[col]) * sscale[col], 0.f);
                    }
                    As[nb][(k4A[i] * 4 + j) * 132 + rA[i]] = v;
                }
            }
        }
        if (c + 2 < NCHUNK) {
            #pragma unroll
            for (int i = 0; i < 2; i++)
                pa[i] = okA[i]
                      ? *(const float4*)(src + (size_t)(row0 + rA[i]) * HID
                                         + (c + 2) * KC + k4A[i] * 4)
                      : make_float4(0.f, 0.f, 0.f, 0.f);
        }
        const float* as = As[c & 1];
        const float* bs = Bs[c & 1];
        #pragma unroll
        for (int k = 0; k < KC; k++) {
            float4 a0 = *(const float4*)(as + k * 132 + tr * 8);
            float4 a1 = *(const float4*)(as + k * 132 + tr * 8 + 4);
            float4 b0 = *(const float4*)(bs + k * 128 + tc * 8);
            float4 b1 = *(const float4*)(bs + k * 128 + tc * 8 + 4);
            ull ap[4] = { pk2(a0.x, a0.y), pk2(a0.z, a0.w),
                          pk2(a1.x, a1.y), pk2(a1.z, a1.w) };
            ull bd[8] = { pk2(b0.x, b0.x), pk2(b0.y, b0.y),
                          pk2(b0.z, b0.z), pk2(b0.w, b0.w),
                          pk2(b1.x, b1.x), pk2(b1.y, b1.y),
                          pk2(b1.z, b1.z), pk2(b1.w, b1.w) };
            #pragma unroll
            for (int i = 0; i < 4; i++)
                #pragma unroll
                for (int j = 0; j < 8; j++)
                    fma2(acc[i][j], ap[i], bd[j]);
        }
    }

    float bv[8];
    #pragma unroll
    for (int j = 0; j < 8; j++) bv[j] = bias[tc * 8 + j];
    #pragma unroll
    for (int i2 = 0; i2 < 4; i2++) {
        float2 v[8];
        #pragma unroll
        for (int j = 0; j < 8; j++) v[j] = upk2(acc[i2][j]);
        int r0 = row0 + tr * 8 + i2 * 2;
        if (r0 < nrows) {
            float4 o0 = make_float4(v[0].x + bv[0], v[1].x + bv[1],
                                    v[2].x + bv[2], v[3].x + bv[3]);
            float4 o1 = make_float4(v[4].x + bv[4], v[5].x + bv[5],
                                    v[6].x + bv[6], v[7].x + bv[7]);
            *(float4*)(g_hw + (size_t)r0 * HID + tc * 8)     = o0;
            *(float4*)(g_hw + (size_t)r0 * HID + tc * 8 + 4) = o1;
        }
        if (r0 + 1 < nrows) {
            float4 o0 = make_float4(v[0].y + bv[0], v[1].y + bv[1],
                                    v[2].y + bv[2], v[3].y + bv[3]);
            float4 o1 = make_float4(v[4].y + bv[4], v[5].y + bv[5],
                                    v[6].y + bv[6], v[7].y + bv[7]);
            *(float4*)(g_hw + (size_t)(r0 + 1) * HID + tc * 8)     = o0;
            *(float4*)(g_hw + (size_t)(r0 + 1) * HID + tc * 8 + 4) = o1;
        }
    }
}

// ---------------- aggregation (warp per node, gather unrolled x4) + BN stats ----------------
__global__ __launch_bounds__(256) void agg_kernel(int layer) {
    __shared__ float bsum[HID];
    __shared__ float bss[HID];
    int tid = threadIdx.x;
    for (int i = tid; i < HID; i += blockDim.x) { bsum[i] = 0.f; bss[i] = 0.f; }
    __syncthreads();

    int lane = tid & 31;
    int wglobal = (blockIdx.x * blockDim.x + tid) >> 5;
    int nwarps  = (gridDim.x * blockDim.x) >> 5;

    float ls0 = 0.f, ls1 = 0.f, ls2 = 0.f, ls3 = 0.f;
    float lq0 = 0.f, lq1 = 0.f, lq2 = 0.f, lq3 = 0.f;

    for (int n = wglobal; n < NODES; n += nwarps) {
        float dv = g_dinv[n];
        float sn = dv * dv;
        float4 a = ((const float4*)(g_hw + (size_t)n * HID))[lane];
        float4 acc = make_float4(a.x * sn, a.y * sn, a.z * sn, a.w * sn);
        int beg = g_off[n], end = g_off[n + 1];
        int i = beg;
        for (; i + 4 <= end; i += 4) {
            int2 e0 = g_csr[i],     e1 = g_csr[i + 1];
            int2 e2 = g_csr[i + 2], e3 = g_csr[i + 3];
            float w0 = __int_as_float(e0.y), w1 = __int_as_float(e1.y);
            float w2 = __int_as_float(e2.y), w3 = __int_as_float(e3.y);
            float4 v0 = ((const float4*)(g_hw + (size_t)e0.x * HID))[lane];
            float4 v1 = ((const float4*)(g_hw + (size_t)e1.x * HID))[lane];
            float4 v2 = ((const float4*)(g_hw + (size_t)e2.x * HID))[lane];
            float4 v3 = ((const float4*)(g_hw + (size_t)e3.x * HID))[lane];
            acc.x += w0 * v0.x + w1 * v1.x + w2 * v2.x + w3 * v3.x;
            acc.y += w0 * v0.y + w1 * v1.y + w2 * v2.y + w3 * v3.y;
            acc.z += w0 * v0.z + w1 * v1.z + w2 * v2.z + w3 * v3.z;
            acc.w += w0 * v0.w + w1 * v1.w + w2 * v2.w + w3 * v3.w;
        }
        for (; i + 2 <= end; i += 2) {
            int2 e0 = g_csr[i], e1 = g_csr[i + 1];
            float w0 = __int_as_float(e0.y), w1 = __int_as_float(e1.y);
            float4 v0 = ((const float4*)(g_hw + (size_t)e0.x * HID))[lane];
            float4 v1 = ((const float4*)(g_hw + (size_t)e1.x * HID))[lane];
            acc.x += w0 * v0.x + w1 * v1.x;
            acc.y += w0 * v0.y + w1 * v1.y;
            acc.z += w0 * v0.z + w1 * v1.z;
            acc.w += w0 * v0.w + w1 * v1.w;
        }
        if (i < end) {
            int2 e0 = g_csr[i];
            float w = __int_as_float(e0.y);
            float4 v = ((const float4*)(g_hw + (size_t)e0.x * HID))[lane];
            acc.x += w * v.x; acc.y += w * v.y;
            acc.z += w * v.z; acc.w += w * v.w;
        }
        ((float4*)(g_agg + (size_t)n * HID))[lane] = acc;
        ls0 += acc.x; ls1 += acc.y; ls2 += acc.z; ls3 += acc.w;
        lq0 += acc.x * acc.x; lq1 += acc.y * acc.y;
        lq2 += acc.z * acc.z; lq3 += acc.w * acc.w;
    }
    int c = lane * 4;
    atomicAdd(&bsum[c + 0], ls0); atomicAdd(&bsum[c + 1], ls1);
    atomicAdd(&bsum[c + 2], ls2); atomicAdd(&bsum[c + 3], ls3);
    atomicAdd(&bss[c + 0], lq0);  atomicAdd(&bss[c + 1], lq1);
    atomicAdd(&bss[c + 2], lq2);  atomicAdd(&bss[c + 3], lq3);
    __syncthreads();
    for (int i = tid; i < HID; i += blockDim.x) {
        atomicAdd(&g_stats[layer * 256 + i],       bsum[i]);
        atomicAdd(&g_stats[layer * 256 + HID + i], bss[i]);
    }
}

// ---------------- prep_we: no dependencies -> overlapped early on sG ----------------
__global__ void prep_we_kernel(const float* __restrict__ l1w) {
    int j = threadIdx.x;   // 128
    float we = 0.f;
    #pragma unroll 8
    for (int k = 2 * HID; k < 4 * HID; k++)
        we += l1w[(size_t)k * HID + j];
    g_we[j] = we;
}

// ==================== pipelined scoring: base[] computed in-block (no prep_base launch) ====================
__global__ __launch_bounds__(256, 2) void score_kernel(
    const float* __restrict__ W,    // lin1_w (rows 0..127 used for GEMM; rows 128..255 for base)
    const float* __restrict__ l1b,
    const float* __restrict__ l2w, const float* __restrict__ l2b,
    const float* __restrict__ ecn, const float* __restrict__ parts,
    const int* __restrict__ curr,
    float* __restrict__ h, float* __restrict__ out)
{
    __shared__ float As[2][KC * 132];
    __shared__ float Bs[2][KC * 128];
    __shared__ float smean[HID], sscale[HID];
    __shared__ float xs[HID];
    __shared__ float sbase[HID];
    __shared__ float sarr[128];
    __shared__ float pp[NPART];
    int tid = threadIdx.x;
    int tr = tid >> 4, tc = tid & 15;
    int row0 = blockIdx.x * 128;

    if (tid < HID) {
        float m = g_stats[2 * 256 + tid] * (1.0f / NODES);
        float v = g_stats[2 * 256 + HID + tid] * (1.0f / NODES) - m * m;
        smean[tid]  = m;
        sscale[tid] = rsqrtf(v + BN_EPS);
    }

    int rA[2], k4A[2];
    bool okA[2];
    #pragma unroll
    for (int i = 0; i < 2; i++) {
        int slot = tid + i * 256;
        rA[i]  = slot >> 2;
        k4A[i] = slot & 3;
        okA[i] = (row0 + rA[i]) < NODES;
    }
    int kB[2], c4B[2];
    #pragma unroll
    for (int i = 0; i < 2; i++) {
        int slot = tid + i * 256;
        kB[i]  = slot >> 5;
        c4B[i] = slot & 31;
    }

    ull acc[4][8];
    #pragma unroll
    for (int i = 0; i < 4; i++)
        #pragma unroll
        for (int j = 0; j < 8; j++) acc[i][j] = 0ull;

    float4 pa[2];
    #pragma unroll
    for (int i = 0; i < 2; i++)
        pa[i] = okA[i]
              ? *(const float4*)(g_agg + (size_t)(row0 + rA[i]) * HID + k4A[i] * 4)
              : make_float4(0.f, 0.f, 0.f, 0.f);
    #pragma unroll
    for (int i = 0; i < 2; i++)
        cpasync16(&Bs[0][kB[i] * 128 + c4B[i] * 4],
                  W + (size_t)kB[i] * HID + c4B[i] * 4);
    cpasync_commit();
    __syncthreads();   // smean/sscale ready
    // STS chunk 0: BN+ReLU, write h, stage to As
    #pragma unroll
    for (int i = 0; i < 2; i++) {
        float v4[4] = { pa[i].x, pa[i].y, pa[i].z, pa[i].w };
        float o4[4];
        #pragma unroll
        for (int j = 0; j < 4; j++) {
            int col = k4A[i] * 4 + j;
            o4[j] = fmaxf((v4[j] - smean[col]) * sscale[col], 0.f);
            As[0][col * 132 + rA[i]] = o4[j];
        }
        if (okA[i])
            *(float4*)(h + (size_t)(row0 + rA[i]) * HID + k4A[i] * 4) =
                make_float4(o4[0], o4[1], o4[2], o4[3]);
    }
    #pragma unroll
    for (int i = 0; i < 2; i++)
        pa[i] = okA[i]
              ? *(const float4*)(g_agg + (size_t)(row0 + rA[i]) * HID + KC + k4A[i] * 4)
              : make_float4(0.f, 0.f, 0.f, 0.f);

    // ---- in-block base[] computation (replaces prep_base kernel) ----
    if (tid < HID) {
        int c = *curr;
        xs[tid] = fmaxf((g_agg[(size_t)c * HID + tid] - smean[tid]) * sscale[tid], 0.f);
    }
    __syncthreads();
    if (tid < HID) {
        float accb = l1b[tid];
        #pragma unroll 8
        for (int k = 0; k < HID; k++)
            accb += xs[k] * W[(size_t)(HID + k) * HID + tid];
        sbase[tid] = accb;
    }

    #pragma unroll 1
    for (int c = 0; c < NCHUNK; c++) {
        cpasync_wait_all();
        __syncthreads();
        int nb = (c + 1) & 1;
        if (c + 1 < NCHUNK) {
            #pragma unroll
            for (int i = 0; i < 2; i++)
                cpasync16(&Bs[nb][kB[i] * 128 + c4B[i] * 4],
                          W + (size_t)((c + 1) * KC + kB[i]) * HID + c4B[i] * 4);
            cpasync_commit();
            #pragma unroll
            for (int i = 0; i < 2; i++) {
                float v4[4] = { pa[i].x, pa[i].y, pa[i].z, pa[i].w };
                float o4[4];
                #pragma unroll
                for (int j = 0; j < 4; j++) {
                    int col = (c + 1) * KC + k4A[i] * 4 + j;
                    o4[j] = fmaxf((v4[j] - smean[col]) * sscale[col], 0.f);
                    As[nb][(k4A[i] * 4 + j) * 132 + rA[i]] = o4[j];
                }
                if (okA[i])
                    *(float4*)(h + (size_t)(row0 + rA[i]) * HID
                               + (c + 1) * KC + k4A[i] * 4) =
                        make_float4(o4[0], o4[1], o4[2], o4[3]);
            }
        }
        if (c + 2 < NCHUNK) {
            #pragma unroll
            for (int i = 0; i < 2; i++)
                pa[i] = okA[i]
                      ? *(const float4*)(g_agg + (size_t)(row0 + rA[i]) * HID
                                         + (c + 2) * KC + k4A[i] * 4)
                      : make_float4(0.f, 0.f, 0.f, 0.f);
        }
        const float* as = As[c & 1];
        const float* bs = Bs[c & 1];
        #pragma unroll
        for (int k = 0; k < KC; k++) {
            float4 a0 = *(const float4*)(as + k * 132 + tr * 8);
            float4 a1 = *(const float4*)(as + k * 132 + tr * 8 + 4);
            float4 b0 = *(const float4*)(bs + k * 128 + tc * 8);
            float4 b1 = *(const float4*)(bs + k * 128 + tc * 8 + 4);
            ull ap[4] = { pk2(a0.x, a0.y), pk2(a0.z, a0.w),
                          pk2(a1.x, a1.y), pk2(a1.z, a1.w) };
            ull bd[8] = { pk2(b0.x, b0.x), pk2(b0.y, b0.y),
                          pk2(b0.z, b0.z), pk2(b0.w, b0.w),
                          pk2(b1.x, b1.x), pk2(b1.y, b1.y),
                          pk2(b1.z, b1.z), pk2(b1.w, b1.w) };
            #pragma unroll
            for (int i = 0; i < 4; i++)
                #pragma unroll
                for (int j = 0; j < 8; j++)
                    fma2(acc[i][j], ap[i], bd[j]);
        }
    }

    float w2[8], bb[8], wev[8];
    #pragma unroll
    for (int j = 0; j < 8; j++) {
        w2[j]  = l2w[tc * 8 + j];
        bb[j]  = sbase[tc * 8 + j];
        wev[j] = g_we[tc * 8 + j];
    }
    float b2 = l2b[0];
    #pragma unroll
    for (int i2 = 0; i2 < 4; i2++) {
        float2 v[8];
        #pragma unroll
        for (int j = 0; j < 8; j++) v[j] = upk2(acc[i2][j]);
        #pragma unroll
        for (int half = 0; half < 2; half++) {
            int row = row0 + tr * 8 + i2 * 2 + half;
            float e = (row < NODES) ? ecn[row] : 0.f;
            float s = 0.f;
            #pragma unroll
            for (int j = 0; j < 8; j++) {
                float val = half ? v[j].y : v[j].x;
                float t = val + bb[j] + e * wev[j];
                s += fmaxf(t, 0.f) * w2[j];
            }
            s += __shfl_xor_sync(0xffffffffu, s, 8, 16);
            s += __shfl_xor_sync(0xffffffffu, s, 4, 16);
            s += __shfl_xor_sync(0xffffffffu, s, 2, 16);
            s += __shfl_xor_sync(0xffffffffu, s, 1, 16);
            if (tc == 0) sarr[tr * 8 + i2 * 2 + half] = (row < NODES) ? (s + b2) : 0.f;
        }
    }
    if (tid < NPART) pp[tid] = 0.f;
    __syncthreads();
    int p = tid & 31, g = tid >> 5;
    float psum = 0.f;
    for (int r = g * 16; r < g * 16 + 16; r++) {
        int row = row0 + r;
        if (row < NODES) psum += sarr[r] * parts[(size_t)row * NPART + p];
    }
    atomicAdd(&pp[p], psum);
    __syncthreads();
    if (tid < NPART) atomicAdd(&out[tid], pp[tid]);
}

// ---------------- launcher ----------------
extern "C" void kernel_launch(void* const* d_in, const int* in_sizes, int n_in,
                              void* d_out, int out_size) {
    const float* x      = (const float*)d_in[0];
    const int*   ei     = (const int*)d_in[1];
    const float* ew     = (const float*)d_in[2];
    const float* parts  = (const float*)d_in[3];
    // d_in[4] = node_weights (unused by reference)
    const float* ecn    = (const float*)d_in[5];
    const float* conv_w = (const float*)d_in[6];
    const float* conv_b = (const float*)d_in[7];
    const float* l1w    = (const float*)d_in[8];
    const float* l1b    = (const float*)d_in[9];
    const float* l2w    = (const float*)d_in[10];
    const float* l2b    = (const float*)d_in[11];
    const int*   curr   = (const int*)d_in[12];

    float* out = (float*)d_out;          // [0:32) partition scores
    float* h   = out + NPART;            // [32 : 32+N*H) final h

    cudaStream_t sG;
    cudaStreamCreateWithFlags(&sG, cudaStreamNonBlocking);
    cudaEvent_t evFork, evJoin;
    cudaEventCreateWithFlags(&evFork, cudaEventDisableTiming);
    cudaEventCreateWithFlags(&evJoin, cudaEventDisableTiming);

    const int gemm_blocks = (NODES + 127) / 128;   // 391
    const int agg_blocks  = 1184;

    cudaEventRecord(evFork, 0);
    cudaStreamWaitEvent(sG, evFork, 0);

    // ---- setup chain on default stream; gemm0 is the 4th submission -> ncu target ----
    zero_init_kernel<<<(NODES + 255) / 256, 256>>>(out);         // 1
    deg_count_kernel<<<(NE + 255) / 256, 256>>>(ei, ew);         // 2
    scan_kernel2<<<NSB, SBLK>>>();                               // 3
    gemm_kernel<<<gemm_blocks, 256, 0, sG>>>(x, conv_w, conv_b, -1, NODES);  // 4 <- ncu
    prep_we_kernel<<<1, 128, 0, sG>>>(l1w);                      // 5
    csr_fill_kernel<<<(NE + 255) / 256, 256>>>(ei, ew);          // 6

    cudaEventRecord(evJoin, sG);
    cudaStreamWaitEvent(0, evJoin, 0);

    agg_kernel<<<agg_blocks, 256>>>(0);
    gemm_kernel<<<gemm_blocks, 256>>>(nullptr, conv_w + 1 * HID * HID,
                                      conv_b + 1 * HID, 0, NODES);
    agg_kernel<<<agg_blocks, 256>>>(1);
    gemm_kernel<<<gemm_blocks, 256>>>(nullptr, conv_w + 2 * HID * HID,
                                      conv_b + 2 * HID, 1, NODES);
    agg_kernel<<<agg_blocks, 256>>>(2);

    score_kernel<<<gemm_blocks, 256>>>(l1w, l1b, l2w, l2b, ecn, parts, curr, h, out);
}

// round 12
// speedup vs baseline: 1.0174x; 1.0171x over previous
#include <cuda_runtime.h>

#define NODES 50000
#define NE    800000
#define HID   128
#define NPART 32
#define BN_EPS 1e-5f
#define SBLK  512
#define NSB   ((NODES + SBLK - 1) / SBLK)   // 98

typedef unsigned long long ull;

// ---------------- scratch (device globals; no runtime alloc) ----------------
__device__ float g_deg[NODES];
__device__ int   g_cnt[NODES];
__device__ int   g_off[NODES + 1];
__device__ int   g_cur[NODES];
__device__ float g_dinv[NODES];
__device__ int   g_aggv[NSB];
__device__ volatile int g_flag[NSB];
__device__ int2  g_csr[NE];                 // {src, float_as_int(norm)}
__device__ float g_hw[NODES * HID];
__device__ float g_agg[NODES * HID];
__device__ float g_stats[3 * 2 * HID];      // per layer: [0:128) sum, [128:256) sumsq
__device__ float g_base[HID];
__device__ float g_we[HID];

// ---------------- f32x2 helpers ----------------
__device__ __forceinline__ ull pk2(float lo, float hi) {
    ull r;
    asm("mov.b64 %0, {%1, %2};" : "=l"(r) : "f"(lo), "f"(hi));
    return r;
}
__device__ __forceinline__ void fma2(ull& d, ull a, ull b) {
    asm("fma.rn.f32x2 %0, %1, %2, %0;" : "+l"(d) : "l"(a), "l"(b));
}
__device__ __forceinline__ float2 upk2(ull v) {
    float2 f;
    asm("mov.b64 {%0, %1}, %2;" : "=f"(f.x), "=f"(f.y) : "l"(v));
    return f;
}
// ---------------- cp.async helpers ----------------
__device__ __forceinline__ void cpasync16(void* smem_ptr, const void* gptr) {
    unsigned s = (unsigned)__cvta_generic_to_shared(smem_ptr);
    asm volatile("cp.async.cg.shared.global [%0], [%1], 16;"
                 :: "r"(s), "l"(gptr) : "memory");
}
__device__ __forceinline__ void cpasync_commit() {
    asm volatile("cp.async.commit_group;" ::: "memory");
}
__device__ __forceinline__ void cpasync_wait_all() {
    asm volatile("cp.async.wait_group 0;" ::: "memory");
}

// ---------------- init ----------------
__global__ void zero_init_kernel(float* out) {
    int i = blockIdx.x * blockDim.x + threadIdx.x;
    if (i < NODES) { g_deg[i] = 0.f; g_cnt[i] = 0; g_cur[i] = 0; }
    if (i < NPART) out[i] = 0.f;
    if (i < 3 * 2 * HID) g_stats[i] = 0.f;
    if (i < NSB) g_flag[i] = 0;
}

// ---------------- degree + count ----------------
__global__ void deg_count_kernel(const int* __restrict__ ei,
                                 const float* __restrict__ ew) {
    int e = blockIdx.x * blockDim.x + threadIdx.x;
    if (e >= NE) return;
    int dst = ei[NE + e];
    atomicAdd(&g_deg[dst], ew[e]);
    atomicAdd(&g_cnt[dst], 1);
}

// ---------------- single-kernel scan (decoupled lookback) + dinv fused ----------------
__global__ __launch_bounds__(SBLK) void scan_kernel2() {
    __shared__ int ws[SBLK / 32];
    __shared__ int s_prefix;
    int t = threadIdx.x, lane = t & 31, w = t >> 5;
    int bid = blockIdx.x;
    int i = bid * SBLK + t;
    int v = (i < NODES) ? g_cnt[i] : 0;
    if (i < NODES) g_dinv[i] = rsqrtf(g_deg[i] + 1.0f);

    int inc = v;
    #pragma unroll
    for (int o = 1; o < 32; o <<= 1) {
        int u = __shfl_up_sync(0xffffffffu, inc, o);
        if (lane >= o) inc += u;
    }
    if (lane == 31) ws[w] = inc;
    __syncthreads();

    if (w == 0 && lane < SBLK / 32) {
        int x = ws[lane];
        int xi = x;
        #pragma unroll
        for (int o = 1; o < 16; o <<= 1) {
            int u = __shfl_up_sync(0x0000ffffu, xi, o);
            if (lane >= o) xi += u;
        }
        ws[lane] = xi - x;                 // exclusive warp offsets
        if (lane == SBLK / 32 - 1) {       // xi = block total
            g_aggv[bid] = xi;
            __threadfence();
            g_flag[bid] = 1;
        }
    }
    __syncthreads();

    if (w == 0) {
        int sum = 0;
        for (int base = 0; base < bid; base += 32) {
            int p = base + lane;
            int a = 0;
            if (p < bid) {
                while (g_flag[p] == 0) { }
                __threadfence();
                a = g_aggv[p];
            }
            #pragma unroll
            for (int o = 16; o; o >>= 1) a += __shfl_down_sync(0xffffffffu, a, o);
            if (lane == 0) sum += a;
        }
        if (lane == 0) s_prefix = sum;
    }
    __syncthreads();

    int pref = s_prefix;
    if (i < NODES) g_off[i] = pref + ws[w] + inc - v;
    if (bid == NSB - 1 && t == SBLK - 1) g_off[NODES] = pref + ws[w] + inc;
}

// ---------------- CSR fill (interleaved) ----------------
__global__ void csr_fill_kernel(const int* __restrict__ ei,
                                const float* __restrict__ ew) {
    int e = blockIdx.x * blockDim.x + threadIdx.x;
    if (e >= NE) return;
    int src = ei[e];
    int dst = ei[NE + e];
    int pos = g_off[dst] + atomicAdd(&g_cur[dst], 1);
    float norm = g_dinv[src] * ew[e] * g_dinv[dst];
    g_csr[pos] = make_int2(src, __float_as_int(norm));
}

// ==================== pipelined GEMM (R9-proven: double-buffered, wait_group 0) ====================
#define KC 16
#define NCHUNK (HID / KC)   // 8
__global__ __launch_bounds__(256) void gemm_kernel(
    const float* __restrict__ A, const float* __restrict__ W,
    const float* __restrict__ bias, int layer, int nrows)
{
    __shared__ float As[2][KC * 132];   // [k][row], padded
    __shared__ float Bs[2][KC * 128];   // [k][col]
    __shared__ float smean[HID], sscale[HID];
    const bool bn = (layer >= 0);
    const float* __restrict__ src = bn ? (const float*)g_agg : A;
    int tid = threadIdx.x;
    int tr = tid >> 4, tc = tid & 15;
    int row0 = blockIdx.x * 128;

    if (bn && tid < HID) {
        float m = g_stats[layer * 256 + tid] * (1.0f / NODES);
        float v = g_stats[layer * 256 + HID + tid] * (1.0f / NODES) - m * m;
        smean[tid]  = m;
        sscale[tid] = rsqrtf(v + BN_EPS);
    }

    int rA[2], k4A[2];
    bool okA[2];
    #pragma unroll
    for (int i = 0; i < 2; i++) {
        int slot = tid + i * 256;
        rA[i]  = slot >> 2;
        k4A[i] = slot & 3;
        okA[i] = (row0 + rA[i]) < nrows;
    }
    int kB[2], c4B[2];
    #pragma unroll
    for (int i = 0; i < 2; i++) {
        int slot = tid + i * 256;
        kB[i]  = slot >> 5;
        c4B[i] = slot & 31;
    }

    ull acc[4][8];
    #pragma unroll
    for (int i = 0; i < 4; i++)
        #pragma unroll
        for (int j = 0; j < 8; j++) acc[i][j] = 0ull;

    float4 pa[2];
    #pragma unroll
    for (int i = 0; i < 2; i++)
        pa[i] = okA[i]
              ? *(const float4*)(src + (size_t)(row0 + rA[i]) * HID + k4A[i] * 4)
              : make_float4(0.f, 0.f, 0.f, 0.f);
    #pragma unroll
    for (int i = 0; i < 2; i++)
        cpasync16(&Bs[0][kB[i] * 128 + c4B[i] * 4],
                  W + (size_t)kB[i] * HID + c4B[i] * 4);
    cpasync_commit();
    __syncthreads();
    #pragma unroll
    for (int i = 0; i < 2; i++) {
        float v4[4] = { pa[i].x, pa[i].y, pa[i].z, pa[i].w };
        #pragma unroll
        for (int j = 0; j < 4; j++) {
            float v = v4[j];
            if (bn) {
                int col = k4A[i] * 4 + j;
                v = fmaxf((v - smean[col]) * sscale[col], 0.f);
            }
            As[0][(k4A[i] * 4 + j) * 132 + rA[i]] = v;
        }
    }
    #pragma unroll
    for (int i = 0; i < 2; i++)
        pa[i] = okA[i]
              ? *(const float4*)(src + (size_t)(row0 + rA[i]) * HID + KC + k4A[i] * 4)
              : make_float4(0.f, 0.f, 0.f, 0.f);

    #pragma unroll 1
    for (int c = 0; c < NCHUNK; c++) {
        cpasync_wait_all();
        __syncthreads();
        int nb = (c + 1) & 1;
        if (c + 1 < NCHUNK) {
            #pragma unroll
            for (int i = 0; i < 2; i++)
                cpasync16(&Bs[nb][kB[i] * 128 + c4B[i] * 4],
                          W + (size_t)((c + 1) * KC + kB[i]) * HID + c4B[i] * 4);
            cpasync_commit();
            #pragma unroll
            for (int i = 0; i < 2; i++) {
                float v4[4] = { pa[i].x, pa[i].y, pa[i].z, pa[i].w };
                #pragma unroll
                for (int j = 0; j < 4; j++) {
                    float v = v4[j];
                    if (bn) {
                        int col = (c + 1) * KC + k4A[i] * 4 + j;
                        v = fmaxf((v - smean[col]) * sscale[col], 0.f);
                    }
                    As[nb][(k4A[i] * 4 + j) * 132 + rA[i]] = v;
                }
            }
        }
        if (c + 2 < NCHUNK) {
            #pragma unroll
            for (int i = 0; i < 2; i++)
                pa[i] = okA[i]
                      ? *(const float4*)(src + (size_t)(row0 + rA[i]) * HID
                                         + (c + 2) * KC + k4A[i] * 4)
                      : make_float4(0.f, 0.f, 0.f, 0.f);
        }
        const float* as = As[c & 1];
        const float* bs = Bs[c & 1];
        #pragma unroll
        for (int k = 0; k < KC; k++) {
            float4 a0 = *(const float4*)(as + k * 132 + tr * 8);
            float4 a1 = *(const float4*)(as + k * 132 + tr * 8 + 4);
            float4 b0 = *(const float4*)(bs + k * 128 + tc * 8);
            float4 b1 = *(const float4*)(bs + k * 128 + tc * 8 + 4);
            ull ap[4] = { pk2(a0.x, a0.y), pk2(a0.z, a0.w),
                          pk2(a1.x, a1.y), pk2(a1.z, a1.w) };
            ull bd[8] = { pk2(b0.x, b0.x), pk2(b0.y, b0.y),
                          pk2(b0.z, b0.z), pk2(b0.w, b0.w),
                          pk2(b1.x, b1.x), pk2(b1.y, b1.y),
                          pk2(b1.z, b1.z), pk2(b1.w, b1.w) };
            #pragma unroll
            for (int i = 0; i < 4; i++)
                #pragma unroll
                for (int j = 0; j < 8; j++)
                    fma2(acc[i][j], ap[i], bd[j]);
        }
    }

    float bv[8];
    #pragma unroll
    for (int j = 0; j < 8; j++) bv[j] = bias[tc * 8 + j];
    #pragma unroll
    for (int i2 = 0; i2 < 4; i2++) {
        float2 v[8];
        #pragma unroll
        for (int j = 0; j < 8; j++) v[j] = upk2(acc[i2][j]);
        int r0 = row0 + tr * 8 + i2 * 2;
        if (r0 < nrows) {
            float4 o0 = make_float4(v[0].x + bv[0], v[1].x + bv[1],
                                    v[2].x + bv[2], v[3].x + bv[3]);
            float4 o1 = make_float4(v[4].x + bv[4], v[5].x + bv[5],
                                    v[6].x + bv[6], v[7].x + bv[7]);
            *(float4*)(g_hw + (size_t)r0 * HID + tc * 8)     = o0;
            *(float4*)(g_hw + (size_t)r0 * HID + tc * 8 + 4) = o1;
        }
        if (r0 + 1 < nrows) {
            float4 o0 = make_float4(v[0].y + bv[0], v[1].y + bv[1],
                                    v[2].y + bv[2], v[3].y + bv[3]);
            float4 o1 = make_float4(v[4].y + bv[4], v[5].y + bv[5],
                                    v[6].y + bv[6], v[7].y + bv[7]);
            *(float4*)(g_hw + (size_t)(r0 + 1) * HID + tc * 8)     = o0;
            *(float4*)(g_hw + (size_t)(r0 + 1) * HID + tc * 8 + 4) = o1;
        }
    }
}

// ---------------- aggregation (warp per node, gather unrolled x4) + BN stats ----------------
__global__ __launch_bounds__(256) void agg_kernel(int layer) {
    __shared__ float bsum[HID];
    __shared__ float bss[HID];
    int tid = threadIdx.x;
    for (int i = tid; i < HID; i += blockDim.x) { bsum[i] = 0.f; bss[i] = 0.f; }
    __syncthreads();

    int lane = tid & 31;
    int wglobal = (blockIdx.x * blockDim.x + tid) >> 5;
    int nwarps  = (gridDim.x * blockDim.x) >> 5;

    float ls0 = 0.f, ls1 = 0.f, ls2 = 0.f, ls3 = 0.f;
    float lq0 = 0.f, lq1 = 0.f, lq2 = 0.f, lq3 = 0.f;

    for (int n = wglobal; n < NODES; n += nwarps) {
        float dv = g_dinv[n];
        float sn = dv * dv;
        float4 a = ((const float4*)(g_hw + (size_t)n * HID))[lane];
        float4 acc = make_float4(a.x * sn, a.y * sn, a.z * sn, a.w * sn);
        int beg = g_off[n], end = g_off[n + 1];
        int i = beg;
        for (; i + 4 <= end; i += 4) {
            int2 e0 = g_csr[i],     e1 = g_csr[i + 1];
            int2 e2 = g_csr[i + 2], e3 = g_csr[i + 3];
            float w0 = __int_as_float(e0.y), w1 = __int_as_float(e1.y);
            float w2 = __int_as_float(e2.y), w3 = __int_as_float(e3.y);
            float4 v0 = ((const float4*)(g_hw + (size_t)e0.x * HID))[lane];
            float4 v1 = ((const float4*)(g_hw + (size_t)e1.x * HID))[lane];
            float4 v2 = ((const float4*)(g_hw + (size_t)e2.x * HID))[lane];
            float4 v3 = ((const float4*)(g_hw + (size_t)e3.x * HID))[lane];
            acc.x += w0 * v0.x + w1 * v1.x + w2 * v2.x + w3 * v3.x;
            acc.y += w0 * v0.y + w1 * v1.y + w2 * v2.y + w3 * v3.y;
            acc.z += w0 * v0.z + w1 * v1.z + w2 * v2.z + w3 * v3.z;
            acc.w += w0 * v0.w + w1 * v1.w + w2 * v2.w + w3 * v3.w;
        }
        for (; i + 2 <= end; i += 2) {
            int2 e0 = g_csr[i], e1 = g_csr[i + 1];
            float w0 = __int_as_float(e0.y), w1 = __int_as_float(e1.y);
            float4 v0 = ((const float4*)(g_hw + (size_t)e0.x * HID))[lane];
            float4 v1 = ((const float4*)(g_hw + (size_t)e1.x * HID))[lane];
            acc.x += w0 * v0.x + w1 * v1.x;
            acc.y += w0 * v0.y + w1 * v1.y;
            acc.z += w0 * v0.z + w1 * v1.z;
            acc.w += w0 * v0.w + w1 * v1.w;
        }
        if (i < end) {
            int2 e0 = g_csr[i];
            float w = __int_as_float(e0.y);
            float4 v = ((const float4*)(g_hw + (size_t)e0.x * HID))[lane];
            acc.x += w * v.x; acc.y += w * v.y;
            acc.z += w * v.z; acc.w += w * v.w;
        }
        ((float4*)(g_agg + (size_t)n * HID))[lane] = acc;
        ls0 += acc.x; ls1 += acc.y; ls2 += acc.z; ls3 += acc.w;
        lq0 += acc.x * acc.x; lq1 += acc.y * acc.y;
        lq2 += acc.z * acc.z; lq3 += acc.w * acc.w;
    }
    int c = lane * 4;
    atomicAdd(&bsum[c + 0], ls0); atomicAdd(&bsum[c + 1], ls1);
    atomicAdd(&bsum[c + 2], ls2); atomicAdd(&bsum[c + 3], ls3);
    atomicAdd(&bss[c + 0], lq0);  atomicAdd(&bss[c + 1], lq1);
    atomicAdd(&bss[c + 2], lq2);  atomicAdd(&bss[c + 3], lq3);
    __syncthreads();
    for (int i = tid; i < HID; i += blockDim.x) {
        atomicAdd(&g_stats[layer * 256 + i],       bsum[i]);
        atomicAdd(&g_stats[layer * 256 + HID + i], bss[i]);
    }
}

// ---------------- prep split: g_we has NO dependencies -> overlapped early ----------------
__global__ void prep_we_kernel(const float* __restrict__ l1w) {
    int j = threadIdx.x;   // 128
    float we = 0.f;
    #pragma unroll 8
    for (int k = 2 * HID; k < 4 * HID; k++)
        we += l1w[(size_t)k * HID + j];
    g_we[j] = we;
}

__global__ void prep_base_kernel(const float* __restrict__ l1w,
                                 const float* __restrict__ l1b,
                                 const int* __restrict__ curr) {
    __shared__ float xs[HID];
    int j = threadIdx.x;   // 128
    int c = *curr;
    float m = g_stats[2 * 256 + j] * (1.0f / NODES);
    float v = g_stats[2 * 256 + HID + j] * (1.0f / NODES) - m * m;
    float sc = rsqrtf(v + BN_EPS);
    xs[j] = fmaxf((g_agg[(size_t)c * HID + j] - m) * sc, 0.f);
    __syncthreads();
    float acc = 0.f;
    #pragma unroll 8
    for (int k = 0; k < HID; k++)
        acc += xs[k] * l1w[(size_t)(HID + k) * HID + j];
    g_base[j] = l1b[j] + acc;
}

// ==================== pipelined scoring (R9-proven) ====================
__global__ __launch_bounds__(256, 2) void score_kernel(
    const float* __restrict__ W,    // lin1_w rows 0..127
    const float* __restrict__ l2w, const float* __restrict__ l2b,
    const float* __restrict__ ecn, const float* __restrict__ parts,
    float* __restrict__ h, float* __restrict__ out)
{
    __shared__ float As[2][KC * 132];
    __shared__ float Bs[2][KC * 128];
    __shared__ float smean[HID], sscale[HID];
    __shared__ float sarr[128];
    __shared__ float pp[NPART];
    int tid = threadIdx.x;
    int tr = tid >> 4, tc = tid & 15;
    int row0 = blockIdx.x * 128;

    if (tid < HID) {
        float m = g_stats[2 * 256 + tid] * (1.0f / NODES);
        float v = g_stats[2 * 256 + HID + tid] * (1.0f / NODES) - m * m;
        smean[tid]  = m;
        sscale[tid] = rsqrtf(v + BN_EPS);
    }

    int rA[2], k4A[2];
    bool okA[2];
    #pragma unroll
    for (int i = 0; i < 2; i++) {
        int slot = tid + i * 256;
        rA[i]  = slot >> 2;
        k4A[i] = slot & 3;
        okA[i] = (row0 + rA[i]) < NODES;
    }
    int kB[2], c4B[2];
    #pragma unroll
    for (int i = 0; i < 2; i++) {
        int slot = tid + i * 256;
        kB[i]  = slot >> 5;
        c4B[i] = slot & 31;
    }

    ull acc[4][8];
    #pragma unroll
    for (int i = 0; i < 4; i++)
        #pragma unroll
        for (int j = 0; j < 8; j++) acc[i][j] = 0ull;

    float4 pa[2];
    #pragma unroll
    for (int i = 0; i < 2; i++)
        pa[i] = okA[i]
              ? *(const float4*)(g_agg + (size_t)(row0 + rA[i]) * HID + k4A[i] * 4)
              : make_float4(0.f, 0.f, 0.f, 0.f);
    #pragma unroll
    for (int i = 0; i < 2; i++)
        cpasync16(&Bs[0][kB[i] * 128 + c4B[i] * 4],
                  W + (size_t)kB[i] * HID + c4B[i] * 4);
    cpasync_commit();
    __syncthreads();   // smean/sscale ready
    #pragma unroll
    for (int i = 0; i < 2; i++) {
        float v4[4] = { pa[i].x, pa[i].y, pa[i].z, pa[i].w };
        float o4[4];
        #pragma unroll
        for (int j = 0; j < 4; j++) {
            int col = k4A[i] * 4 + j;
            o4[j] = fmaxf((v4[j] - smean[col]) * sscale[col], 0.f);
            As[0][col * 132 + rA[i]] = o4[j];
        }
        if (okA[i])
            *(float4*)(h + (size_t)(row0 + rA[i]) * HID + k4A[i] * 4) =
                make_float4(o4[0], o4[1], o4[2], o4[3]);
    }
    #pragma unroll
    for (int i = 0; i < 2; i++)
        pa[i] = okA[i]
              ? *(const float4*)(g_agg + (size_t)(row0 + rA[i]) * HID + KC + k4A[i] * 4)
              : make_float4(0.f, 0.f, 0.f, 0.f);

    #pragma unroll 1
    for (int c = 0; c < NCHUNK; c++) {
        cpasync_wait_all();
        __syncthreads();
        int nb = (c + 1) & 1;
        if (c + 1 < NCHUNK) {
            #pragma unroll
            for (int i = 0; i < 2; i++)
                cpasync16(&Bs[nb][kB[i] * 128 + c4B[i] * 4],
                          W + (size_t)((c + 1) * KC + kB[i]) * HID + c4B[i] * 4);
            cpasync_commit();
            #pragma unroll
            for (int i = 0; i < 2; i++) {
                float v4[4] = { pa[i].x, pa[i].y, pa[i].z, pa[i].w };
                float o4[4];
                #pragma unroll
                for (int j = 0; j < 4; j++) {
                    int col = (c + 1) * KC + k4A[i] * 4 + j;
                    o4[j] = fmaxf((v4[j] - smean[col]) * sscale[col], 0.f);
                    As[nb][(k4A[i] * 4 + j) * 132 + rA[i]] = o4[j];
                }
                if (okA[i])
                    *(float4*)(h + (size_t)(row0 + rA[i]) * HID
                               + (c + 1) * KC + k4A[i] * 4) =
                        make_float4(o4[0], o4[1], o4[2], o4[3]);
            }
        }
        if (c + 2 < NCHUNK) {
            #pragma unroll
            for (int i = 0; i < 2; i++)
                pa[i] = okA[i]
                      ? *(const float4*)(g_agg + (size_t)(row0 + rA[i]) * HID
                                         + (c + 2) * KC + k4A[i] * 4)
                      : make_float4(0.f, 0.f, 0.f, 0.f);
        }
        const float* as = As[c & 1];
        const float* bs = Bs[c & 1];
        #pragma unroll
        for (int k = 0; k < KC; k++) {
            float4 a0 = *(const float4*)(as + k * 132 + tr * 8);
            float4 a1 = *(const float4*)(as + k * 132 + tr * 8 + 4);
            float4 b0 = *(const float4*)(bs + k * 128 + tc * 8);
            float4 b1 = *(const float4*)(bs + k * 128 + tc * 8 + 4);
            ull ap[4] = { pk2(a0.x, a0.y), pk2(a0.z, a0.w),
                          pk2(a1.x, a1.y), pk2(a1.z, a1.w) };
            ull bd[8] = { pk2(b0.x, b0.x), pk2(b0.y, b0.y),
                          pk2(b0.z, b0.z), pk2(b0.w, b0.w),
                          pk2(b1.x, b1.x), pk2(b1.y, b1.y),
                          pk2(b1.z, b1.z), pk2(b1.w, b1.w) };
            #pragma unroll
            for (int i = 0; i < 4; i++)
                #pragma unroll
                for (int j = 0; j < 8; j++)
                    fma2(acc[i][j], ap[i], bd[j]);
        }
    }

    float w2[8], bb[8], wev[8];
    #pragma unroll
    for (int j = 0; j < 8; j++) {
        w2[j]  = l2w[tc * 8 + j];
        bb[j]  = g_base[tc * 8 + j];
        wev[j] = g_we[tc * 8 + j];
    }
    float b2 = l2b[0];
    #pragma unroll
    for (int i2 = 0; i2 < 4; i2++) {
        float2 v[8];
        #pragma unroll
        for (int j = 0; j < 8; j++) v[j] = upk2(acc[i2][j]);
        #pragma unroll
        for (int half = 0; half < 2; half++) {
            int row = row0 + tr * 8 + i2 * 2 + half;
            float e = (row < NODES) ? ecn[row] : 0.f;
            float s = 0.f;
            #pragma unroll
            for (int j = 0; j < 8; j++) {
                float val = half ? v[j].y : v[j].x;
                float t = val + bb[j] + e * wev[j];
                s += fmaxf(t, 0.f) * w2[j];
            }
            s += __shfl_xor_sync(0xffffffffu, s, 8, 16);
            s += __shfl_xor_sync(0xffffffffu, s, 4, 16);
            s += __shfl_xor_sync(0xffffffffu, s, 2, 16);
            s += __shfl_xor_sync(0xffffffffu, s, 1, 16);
            if (tc == 0) sarr[tr * 8 + i2 * 2 + half] = (row < NODES) ? (s + b2) : 0.f;
        }
    }
    if (tid < NPART) pp[tid] = 0.f;
    __syncthreads();
    int p = tid & 31, g = tid >> 5;
    float psum = 0.f;
    for (int r = g * 16; r < g * 16 + 16; r++) {
        int row = row0 + r;
        if (row < NODES) psum += sarr[r] * parts[(size_t)row * NPART + p];
    }
    atomicAdd(&pp[p], psum);
    __syncthreads();
    if (tid < NPART) atomicAdd(&out[tid], pp[tid]);
}

// ---------------- launcher (exact R9 structure) ----------------
extern "C" void kernel_launch(void* const* d_in, const int* in_sizes, int n_in,
                              void* d_out, int out_size) {
    const float* x      = (const float*)d_in[0];
    const int*   ei     = (const int*)d_in[1];
    const float* ew     = (const float*)d_in[2];
    const float* parts  = (const float*)d_in[3];
    // d_in[4] = node_weights (unused by reference)
    const float* ecn    = (const float*)d_in[5];
    const float* conv_w = (const float*)d_in[6];
    const float* conv_b = (const float*)d_in[7];
    const float* l1w    = (const float*)d_in[8];
    const float* l1b    = (const float*)d_in[9];
    const float* l2w    = (const float*)d_in[10];
    const float* l2b    = (const float*)d_in[11];
    const int*   curr   = (const int*)d_in[12];

    float* out = (float*)d_out;          // [0:32) partition scores
    float* h   = out + NPART;            // [32 : 32+N*H) final h

    // exact single-wave grid for agg (pure host queries; graph-legal)
    int agg_blocks = 1184;
    {
        int dev = 0, sms = 0, maxb = 0;
        if (cudaGetDevice(&dev) == cudaSuccess &&
            cudaDeviceGetAttribute(&sms, cudaDevAttrMultiProcessorCount, dev) == cudaSuccess &&
            cudaOccupancyMaxActiveBlocksPerMultiprocessor(&maxb, agg_kernel, 256, 0) == cudaSuccess &&
            sms > 0 && maxb > 0) {
            agg_blocks = sms * maxb;
        }
    }

    cudaStream_t sG;
    cudaStreamCreateWithFlags(&sG, cudaStreamNonBlocking);
    cudaEvent_t evFork, evJoin;
    cudaEventCreateWithFlags(&evFork, cudaEventDisableTiming);
    cudaEventCreateWithFlags(&evJoin, cudaEventDisableTiming);

    const int gemm_blocks = (NODES + 127) / 128;   // 391

    cudaEventRecord(evFork, 0);
    cudaStreamWaitEvent(sG, evFork, 0);

    // ---- setup chain on default stream (R9 order: csr_fill is 4th launch) ----
    zero_init_kernel<<<(NODES + 255) / 256, 256>>>(out);         // 1
    deg_count_kernel<<<(NE + 255) / 256, 256>>>(ei, ew);         // 2
    scan_kernel2<<<NSB, SBLK>>>();                               // 3
    csr_fill_kernel<<<(NE + 255) / 256, 256>>>(ei, ew);          // 4 <- ncu target

    // ---- overlapped on sG: we-sums (no deps) + gemm0 (depends only on x) ----
    prep_we_kernel<<<1, 128, 0, sG>>>(l1w);                      // 5
    gemm_kernel<<<gemm_blocks, 256, 0, sG>>>(x, conv_w, conv_b, -1, NODES);  // 6

    cudaEventRecord(evJoin, sG);
    cudaStreamWaitEvent(0, evJoin, 0);

    agg_kernel<<<agg_blocks, 256>>>(0);
    gemm_kernel<<<gemm_blocks, 256>>>(nullptr, conv_w + 1 * HID * HID,
                                      conv_b + 1 * HID, 0, NODES);
    agg_kernel<<<agg_blocks, 256>>>(1);
    gemm_kernel<<<gemm_blocks, 256>>>(nullptr, conv_w + 2 * HID * HID,
                                      conv_b + 2 * HID, 1, NODES);
    agg_kernel<<<agg_blocks, 256>>>(2);

    prep_base_kernel<<<1, 128>>>(l1w, l1b, curr);
    score_kernel<<<gemm_blocks, 256>>>(l1w, l2w, l2b, ecn, parts, h, out);
}

// round 14
// speedup vs baseline: 1.0987x; 1.0799x over previous
#include <cuda_runtime.h>
#include <cuda_bf16.h>
#include <mma.h>

#define NODES 50000
#define NE    800000
#define HID   128
#define NPART 32
#define BN_EPS 1e-5f
#define SBLK  512
#define NSB   ((NODES + SBLK - 1) / SBLK)   // 98

typedef unsigned long long ull;
using namespace nvcuda;

// ---------------- scratch (device globals; no runtime alloc) ----------------
__device__ float g_deg[NODES];
__device__ int   g_cnt[NODES];
__device__ int   g_off[NODES + 1];
__device__ int   g_cur[NODES];
__device__ float g_dinv[NODES];
__device__ int   g_aggv[NSB];
__device__ volatile int g_flag[NSB];
__device__ int2  g_csr[NE];                 // {src, float_as_int(norm)}
__device__ float g_hw[NODES * HID];
__device__ float g_agg[NODES * HID];
__device__ float g_stats[3 * 2 * HID];      // per layer: [0:128) sum, [128:256) sumsq
__device__ float g_base[HID];
__device__ float g_we[HID];
// pre-split conv weights, row-major [K][N] bf16, per layer 16384 elems
__device__ __nv_bfloat16 g_bhi[3 * 16384];
__device__ __nv_bfloat16 g_blo[3 * 16384];

// ---------------- f32x2 helpers (score kernel) ----------------
__device__ __forceinline__ ull pk2(float lo, float hi) {
    ull r;
    asm("mov.b64 %0, {%1, %2};" : "=l"(r) : "f"(lo), "f"(hi));
    return r;
}
__device__ __forceinline__ void fma2(ull& d, ull a, ull b) {
    asm("fma.rn.f32x2 %0, %1, %2, %0;" : "+l"(d) : "l"(a), "l"(b));
}
__device__ __forceinline__ float2 upk2(ull v) {
    float2 f;
    asm("mov.b64 {%0, %1}, %2;" : "=f"(f.x), "=f"(f.y) : "l"(v));
    return f;
}
// ---------------- cp.async helpers ----------------
__device__ __forceinline__ void cpasync16(void* smem_ptr, const void* gptr) {
    unsigned s = (unsigned)__cvta_generic_to_shared(smem_ptr);
    asm volatile("cp.async.cg.shared.global [%0], [%1], 16;"
                 :: "r"(s), "l"(gptr) : "memory");
}
__device__ __forceinline__ void cpasync_commit() {
    asm volatile("cp.async.commit_group;" ::: "memory");
}
__device__ __forceinline__ void cpasync_wait_all() {
    asm volatile("cp.async.wait_group 0;" ::: "memory");
}

// ---------------- init ----------------
__global__ void zero_init_kernel(float* out) {
    int i = blockIdx.x * blockDim.x + threadIdx.x;
    if (i < NODES) { g_deg[i] = 0.f; g_cnt[i] = 0; g_cur[i] = 0; }
    if (i < NPART) out[i] = 0.f;
    if (i < 3 * 2 * HID) g_stats[i] = 0.f;
    if (i < NSB) g_flag[i] = 0;
}

// ---------------- degree + count ----------------
__global__ void deg_count_kernel(const int* __restrict__ ei,
                                 const float* __restrict__ ew) {
    int e = blockIdx.x * blockDim.x + threadIdx.x;
    if (e >= NE) return;
    int dst = ei[NE + e];
    atomicAdd(&g_deg[dst], ew[e]);
    atomicAdd(&g_cnt[dst], 1);
}

// ---------------- single-kernel scan (decoupled lookback) + dinv fused ----------------
__global__ __launch_bounds__(SBLK) void scan_kernel2() {
    __shared__ int ws[SBLK / 32];
    __shared__ int s_prefix;
    int t = threadIdx.x, lane = t & 31, w = t >> 5;
    int bid = blockIdx.x;
    int i = bid * SBLK + t;
    int v = (i < NODES) ? g_cnt[i] : 0;
    if (i < NODES) g_dinv[i] = rsqrtf(g_deg[i] + 1.0f);

    int inc = v;
    #pragma unroll
    for (int o = 1; o < 32; o <<= 1) {
        int u = __shfl_up_sync(0xffffffffu, inc, o);
        if (lane >= o) inc += u;
    }
    if (lane == 31) ws[w] = inc;
    __syncthreads();

    if (w == 0 && lane < SBLK / 32) {
        int x = ws[lane];
        int xi = x;
        #pragma unroll
        for (int o = 1; o < 16; o <<= 1) {
            int u = __shfl_up_sync(0x0000ffffu, xi, o);
            if (lane >= o) xi += u;
        }
        ws[lane] = xi - x;
        if (lane == SBLK / 32 - 1) {
            g_aggv[bid] = xi;
            __threadfence();
            g_flag[bid] = 1;
        }
    }
    __syncthreads();

    if (w == 0) {
        int sum = 0;
        for (int base = 0; base < bid; base += 32) {
            int p = base + lane;
            int a = 0;
            if (p < bid) {
                while (g_flag[p] == 0) { }
                __threadfence();
                a = g_aggv[p];
            }
            #pragma unroll
            for (int o = 16; o; o >>= 1) a += __shfl_down_sync(0xffffffffu, a, o);
            if (lane == 0) sum += a;
        }
        if (lane == 0) s_prefix = sum;
    }
    __syncthreads();

    int pref = s_prefix;
    if (i < NODES) g_off[i] = pref + ws[w] + inc - v;
    if (bid == NSB - 1 && t == SBLK - 1) g_off[NODES] = pref + ws[w] + inc;
}

// ---------------- CSR fill (interleaved) ----------------
__global__ void csr_fill_kernel(const int* __restrict__ ei,
                                const float* __restrict__ ew) {
    int e = blockIdx.x * blockDim.x + threadIdx.x;
    if (e >= NE) return;
    int src = ei[e];
    int dst = ei[NE + e];
    int pos = g_off[dst] + atomicAdd(&g_cur[dst], 1);
    float norm = g_dinv[src] * ew[e] * g_dinv[dst];
    g_csr[pos] = make_int2(src, __float_as_int(norm));
}

// ---------------- W pre-split into row-major bf16 hi/lo ----------------
__global__ void bsplit_kernel(const float* __restrict__ conv_w) {
    int idx = blockIdx.x * blockDim.x + threadIdx.x;
    if (idx >= 3 * 16384) return;
    float wv = conv_w[idx];
    __nv_bfloat16 h = __float2bfloat16(wv);
    float res = wv - __bfloat162float(h);
    g_bhi[idx] = h;
    g_blo[idx] = __float2bfloat16(res);
}

// ==================== WMMA bf16x3 GEMM: g_hw = act(A) @ W + bias ====================
// 256 threads, 128x128 tile, K=128. 8 warps in 4x2 -> 32x64 warp tiles.
// smem: A_hi, A_lo, B_hi, B_lo each [128][136] bf16 (34816 B) + scalars.
#define LDM 136
#define TILE_B (128 * LDM * 2)          // 34816
#define TG_SMEM (4 * TILE_B + 1536)     // 140800
__global__ __launch_bounds__(256)
void tgemm_kernel(const float* __restrict__ A, const float* __restrict__ bias,
                  int wsel, int bnlayer, int nrows)
{
    extern __shared__ char dsm[];
    __nv_bfloat16* Ah = (__nv_bfloat16*)dsm;
    __nv_bfloat16* Al = (__nv_bfloat16*)(dsm + TILE_B);
    __nv_bfloat16* Bh = (__nv_bfloat16*)(dsm + 2 * TILE_B);
    __nv_bfloat16* Bl = (__nv_bfloat16*)(dsm + 3 * TILE_B);
    float* smean  = (float*)(dsm + 4 * TILE_B);
    float* sscale = (float*)(dsm + 4 * TILE_B + 512);
    float* sbias  = (float*)(dsm + 4 * TILE_B + 1024);

    int tid = threadIdx.x;
    int wid = tid >> 5;
    int warp_m = wid >> 1;          // 0..3
    int warp_n = wid & 1;           // 0..1
    int row0 = blockIdx.x * 128;
    const bool bn = (bnlayer >= 0);
    const float* __restrict__ src = bn ? (const float*)g_agg : A;

    if (tid < HID) {
        if (bn) {
            float m = g_stats[bnlayer * 256 + tid] * (1.0f / NODES);
            float v = g_stats[bnlayer * 256 + HID + tid] * (1.0f / NODES) - m * m;
            smean[tid]  = m;
            sscale[tid] = rsqrtf(v + BN_EPS);
        }
        sbias[tid] = bias[tid];
    }

    // ---- stage B hi/lo via cp.async (row-major, 256B/row -> ldm 136) ----
    {
        const char* bh = (const char*)(g_bhi + (size_t)wsel * 16384);
        const char* bl = (const char*)(g_blo + (size_t)wsel * 16384);
        #pragma unroll
        for (int it = 0; it < 8; it++) {
            int g = tid + it * 256;          // 0..2047
            int k = g >> 4, seg = g & 15;
            cpasync16((char*)Bh + k * (LDM * 2) + seg * 16, bh + k * 256 + seg * 16);
            cpasync16((char*)Bl + k * (LDM * 2) + seg * 16, bl + k * 256 + seg * 16);
        }
        cpasync_commit();
    }
    __syncthreads();   // smean/sscale/sbias visible

    // ---- stage A: fp32 load -> BN+ReLU -> hi/lo split ----
    #pragma unroll 4
    for (int it = 0; it < 16; it++) {
        int idx4 = tid + it * 256;           // 0..4095 float4s
        int r = idx4 >> 5, k4 = idx4 & 31;
        float4 v = make_float4(0.f, 0.f, 0.f, 0.f);
        int row = row0 + r;
        if (row < nrows)
            v = *(const float4*)(src + (size_t)row * HID + k4 * 4);
        float f[4] = { v.x, v.y, v.z, v.w };
        if (bn) {
            int c0 = k4 * 4;
            #pragma unroll
            for (int j = 0; j < 4; j++)
                f[j] = fmaxf((f[j] - smean[c0 + j]) * sscale[c0 + j], 0.f);
        }
        ushort4 hv, lv;
        unsigned short* hp = (unsigned short*)&hv;
        unsigned short* lp = (unsigned short*)&lv;
        #pragma unroll
        for (int j = 0; j < 4; j++) {
            __nv_bfloat16 h = __float2bfloat16(f[j]);
            float res = f[j] - __bfloat162float(h);
            __nv_bfloat16 l = __float2bfloat16(res);
            hp[j] = *(unsigned short*)&h;
            lp[j] = *(unsigned short*)&l;
        }
        unsigned off = (unsigned)r * LDM + k4 * 4;   // elements; 8B-aligned
        *(ushort4*)(Ah + off) = hv;
        *(ushort4*)(Al + off) = lv;
    }
    cpasync_wait_all();
    __syncthreads();

    // ---- WMMA mainloop: 3 terms, 8 K-chunks ----
    wmma::fragment<wmma::accumulator, 16, 16, 16, float> acc[2][4];
    #pragma unroll
    for (int i = 0; i < 2; i++)
        #pragma unroll
        for (int j = 0; j < 4; j++)
            wmma::fill_fragment(acc[i][j], 0.0f);

    #pragma unroll 1
    for (int kc = 0; kc < 8; kc++) {
        int k0 = kc * 16;
        wmma::fragment<wmma::matrix_b, 16, 16, 16, __nv_bfloat16, wmma::row_major> bh[4], bl[4];
        #pragma unroll
        for (int j = 0; j < 4; j++) {
            int c0 = warp_n * 64 + j * 16;
            wmma::load_matrix_sync(bh[j], Bh + (size_t)k0 * LDM + c0, LDM);
            wmma::load_matrix_sync(bl[j], Bl + (size_t)k0 * LDM + c0, LDM);
        }
        #pragma unroll
        for (int i = 0; i < 2; i++) {
            int r0 = warp_m * 32 + i * 16;
            wmma::fragment<wmma::matrix_a, 16, 16, 16, __nv_bfloat16, wmma::row_major> ah, al;
            wmma::load_matrix_sync(ah, Ah + (size_t)r0 * LDM + k0, LDM);
            wmma::load_matrix_sync(al, Al + (size_t)r0 * LDM + k0, LDM);
            #pragma unroll
            for (int j = 0; j < 4; j++) {
                wmma::mma_sync(acc[i][j], ah, bh[j], acc[i][j]);
                wmma::mma_sync(acc[i][j], ah, bl[j], acc[i][j]);
                wmma::mma_sync(acc[i][j], al, bh[j], acc[i][j]);
            }
        }
    }
    __syncthreads();   // done reading tiles; reuse as float output buffer

    float* fout = (float*)dsm;   // [128][LDM] floats (69632 B < 2*TILE_B)
    #pragma unroll
    for (int i = 0; i < 2; i++)
        #pragma unroll
        for (int j = 0; j < 4; j++) {
            int r0 = warp_m * 32 + i * 16;
            int c0 = warp_n * 64 + j * 16;
            wmma::store_matrix_sync(fout + (size_t)r0 * LDM + c0, acc[i][j],
                                    LDM, wmma::mem_row_major);
        }
    __syncthreads();

    // ---- write out with bias ----
    #pragma unroll 4
    for (int it = 0; it < 16; it++) {
        int idx4 = tid + it * 256;
        int r = idx4 >> 5, c4 = idx4 & 31;
        int row = row0 + r;
        if (row < nrows) {
            const float* s = fout + (size_t)r * LDM + c4 * 4;
            float4 ov = make_float4(s[0] + sbias[c4 * 4 + 0],
                                    s[1] + sbias[c4 * 4 + 1],
                                    s[2] + sbias[c4 * 4 + 2],
                                    s[3] + sbias[c4 * 4 + 3]);
            *(float4*)(g_hw + (size_t)row * HID + c4 * 4) = ov;
        }
    }
}

// ---------------- aggregation (warp per node, gather unrolled x4) + BN stats ----------------
__global__ __launch_bounds__(256) void agg_kernel(int layer) {
    __shared__ float bsum[HID];
    __shared__ float bss[HID];
    int tid = threadIdx.x;
    for (int i = tid; i < HID; i += blockDim.x) { bsum[i] = 0.f; bss[i] = 0.f; }
    __syncthreads();

    int lane = tid & 31;
    int wglobal = (blockIdx.x * blockDim.x + tid) >> 5;
    int nwarps  = (gridDim.x * blockDim.x) >> 5;

    float ls0 = 0.f, ls1 = 0.f, ls2 = 0.f, ls3 = 0.f;
    float lq0 = 0.f, lq1 = 0.f, lq2 = 0.f, lq3 = 0.f;

    for (int n = wglobal; n < NODES; n += nwarps) {
        float dv = g_dinv[n];
        float sn = dv * dv;
        float4 a = ((const float4*)(g_hw + (size_t)n * HID))[lane];
        float4 acc = make_float4(a.x * sn, a.y * sn, a.z * sn, a.w * sn);
        int beg = g_off[n], end = g_off[n + 1];
        int i = beg;
        for (; i + 4 <= end; i += 4) {
            int2 e0 = g_csr[i],     e1 = g_csr[i + 1];
            int2 e2 = g_csr[i + 2], e3 = g_csr[i + 3];
            float w0 = __int_as_float(e0.y), w1 = __int_as_float(e1.y);
            float w2 = __int_as_float(e2.y), w3 = __int_as_float(e3.y);
            float4 v0 = ((const float4*)(g_hw + (size_t)e0.x * HID))[lane];
            float4 v1 = ((const float4*)(g_hw + (size_t)e1.x * HID))[lane];
            float4 v2 = ((const float4*)(g_hw + (size_t)e2.x * HID))[lane];
            float4 v3 = ((const float4*)(g_hw + (size_t)e3.x * HID))[lane];
            acc.x += w0 * v0.x + w1 * v1.x + w2 * v2.x + w3 * v3.x;
            acc.y += w0 * v0.y + w1 * v1.y + w2 * v2.y + w3 * v3.y;
            acc.z += w0 * v0.z + w1 * v1.z + w2 * v2.z + w3 * v3.z;
            acc.w += w0 * v0.w + w1 * v1.w + w2 * v2.w + w3 * v3.w;
        }
        for (; i + 2 <= end; i += 2) {
            int2 e0 = g_csr[i], e1 = g_csr[i + 1];
            float w0 = __int_as_float(e0.y), w1 = __int_as_float(e1.y);
            float4 v0 = ((const float4*)(g_hw + (size_t)e0.x * HID))[lane];
            float4 v1 = ((const float4*)(g_hw + (size_t)e1.x * HID))[lane];
            acc.x += w0 * v0.x + w1 * v1.x;
            acc.y += w0 * v0.y + w1 * v1.y;
            acc.z += w0 * v0.z + w1 * v1.z;
            acc.w += w0 * v0.w + w1 * v1.w;
        }
        if (i < end) {
            int2 e0 = g_csr[i];
            float w = __int_as_float(e0.y);
            float4 v = ((const float4*)(g_hw + (size_t)e0.x * HID))[lane];
            acc.x += w * v.x; acc.y += w * v.y;
            acc.z += w * v.z; acc.w += w * v.w;
        }
        ((float4*)(g_agg + (size_t)n * HID))[lane] = acc;
        ls0 += acc.x; ls1 += acc.y; ls2 += acc.z; ls3 += acc.w;
        lq0 += acc.x * acc.x; lq1 += acc.y * acc.y;
        lq2 += acc.z * acc.z; lq3 += acc.w * acc.w;
    }
    int c = lane * 4;
    atomicAdd(&bsum[c + 0], ls0); atomicAdd(&bsum[c + 1], ls1);
    atomicAdd(&bsum[c + 2], ls2); atomicAdd(&bsum[c + 3], ls3);
    atomicAdd(&bss[c + 0], lq0);  atomicAdd(&bss[c + 1], lq1);
    atomicAdd(&bss[c + 2], lq2);  atomicAdd(&bss[c + 3], lq3);
    __syncthreads();
    for (int i = tid; i < HID; i += blockDim.x) {
        atomicAdd(&g_stats[layer * 256 + i],       bsum[i]);
        atomicAdd(&g_stats[layer * 256 + HID + i], bss[i]);
    }
}

// ---------------- prep split ----------------
__global__ void prep_we_kernel(const float* __restrict__ l1w) {
    int j = threadIdx.x;
    float we = 0.f;
    #pragma unroll 8
    for (int k = 2 * HID; k < 4 * HID; k++)
        we += l1w[(size_t)k * HID + j];
    g_we[j] = we;
}

__global__ void prep_base_kernel(const float* __restrict__ l1w,
                                 const float* __restrict__ l1b,
                                 const int* __restrict__ curr) {
    __shared__ float xs[HID];
    int j = threadIdx.x;
    int c = *curr;
    float m = g_stats[2 * 256 + j] * (1.0f / NODES);
    float v = g_stats[2 * 256 + HID + j] * (1.0f / NODES) - m * m;
    float sc = rsqrtf(v + BN_EPS);
    xs[j] = fmaxf((g_agg[(size_t)c * HID + j] - m) * sc, 0.f);
    __syncthreads();
    float acc = 0.f;
    #pragma unroll 8
    for (int k = 0; k < HID; k++)
        acc += xs[k] * l1w[(size_t)(HID + k) * HID + j];
    g_base[j] = l1b[j] + acc;
}

// ==================== pipelined scoring (R9-proven, unchanged) ====================
#define KC 16
#define NCHUNK (HID / KC)
__global__ __launch_bounds__(256, 2) void score_kernel(
    const float* __restrict__ W,
    const float* __restrict__ l2w, const float* __restrict__ l2b,
    const float* __restrict__ ecn, const float* __restrict__ parts,
    float* __restrict__ h, float* __restrict__ out)
{
    __shared__ float As[2][KC * 132];
    __shared__ float Bs[2][KC * 128];
    __shared__ float smean[HID], sscale[HID];
    __shared__ float sarr[128];
    __shared__ float pp[NPART];
    int tid = threadIdx.x;
    int tr = tid >> 4, tc = tid & 15;
    int row0 = blockIdx.x * 128;

    if (tid < HID) {
        float m = g_stats[2 * 256 + tid] * (1.0f / NODES);
        float v = g_stats[2 * 256 + HID + tid] * (1.0f / NODES) - m * m;
        smean[tid]  = m;
        sscale[tid] = rsqrtf(v + BN_EPS);
    }

    int rA[2], k4A[2];
    bool okA[2];
    #pragma unroll
    for (int i = 0; i < 2; i++) {
        int slot = tid + i * 256;
        rA[i]  = slot >> 2;
        k4A[i] = slot & 3;
        okA[i] = (row0 + rA[i]) < NODES;
    }
    int kB[2], c4B[2];
    #pragma unroll
    for (int i = 0; i < 2; i++) {
        int slot = tid + i * 256;
        kB[i]  = slot >> 5;
        c4B[i] = slot & 31;
    }

    ull acc[4][8];
    #pragma unroll
    for (int i = 0; i < 4; i++)
        #pragma unroll
        for (int j = 0; j < 8; j++) acc[i][j] = 0ull;

    float4 pa[2];
    #pragma unroll
    for (int i = 0; i < 2; i++)
        pa[i] = okA[i]
              ? *(const float4*)(g_agg + (size_t)(row0 + rA[i]) * HID + k4A[i] * 4)
              : make_float4(0.f, 0.f, 0.f, 0.f);
    #pragma unroll
    for (int i = 0; i < 2; i++)
        cpasync16(&Bs[0][kB[i] * 128 + c4B[i] * 4],
                  W + (size_t)kB[i] * HID + c4B[i] * 4);
    cpasync_commit();
    __syncthreads();
    #pragma unroll
    for (int i = 0; i < 2; i++) {
        float v4[4] = { pa[i].x, pa[i].y, pa[i].z, pa[i].w };
        float o4[4];
        #pragma unroll
        for (int j = 0; j < 4; j++) {
            int col = k4A[i] * 4 + j;
            o4[j] = fmaxf((v4[j] - smean[col]) * sscale[col], 0.f);
            As[0][col * 132 + rA[i]] = o4[j];
        }
        if (okA[i])
            *(float4*)(h + (size_t)(row0 + rA[i]) * HID + k4A[i] * 4) =
                make_float4(o4[0], o4[1], o4[2], o4[3]);
    }
    #pragma unroll
    for (int i = 0; i < 2; i++)
        pa[i] = okA[i]
              ? *(const float4*)(g_agg + (size_t)(row0 + rA[i]) * HID + KC + k4A[i] * 4)
              : make_float4(0.f, 0.f, 0.f, 0.f);

    #pragma unroll 1
    for (int c = 0; c < NCHUNK; c++) {
        cpasync_wait_all();
        __syncthreads();
        int nb = (c + 1) & 1;
        if (c + 1 < NCHUNK) {
            #pragma unroll
            for (int i = 0; i < 2; i++)
                cpasync16(&Bs[nb][kB[i] * 128 + c4B[i] * 4],
                          W + (size_t)((c + 1) * KC + kB[i]) * HID + c4B[i] * 4);
            cpasync_commit();
            #pragma unroll
            for (int i = 0; i < 2; i++) {
                float v4[4] = { pa[i].x, pa[i].y, pa[i].z, pa[i].w };
                float o4[4];
                #pragma unroll
                for (int j = 0; j < 4; j++) {
                    int col = (c + 1) * KC + k4A[i] * 4 + j;
                    o4[j] = fmaxf((v4[j] - smean[col]) * sscale[col], 0.f);
                    As[nb][(k4A[i] * 4 + j) * 132 + rA[i]] = o4[j];
                }
                if (okA[i])
                    *(float4*)(h + (size_t)(row0 + rA[i]) * HID
                               + (c + 1) * KC + k4A[i] * 4) =
                        make_float4(o4[0], o4[1], o4[2], o4[3]);
            }
        }
        if (c + 2 < NCHUNK) {
            #pragma unroll
            for (int i = 0; i < 2; i++)
                pa[i] = okA[i]
                      ? *(const float4*)(g_agg + (size_t)(row0 + rA[i]) * HID
                                         + (c + 2) * KC + k4A[i] * 4)
                      : make_float4(0.f, 0.f, 0.f, 0.f);
        }
        const float* as = As[c & 1];
        const float* bs = Bs[c & 1];
        #pragma unroll
        for (int k = 0; k < KC; k++) {
            float4 a0 = *(const float4*)(as + k * 132 + tr * 8);
            float4 a1 = *(const float4*)(as + k * 132 + tr * 8 + 4);
            float4 b0 = *(const float4*)(bs + k * 128 + tc * 8);
            float4 b1 = *(const float4*)(bs + k * 128 + tc * 8 + 4);
            ull ap[4] = { pk2(a0.x, a0.y), pk2(a0.z, a0.w),
                          pk2(a1.x, a1.y), pk2(a1.z, a1.w) };
            ull bd[8] = { pk2(b0.x, b0.x), pk2(b0.y, b0.y),
                          pk2(b0.z, b0.z), pk2(b0.w, b0.w),
                          pk2(b1.x, b1.x), pk2(b1.y, b1.y),
                          pk2(b1.z, b1.z), pk2(b1.w, b1.w) };
            #pragma unroll
            for (int i = 0; i < 4; i++)
                #pragma unroll
                for (int j = 0; j < 8; j++)
                    fma2(acc[i][j], ap[i], bd[j]);
        }
    }

    float w2[8], bb[8], wev[8];
    #pragma unroll
    for (int j = 0; j < 8; j++) {
        w2[j]  = l2w[tc * 8 + j];
        bb[j]  = g_base[tc * 8 + j];
        wev[j] = g_we[tc * 8 + j];
    }
    float b2 = l2b[0];
    #pragma unroll
    for (int i2 = 0; i2 < 4; i2++) {
        float2 v[8];
        #pragma unroll
        for (int j = 0; j < 8; j++) v[j] = upk2(acc[i2][j]);
        #pragma unroll
        for (int half = 0; half < 2; half++) {
            int row = row0 + tr * 8 + i2 * 2 + half;
            float e = (row < NODES) ? ecn[row] : 0.f;
            float s = 0.f;
            #pragma unroll
            for (int j = 0; j < 8; j++) {
                float val = half ? v[j].y : v[j].x;
                float t = val + bb[j] + e * wev[j];
                s += fmaxf(t, 0.f) * w2[j];
            }
            s += __shfl_xor_sync(0xffffffffu, s, 8, 16);
            s += __shfl_xor_sync(0xffffffffu, s, 4, 16);
            s += __shfl_xor_sync(0xffffffffu, s, 2, 16);
            s += __shfl_xor_sync(0xffffffffu, s, 1, 16);
            if (tc == 0) sarr[tr * 8 + i2 * 2 + half] = (row < NODES) ? (s + b2) : 0.f;
        }
    }
    if (tid < NPART) pp[tid] = 0.f;
    __syncthreads();
    int p = tid & 31, g = tid >> 5;
    float psum = 0.f;
    for (int r = g * 16; r < g * 16 + 16; r++) {
        int row = row0 + r;
        if (row < NODES) psum += sarr[r] * parts[(size_t)row * NPART + p];
    }
    atomicAdd(&pp[p], psum);
    __syncthreads();
    if (tid < NPART) atomicAdd(&out[tid], pp[tid]);
}

// ---------------- launcher ----------------
extern "C" void kernel_launch(void* const* d_in, const int* in_sizes, int n_in,
                              void* d_out, int out_size) {
    const float* x      = (const float*)d_in[0];
    const int*   ei     = (const int*)d_in[1];
    const float* ew     = (const float*)d_in[2];
    const float* parts  = (const float*)d_in[3];
    const float* ecn    = (const float*)d_in[5];
    const float* conv_w = (const float*)d_in[6];
    const float* conv_b = (const float*)d_in[7];
    const float* l1w    = (const float*)d_in[8];
    const float* l1b    = (const float*)d_in[9];
    const float* l2w    = (const float*)d_in[10];
    const float* l2b    = (const float*)d_in[11];
    const int*   curr   = (const int*)d_in[12];

    float* out = (float*)d_out;          // [0:32) partition scores
    float* h   = out + NPART;            // [32 : 32+N*H) final h

    cudaFuncSetAttribute(tgemm_kernel,
                         cudaFuncAttributeMaxDynamicSharedMemorySize, TG_SMEM);

    int agg_blocks = 1184;
    {
        int dev = 0, sms = 0, maxb = 0;
        if (cudaGetDevice(&dev) == cudaSuccess &&
            cudaDeviceGetAttribute(&sms, cudaDevAttrMultiProcessorCount, dev) == cudaSuccess &&
            cudaOccupancyMaxActiveBlocksPerMultiprocessor(&maxb, agg_kernel, 256, 0) == cudaSuccess &&
            sms > 0 && maxb > 0) {
            agg_blocks = sms * maxb;
        }
    }

    cudaStream_t sG;
    cudaStreamCreateWithFlags(&sG, cudaStreamNonBlocking);
    cudaEvent_t evFork, evJoin;
    cudaEventCreateWithFlags(&evFork, cudaEventDisableTiming);
    cudaEventCreateWithFlags(&evJoin, cudaEventDisableTiming);

    const int gemm_blocks = (NODES + 127) / 128;   // 391

    cudaEventRecord(evFork, 0);
    cudaStreamWaitEvent(sG, evFork, 0);

    // default stream: CSR build chain
    zero_init_kernel<<<(NODES + 255) / 256, 256>>>(out);          // 1
    deg_count_kernel<<<(NE + 255) / 256, 256>>>(ei, ew);          // 2
    // sG: weight split + gemm0 (depends only on x/conv_w) + we-sums
    bsplit_kernel<<<192, 256, 0, sG>>>(conv_w);                   // 3
    tgemm_kernel<<<gemm_blocks, 256, TG_SMEM, sG>>>(x, conv_b, 0, -1, NODES); // 4 <- ncu
    prep_we_kernel<<<1, 128, 0, sG>>>(l1w);                       // 5
    scan_kernel2<<<NSB, SBLK>>>();                                // 6
    csr_fill_kernel<<<(NE + 255) / 256, 256>>>(ei, ew);           // 7

    cudaEventRecord(evJoin, sG);
    cudaStreamWaitEvent(0, evJoin, 0);

    agg_kernel<<<agg_blocks, 256>>>(0);
    tgemm_kernel<<<gemm_blocks, 256, TG_SMEM>>>(x, conv_b + HID, 1, 0, NODES);
    agg_kernel<<<agg_blocks, 256>>>(1);
    tgemm_kernel<<<gemm_blocks, 256, TG_SMEM>>>(x, conv_b + 2 * HID, 2, 1, NODES);
    agg_kernel<<<agg_blocks, 256>>>(2);

    prep_base_kernel<<<1, 128>>>(l1w, l1b, curr);
    score_kernel<<<gemm_blocks, 256>>>(l1w, l2w, l2b, ecn, parts, h, out);
}

// round 15
// speedup vs baseline: 1.1240x; 1.0230x over previous
#include <cuda_runtime.h>
#include <cuda_bf16.h>
#include <mma.h>

#define NODES 50000
#define NE    800000
#define HID   128
#define NPART 32
#define BN_EPS 1e-5f
#define SBLK  512
#define NSB   ((NODES + SBLK - 1) / SBLK)   // 98

typedef unsigned long long ull;
using namespace nvcuda;

// ---------------- scratch (device globals; no runtime alloc) ----------------
__device__ float g_deg[NODES];
__device__ int   g_cnt[NODES];
__device__ int   g_off[NODES + 1];
__device__ int   g_cur[NODES];
__device__ float g_dinv[NODES];
__device__ int   g_aggv[NSB];
__device__ volatile int g_flag[NSB];
__device__ int2  g_csr[NE];                 // {src, float_as_int(norm)}
__device__ float g_hw[NODES * HID];
__device__ float g_agg[NODES * HID];
__device__ float g_stats[3 * 2 * HID];      // per layer: [0:128) sum, [128:256) sumsq
__device__ float g_base[HID];
__device__ float g_we[HID];
// pre-split conv weights, row-major [K][N] bf16, per layer 16384 elems
__device__ __nv_bfloat16 g_bhi[3 * 16384];
__device__ __nv_bfloat16 g_blo[3 * 16384];

// ---------------- f32x2 helpers (score kernel) ----------------
__device__ __forceinline__ ull pk2(float lo, float hi) {
    ull r;
    asm("mov.b64 %0, {%1, %2};" : "=l"(r) : "f"(lo), "f"(hi));
    return r;
}
__device__ __forceinline__ void fma2(ull& d, ull a, ull b) {
    asm("fma.rn.f32x2 %0, %1, %2, %0;" : "+l"(d) : "l"(a), "l"(b));
}
__device__ __forceinline__ float2 upk2(ull v) {
    float2 f;
    asm("mov.b64 {%0, %1}, %2;" : "=f"(f.x), "=f"(f.y) : "l"(v));
    return f;
}
// ---------------- cp.async helpers ----------------
__device__ __forceinline__ void cpasync16(void* smem_ptr, const void* gptr) {
    unsigned s = (unsigned)__cvta_generic_to_shared(smem_ptr);
    asm volatile("cp.async.cg.shared.global [%0], [%1], 16;"
                 :: "r"(s), "l"(gptr) : "memory");
}
__device__ __forceinline__ void cpasync_commit() {
    asm volatile("cp.async.commit_group;" ::: "memory");
}
__device__ __forceinline__ void cpasync_wait_all() {
    asm volatile("cp.async.wait_group 0;" ::: "memory");
}

// ---------------- init ----------------
__global__ void zero_init_kernel(float* out) {
    int i = blockIdx.x * blockDim.x + threadIdx.x;
    if (i < NODES) { g_deg[i] = 0.f; g_cnt[i] = 0; g_cur[i] = 0; }
    if (i < NPART) out[i] = 0.f;
    if (i < 3 * 2 * HID) g_stats[i] = 0.f;
    if (i < NSB) g_flag[i] = 0;
}

// ---------------- degree + count ----------------
__global__ void deg_count_kernel(const int* __restrict__ ei,
                                 const float* __restrict__ ew) {
    int e = blockIdx.x * blockDim.x + threadIdx.x;
    if (e >= NE) return;
    int dst = ei[NE + e];
    atomicAdd(&g_deg[dst], ew[e]);
    atomicAdd(&g_cnt[dst], 1);
}

// ---------------- single-kernel scan (decoupled lookback) + dinv fused ----------------
__global__ __launch_bounds__(SBLK) void scan_kernel2() {
    __shared__ int ws[SBLK / 32];
    __shared__ int s_prefix;
    int t = threadIdx.x, lane = t & 31, w = t >> 5;
    int bid = blockIdx.x;
    int i = bid * SBLK + t;
    int v = (i < NODES) ? g_cnt[i] : 0;
    if (i < NODES) g_dinv[i] = rsqrtf(g_deg[i] + 1.0f);

    int inc = v;
    #pragma unroll
    for (int o = 1; o < 32; o <<= 1) {
        int u = __shfl_up_sync(0xffffffffu, inc, o);
        if (lane >= o) inc += u;
    }
    if (lane == 31) ws[w] = inc;
    __syncthreads();

    if (w == 0 && lane < SBLK / 32) {
        int x = ws[lane];
        int xi = x;
        #pragma unroll
        for (int o = 1; o < 16; o <<= 1) {
            int u = __shfl_up_sync(0x0000ffffu, xi, o);
            if (lane >= o) xi += u;
        }
        ws[lane] = xi - x;
        if (lane == SBLK / 32 - 1) {
            g_aggv[bid] = xi;
            __threadfence();
            g_flag[bid] = 1;
        }
    }
    __syncthreads();

    if (w == 0) {
        int sum = 0;
        for (int base = 0; base < bid; base += 32) {
            int p = base + lane;
            int a = 0;
            if (p < bid) {
                while (g_flag[p] == 0) { }
                __threadfence();
                a = g_aggv[p];
            }
            #pragma unroll
            for (int o = 16; o; o >>= 1) a += __shfl_down_sync(0xffffffffu, a, o);
            if (lane == 0) sum += a;
        }
        if (lane == 0) s_prefix = sum;
    }
    __syncthreads();

    int pref = s_prefix;
    if (i < NODES) g_off[i] = pref + ws[w] + inc - v;
    if (bid == NSB - 1 && t == SBLK - 1) g_off[NODES] = pref + ws[w] + inc;
}

// ---------------- CSR fill (interleaved) ----------------
__global__ void csr_fill_kernel(const int* __restrict__ ei,
                                const float* __restrict__ ew) {
    int e = blockIdx.x * blockDim.x + threadIdx.x;
    if (e >= NE) return;
    int src = ei[e];
    int dst = ei[NE + e];
    int pos = g_off[dst] + atomicAdd(&g_cur[dst], 1);
    float norm = g_dinv[src] * ew[e] * g_dinv[dst];
    g_csr[pos] = make_int2(src, __float_as_int(norm));
}

// ---------------- W pre-split into row-major bf16 hi/lo ----------------
__global__ void bsplit_kernel(const float* __restrict__ conv_w) {
    int idx = blockIdx.x * blockDim.x + threadIdx.x;
    if (idx >= 3 * 16384) return;
    float wv = conv_w[idx];
    __nv_bfloat16 h = __float2bfloat16(wv);
    float res = wv - __bfloat162float(h);
    g_bhi[idx] = h;
    g_blo[idx] = __float2bfloat16(res);
}

// ==================== WMMA bf16x3 GEMM: g_hw = act(A) @ W + bias ====================
// 256 threads, 128x128 tile, K=128. 8 warps 4x2 -> 32x64 warp tiles.
// smem: A_hi/A_lo full [128][136]; B hi/lo double-buffered 32-K-row chunks.
// Total 105984 B -> 2 blocks/SM (vs 1 at R14).
#define LDM 136
#define A_TILE (128 * LDM * 2)          // 34816
#define B_CHUNK (32 * LDM * 2)          // 8704
#define TG_SMEM (2 * A_TILE + 4 * B_CHUNK + 1536)   // 105984
__global__ __launch_bounds__(256, 2)
void tgemm_kernel(const float* __restrict__ A, const float* __restrict__ bias,
                  int wsel, int bnlayer, int nrows)
{
    extern __shared__ char dsm[];
    __nv_bfloat16* Ah = (__nv_bfloat16*)dsm;
    __nv_bfloat16* Al = (__nv_bfloat16*)(dsm + A_TILE);
    // B buffers: [buf][hi/lo]
    __nv_bfloat16* Bh[2] = { (__nv_bfloat16*)(dsm + 2 * A_TILE),
                             (__nv_bfloat16*)(dsm + 2 * A_TILE + B_CHUNK) };
    __nv_bfloat16* Bl[2] = { (__nv_bfloat16*)(dsm + 2 * A_TILE + 2 * B_CHUNK),
                             (__nv_bfloat16*)(dsm + 2 * A_TILE + 3 * B_CHUNK) };
    float* smean  = (float*)(dsm + 2 * A_TILE + 4 * B_CHUNK);
    float* sscale = (float*)(dsm + 2 * A_TILE + 4 * B_CHUNK + 512);
    float* sbias  = (float*)(dsm + 2 * A_TILE + 4 * B_CHUNK + 1024);

    int tid = threadIdx.x;
    int wid = tid >> 5;
    int warp_m = wid >> 1;          // 0..3
    int warp_n = wid & 1;           // 0..1
    int row0 = blockIdx.x * 128;
    const bool bn = (bnlayer >= 0);
    const float* __restrict__ src = bn ? (const float*)g_agg : A;
    const char* bhg = (const char*)(g_bhi + (size_t)wsel * 16384);
    const char* blg = (const char*)(g_blo + (size_t)wsel * 16384);

    if (tid < HID) {
        if (bn) {
            float m = g_stats[bnlayer * 256 + tid] * (1.0f / NODES);
            float v = g_stats[bnlayer * 256 + HID + tid] * (1.0f / NODES) - m * m;
            smean[tid]  = m;
            sscale[tid] = rsqrtf(v + BN_EPS);
        }
        sbias[tid] = bias[tid];
    }

    // ---- B chunk 0 in flight (32 K-rows, hi+lo) ----
    {
        int g = tid + 0 * 256;               // 2 iterations: tid, tid+256
        #pragma unroll
        for (int it = 0; it < 2; it++) {
            int gg = tid + it * 256;         // 0..511
            int k = gg >> 4, seg = gg & 15;
            cpasync16((char*)Bh[0] + k * (LDM * 2) + seg * 16, bhg + k * 256 + seg * 16);
            cpasync16((char*)Bl[0] + k * (LDM * 2) + seg * 16, blg + k * 256 + seg * 16);
        }
        (void)g;
        cpasync_commit();
    }
    __syncthreads();   // smean/sscale/sbias visible

    // ---- stage full A: fp32 load -> BN+ReLU -> hi/lo split ----
    #pragma unroll 4
    for (int it = 0; it < 16; it++) {
        int idx4 = tid + it * 256;           // 0..4095 float4s
        int r = idx4 >> 5, k4 = idx4 & 31;
        float4 v = make_float4(0.f, 0.f, 0.f, 0.f);
        int row = row0 + r;
        if (row < nrows)
            v = *(const float4*)(src + (size_t)row * HID + k4 * 4);
        float f[4] = { v.x, v.y, v.z, v.w };
        if (bn) {
            int c0 = k4 * 4;
            #pragma unroll
            for (int j = 0; j < 4; j++)
                f[j] = fmaxf((f[j] - smean[c0 + j]) * sscale[c0 + j], 0.f);
        }
        ushort4 hv, lv;
        unsigned short* hp = (unsigned short*)&hv;
        unsigned short* lp = (unsigned short*)&lv;
        #pragma unroll
        for (int j = 0; j < 4; j++) {
            __nv_bfloat16 h = __float2bfloat16(f[j]);
            float res = f[j] - __bfloat162float(h);
            __nv_bfloat16 l = __float2bfloat16(res);
            hp[j] = *(unsigned short*)&h;
            lp[j] = *(unsigned short*)&l;
        }
        unsigned off = (unsigned)r * LDM + k4 * 4;
        *(ushort4*)(Ah + off) = hv;
        *(ushort4*)(Al + off) = lv;
    }

    wmma::fragment<wmma::accumulator, 16, 16, 16, float> acc[2][4];
    #pragma unroll
    for (int i = 0; i < 2; i++)
        #pragma unroll
        for (int j = 0; j < 4; j++)
            wmma::fill_fragment(acc[i][j], 0.0f);

    // ---- mainloop over 4 K-chunks of 32 (R9 double-buffer pattern) ----
    #pragma unroll 1
    for (int c = 0; c < 4; c++) {
        cpasync_wait_all();     // B chunk c landed
        __syncthreads();        // all see it; other buffer free (and A staged on c=0)
        int nb = (c + 1) & 1;
        if (c + 1 < 4) {
            #pragma unroll
            for (int it = 0; it < 2; it++) {
                int gg = tid + it * 256;
                int k = gg >> 4, seg = gg & 15;
                cpasync16((char*)Bh[nb] + k * (LDM * 2) + seg * 16,
                          bhg + ((c + 1) * 32 + k) * 256 + seg * 16);
                cpasync16((char*)Bl[nb] + k * (LDM * 2) + seg * 16,
                          blg + ((c + 1) * 32 + k) * 256 + seg * 16);
            }
            cpasync_commit();
        }
        const __nv_bfloat16* bh_s = Bh[c & 1];
        const __nv_bfloat16* bl_s = Bl[c & 1];
        #pragma unroll
        for (int k16 = 0; k16 < 2; k16++) {
            int ks = k16 * 16;                   // row in chunk
            int kg = c * 32 + ks;                // col in A tiles
            wmma::fragment<wmma::matrix_b, 16, 16, 16, __nv_bfloat16, wmma::row_major> bh[4], bl[4];
            #pragma unroll
            for (int j = 0; j < 4; j++) {
                int c0 = warp_n * 64 + j * 16;
                wmma::load_matrix_sync(bh[j], bh_s + (size_t)ks * LDM + c0, LDM);
                wmma::load_matrix_sync(bl[j], bl_s + (size_t)ks * LDM + c0, LDM);
            }
            #pragma unroll
            for (int i = 0; i < 2; i++) {
                int r0 = warp_m * 32 + i * 16;
                wmma::fragment<wmma::matrix_a, 16, 16, 16, __nv_bfloat16, wmma::row_major> ah, al;
                wmma::load_matrix_sync(ah, Ah + (size_t)r0 * LDM + kg, LDM);
                wmma::load_matrix_sync(al, Al + (size_t)r0 * LDM + kg, LDM);
                #pragma unroll
                for (int j = 0; j < 4; j++) {
                    wmma::mma_sync(acc[i][j], ah, bh[j], acc[i][j]);
                    wmma::mma_sync(acc[i][j], ah, bl[j], acc[i][j]);
                    wmma::mma_sync(acc[i][j], al, bh[j], acc[i][j]);
                }
            }
        }
        __syncthreads();   // done reading buffer c before it is refilled (c+2)
    }

    // ---- epilogue: smem round-trip + bias ----
    float* fout = (float*)dsm;   // [128][LDM] floats (69632 B <= 2*A_TILE)
    #pragma unroll
    for (int i = 0; i < 2; i++)
        #pragma unroll
        for (int j = 0; j < 4; j++) {
            int r0 = warp_m * 32 + i * 16;
            int c0 = warp_n * 64 + j * 16;
            wmma::store_matrix_sync(fout + (size_t)r0 * LDM + c0, acc[i][j],
                                    LDM, wmma::mem_row_major);
        }
    __syncthreads();

    #pragma unroll 4
    for (int it = 0; it < 16; it++) {
        int idx4 = tid + it * 256;
        int r = idx4 >> 5, c4 = idx4 & 31;
        int row = row0 + r;
        if (row < nrows) {
            const float* s = fout + (size_t)r * LDM + c4 * 4;
            float4 ov = make_float4(s[0] + sbias[c4 * 4 + 0],
                                    s[1] + sbias[c4 * 4 + 1],
                                    s[2] + sbias[c4 * 4 + 2],
                                    s[3] + sbias[c4 * 4 + 3]);
            *(float4*)(g_hw + (size_t)row * HID + c4 * 4) = ov;
        }
    }
}

// ---------------- aggregation (warp per node, gather unrolled x4) + BN stats ----------------
__global__ __launch_bounds__(256) void agg_kernel(int layer) {
    __shared__ float bsum[HID];
    __shared__ float bss[HID];
    int tid = threadIdx.x;
    for (int i = tid; i < HID; i += blockDim.x) { bsum[i] = 0.f; bss[i] = 0.f; }
    __syncthreads();

    int lane = tid & 31;
    int wglobal = (blockIdx.x * blockDim.x + tid) >> 5;
    int nwarps  = (gridDim.x * blockDim.x) >> 5;

    float ls0 = 0.f, ls1 = 0.f, ls2 = 0.f, ls3 = 0.f;
    float lq0 = 0.f, lq1 = 0.f, lq2 = 0.f, lq3 = 0.f;

    for (int n = wglobal; n < NODES; n += nwarps) {
        float dv = g_dinv[n];
        float sn = dv * dv;
        float4 a = ((const float4*)(g_hw + (size_t)n * HID))[lane];
        float4 acc = make_float4(a.x * sn, a.y * sn, a.z * sn, a.w * sn);
        int beg = g_off[n], end = g_off[n + 1];
        int i = beg;
        for (; i + 4 <= end; i += 4) {
            int2 e0 = g_csr[i],     e1 = g_csr[i + 1];
            int2 e2 = g_csr[i + 2], e3 = g_csr[i + 3];
            float w0 = __int_as_float(e0.y), w1 = __int_as_float(e1.y);
            float w2 = __int_as_float(e2.y), w3 = __int_as_float(e3.y);
            float4 v0 = ((const float4*)(g_hw + (size_t)e0.x * HID))[lane];
            float4 v1 = ((const float4*)(g_hw + (size_t)e1.x * HID))[lane];
            float4 v2 = ((const float4*)(g_hw + (size_t)e2.x * HID))[lane];
            float4 v3 = ((const float4*)(g_hw + (size_t)e3.x * HID))[lane];
            acc.x += w0 * v0.x + w1 * v1.x + w2 * v2.x + w3 * v3.x;
            acc.y += w0 * v0.y + w1 * v1.y + w2 * v2.y + w3 * v3.y;
            acc.z += w0 * v0.z + w1 * v1.z + w2 * v2.z + w3 * v3.z;
            acc.w += w0 * v0.w + w1 * v1.w + w2 * v2.w + w3 * v3.w;
        }
        for (; i + 2 <= end; i += 2) {
            int2 e0 = g_csr[i], e1 = g_csr[i + 1];
            float w0 = __int_as_float(e0.y), w1 = __int_as_float(e1.y);
            float4 v0 = ((const float4*)(g_hw + (size_t)e0.x * HID))[lane];
            float4 v1 = ((const float4*)(g_hw + (size_t)e1.x * HID))[lane];
            acc.x += w0 * v0.x + w1 * v1.x;
            acc.y += w0 * v0.y + w1 * v1.y;
            acc.z += w0 * v0.z + w1 * v1.z;
            acc.w += w0 * v0.w + w1 * v1.w;
        }
        if (i < end) {
            int2 e0 = g_csr[i];
            float w = __int_as_float(e0.y);
            float4 v = ((const float4*)(g_hw + (size_t)e0.x * HID))[lane];
            acc.x += w * v.x; acc.y += w * v.y;
            acc.z += w * v.z; acc.w += w * v.w;
        }
        ((float4*)(g_agg + (size_t)n * HID))[lane] = acc;
        ls0 += acc.x; ls1 += acc.y; ls2 += acc.z; ls3 += acc.w;
        lq0 += acc.x * acc.x; lq1 += acc.y * acc.y;
        lq2 += acc.z * acc.z; lq3 += acc.w * acc.w;
    }
    int c = lane * 4;
    atomicAdd(&bsum[c + 0], ls0); atomicAdd(&bsum[c + 1], ls1);
    atomicAdd(&bsum[c + 2], ls2); atomicAdd(&bsum[c + 3], ls3);
    atomicAdd(&bss[c + 0], lq0);  atomicAdd(&bss[c + 1], lq1);
    atomicAdd(&bss[c + 2], lq2);  atomicAdd(&bss[c + 3], lq3);
    __syncthreads();
    for (int i = tid; i < HID; i += blockDim.x) {
        atomicAdd(&g_stats[layer * 256 + i],       bsum[i]);
        atomicAdd(&g_stats[layer * 256 + HID + i], bss[i]);
    }
}

// ---------------- prep split ----------------
__global__ void prep_we_kernel(const float* __restrict__ l1w) {
    int j = threadIdx.x;
    float we = 0.f;
    #pragma unroll 8
    for (int k = 2 * HID; k < 4 * HID; k++)
        we += l1w[(size_t)k * HID + j];
    g_we[j] = we;
}

__global__ void prep_base_kernel(const float* __restrict__ l1w,
                                 const float* __restrict__ l1b,
                                 const int* __restrict__ curr) {
    __shared__ float xs[HID];
    int j = threadIdx.x;
    int c = *curr;
    float m = g_stats[2 * 256 + j] * (1.0f / NODES);
    float v = g_stats[2 * 256 + HID + j] * (1.0f / NODES) - m * m;
    float sc = rsqrtf(v + BN_EPS);
    xs[j] = fmaxf((g_agg[(size_t)c * HID + j] - m) * sc, 0.f);
    __syncthreads();
    float acc = 0.f;
    #pragma unroll 8
    for (int k = 0; k < HID; k++)
        acc += xs[k] * l1w[(size_t)(HID + k) * HID + j];
    g_base[j] = l1b[j] + acc;
}

// ==================== pipelined scoring (R9-proven, unchanged) ====================
#define KC 16
#define NCHUNK (HID / KC)
__global__ __launch_bounds__(256, 2) void score_kernel(
    const float* __restrict__ W,
    const float* __restrict__ l2w, const float* __restrict__ l2b,
    const float* __restrict__ ecn, const float* __restrict__ parts,
    float* __restrict__ h, float* __restrict__ out)
{
    __shared__ float As[2][KC * 132];
    __shared__ float Bs[2][KC * 128];
    __shared__ float smean[HID], sscale[HID];
    __shared__ float sarr[128];
    __shared__ float pp[NPART];
    int tid = threadIdx.x;
    int tr = tid >> 4, tc = tid & 15;
    int row0 = blockIdx.x * 128;

    if (tid < HID) {
        float m = g_stats[2 * 256 + tid] * (1.0f / NODES);
        float v = g_stats[2 * 256 + HID + tid] * (1.0f / NODES) - m * m;
        smean[tid]  = m;
        sscale[tid] = rsqrtf(v + BN_EPS);
    }

    int rA[2], k4A[2];
    bool okA[2];
    #pragma unroll
    for (int i = 0; i < 2; i++) {
        int slot = tid + i * 256;
        rA[i]  = slot >> 2;
        k4A[i] = slot & 3;
        okA[i] = (row0 + rA[i]) < NODES;
    }
    int kB[2], c4B[2];
    #pragma unroll
    for (int i = 0; i < 2; i++) {
        int slot = tid + i * 256;
        kB[i]  = slot >> 5;
        c4B[i] = slot & 31;
    }

    ull acc[4][8];
    #pragma unroll
    for (int i = 0; i < 4; i++)
        #pragma unroll
        for (int j = 0; j < 8; j++) acc[i][j] = 0ull;

    float4 pa[2];
    #pragma unroll
    for (int i = 0; i < 2; i++)
        pa[i] = okA[i]
              ? *(const float4*)(g_agg + (size_t)(row0 + rA[i]) * HID + k4A[i] * 4)
              : make_float4(0.f, 0.f, 0.f, 0.f);
    #pragma unroll
    for (int i = 0; i < 2; i++)
        cpasync16(&Bs[0][kB[i] * 128 + c4B[i] * 4],
                  W + (size_t)kB[i] * HID + c4B[i] * 4);
    cpasync_commit();
    __syncthreads();
    #pragma unroll
    for (int i = 0; i < 2; i++) {
        float v4[4] = { pa[i].x, pa[i].y, pa[i].z, pa[i].w };
        float o4[4];
        #pragma unroll
        for (int j = 0; j < 4; j++) {
            int col = k4A[i] * 4 + j;
            o4[j] = fmaxf((v4[j] - smean[col]) * sscale[col], 0.f);
            As[0][col * 132 + rA[i]] = o4[j];
        }
        if (okA[i])
            *(float4*)(h + (size_t)(row0 + rA[i]) * HID + k4A[i] * 4) =
                make_float4(o4[0], o4[1], o4[2], o4[3]);
    }
    #pragma unroll
    for (int i = 0; i < 2; i++)
        pa[i] = okA[i]
              ? *(const float4*)(g_agg + (size_t)(row0 + rA[i]) * HID + KC + k4A[i] * 4)
              : make_float4(0.f, 0.f, 0.f, 0.f);

    #pragma unroll 1
    for (int c = 0; c < NCHUNK; c++) {
        cpasync_wait_all();
        __syncthreads();
        int nb = (c + 1) & 1;
        if (c + 1 < NCHUNK) {
            #pragma unroll
            for (int i = 0; i < 2; i++)
                cpasync16(&Bs[nb][kB[i] * 128 + c4B[i] * 4],
                          W + (size_t)((c + 1) * KC + kB[i]) * HID + c4B[i] * 4);
            cpasync_commit();
            #pragma unroll
            for (int i = 0; i < 2; i++) {
                float v4[4] = { pa[i].x, pa[i].y, pa[i].z, pa[i].w };
                float o4[4];
                #pragma unroll
                for (int j = 0; j < 4; j++) {
                    int col = (c + 1) * KC + k4A[i] * 4 + j;
                    o4[j] = fmaxf((v4[j] - smean[col]) * sscale[col], 0.f);
                    As[nb][(k4A[i] * 4 + j) * 132 + rA[i]] = o4[j];
                }
                if (okA[i])
                    *(float4*)(h + (size_t)(row0 + rA[i]) * HID
                               + (c + 1) * KC + k4A[i] * 4) =
                        make_float4(o4[0], o4[1], o4[2], o4[3]);
            }
        }
        if (c + 2 < NCHUNK) {
            #pragma unroll
            for (int i = 0; i < 2; i++)
                pa[i] = okA[i]
                      ? *(const float4*)(g_agg + (size_t)(row0 + rA[i]) * HID
                                         + (c + 2) * KC + k4A[i] * 4)
                      : make_float4(0.f, 0.f, 0.f, 0.f);
        }
        const float* as = As[c & 1];
        const float* bs = Bs[c & 1];
        #pragma unroll
        for (int k = 0; k < KC; k++) {
            float4 a0 = *(const float4*)(as + k * 132 + tr * 8);
            float4 a1 = *(const float4*)(as + k * 132 + tr * 8 + 4);
            float4 b0 = *(const float4*)(bs + k * 128 + tc * 8);
            float4 b1 = *(const float4*)(bs + k * 128 + tc * 8 + 4);
            ull ap[4] = { pk2(a0.x, a0.y), pk2(a0.z, a0.w),
                          pk2(a1.x, a1.y), pk2(a1.z, a1.w) };
            ull bd[8] = { pk2(b0.x, b0.x), pk2(b0.y, b0.y),
                          pk2(b0.z, b0.z), pk2(b0.w, b0.w),
                          pk2(b1.x, b1.x), pk2(b1.y, b1.y),
                          pk2(b1.z, b1.z), pk2(b1.w, b1.w) };
            #pragma unroll
            for (int i = 0; i < 4; i++)
                #pragma unroll
                for (int j = 0; j < 8; j++)
                    fma2(acc[i][j], ap[i], bd[j]);
        }
    }

    float w2[8], bb[8], wev[8];
    #pragma unroll
    for (int j = 0; j < 8; j++) {
        w2[j]  = l2w[tc * 8 + j];
        bb[j]  = g_base[tc * 8 + j];
        wev[j] = g_we[tc * 8 + j];
    }
    float b2 = l2b[0];
    #pragma unroll
    for (int i2 = 0; i2 < 4; i2++) {
        float2 v[8];
        #pragma unroll
        for (int j = 0; j < 8; j++) v[j] = upk2(acc[i2][j]);
        #pragma unroll
        for (int half = 0; half < 2; half++) {
            int row = row0 + tr * 8 + i2 * 2 + half;
            float e = (row < NODES) ? ecn[row] : 0.f;
            float s = 0.f;
            #pragma unroll
            for (int j = 0; j < 8; j++) {
                float val = half ? v[j].y : v[j].x;
                float t = val + bb[j] + e * wev[j];
                s += fmaxf(t, 0.f) * w2[j];
            }
            s += __shfl_xor_sync(0xffffffffu, s, 8, 16);
            s += __shfl_xor_sync(0xffffffffu, s, 4, 16);
            s += __shfl_xor_sync(0xffffffffu, s, 2, 16);
            s += __shfl_xor_sync(0xffffffffu, s, 1, 16);
            if (tc == 0) sarr[tr * 8 + i2 * 2 + half] = (row < NODES) ? (s + b2) : 0.f;
        }
    }
    if (tid < NPART) pp[tid] = 0.f;
    __syncthreads();
    int p = tid & 31, g = tid >> 5;
    float psum = 0.f;
    for (int r = g * 16; r < g * 16 + 16; r++) {
        int row = row0 + r;
        if (row < NODES) psum += sarr[r] * parts[(size_t)row * NPART + p];
    }
    atomicAdd(&pp[p], psum);
    __syncthreads();
    if (tid < NPART) atomicAdd(&out[tid], pp[tid]);
}

// ---------------- launcher ----------------
extern "C" void kernel_launch(void* const* d_in, const int* in_sizes, int n_in,
                              void* d_out, int out_size) {
    const float* x      = (const float*)d_in[0];
    const int*   ei     = (const int*)d_in[1];
    const float* ew     = (const float*)d_in[2];
    const float* parts  = (const float*)d_in[3];
    const float* ecn    = (const float*)d_in[5];
    const float* conv_w = (const float*)d_in[6];
    const float* conv_b = (const float*)d_in[7];
    const float* l1w    = (const float*)d_in[8];
    const float* l1b    = (const float*)d_in[9];
    const float* l2w    = (const float*)d_in[10];
    const float* l2b    = (const float*)d_in[11];
    const int*   curr   = (const int*)d_in[12];

    float* out = (float*)d_out;          // [0:32) partition scores
    float* h   = out + NPART;            // [32 : 32+N*H) final h

    cudaFuncSetAttribute(tgemm_kernel,
                         cudaFuncAttributeMaxDynamicSharedMemorySize, TG_SMEM);

    int agg_blocks = 1184;
    {
        int dev = 0, sms = 0, maxb = 0;
        if (cudaGetDevice(&dev) == cudaSuccess &&
            cudaDeviceGetAttribute(&sms, cudaDevAttrMultiProcessorCount, dev) == cudaSuccess &&
            cudaOccupancyMaxActiveBlocksPerMultiprocessor(&maxb, agg_kernel, 256, 0) == cudaSuccess &&
            sms > 0 && maxb > 0) {
            agg_blocks = sms * maxb;
        }
    }

    cudaStream_t sG;
    cudaStreamCreateWithFlags(&sG, cudaStreamNonBlocking);
    cudaEvent_t evFork, evJoin;
    cudaEventCreateWithFlags(&evFork, cudaEventDisableTiming);
    cudaEventCreateWithFlags(&evJoin, cudaEventDisableTiming);

    const int gemm_blocks = (NODES + 127) / 128;   // 391

    cudaEventRecord(evFork, 0);
    cudaStreamWaitEvent(sG, evFork, 0);

    // default stream: CSR build chain
    zero_init_kernel<<<(NODES + 255) / 256, 256>>>(out);          // 1
    deg_count_kernel<<<(NE + 255) / 256, 256>>>(ei, ew);          // 2
    // sG: weight split + gemm0 (depends only on x/conv_w) + we-sums
    bsplit_kernel<<<192, 256, 0, sG>>>(conv_w);                   // 3
    tgemm_kernel<<<gemm_blocks, 256, TG_SMEM, sG>>>(x, conv_b, 0, -1, NODES); // 4 <- ncu
    prep_we_kernel<<<1, 128, 0, sG>>>(l1w);                       // 5
    scan_kernel2<<<NSB, SBLK>>>();                                // 6
    csr_fill_kernel<<<(NE + 255) / 256, 256>>>(ei, ew);           // 7

    cudaEventRecord(evJoin, sG);
    cudaStreamWaitEvent(0, evJoin, 0);

    agg_kernel<<<agg_blocks, 256>>>(0);
    tgemm_kernel<<<gemm_blocks, 256, TG_SMEM>>>(x, conv_b + HID, 1, 0, NODES);
    agg_kernel<<<agg_blocks, 256>>>(1);
    tgemm_kernel<<<gemm_blocks, 256, TG_SMEM>>>(x, conv_b + 2 * HID, 2, 1, NODES);
    agg_kernel<<<agg_blocks, 256>>>(2);

    prep_base_kernel<<<1, 128>>>(l1w, l1b, curr);
    score_kernel<<<gemm_blocks, 256>>>(l1w, l2w, l2b, ecn, parts, h, out);
}

// round 16
// speedup vs baseline: 1.1551x; 1.0277x over previous
#include <cuda_runtime.h>
#include <cuda_bf16.h>
#include <mma.h>

#define NODES 50000
#define NE    800000
#define HID   128
#define NPART 32
#define BN_EPS 1e-5f
#define SBLK  512
#define NSB   ((NODES + SBLK - 1) / SBLK)   // 98

typedef unsigned long long ull;
using namespace nvcuda;

// ---------------- scratch (device globals; no runtime alloc) ----------------
__device__ float g_deg[NODES];
__device__ int   g_cnt[NODES];
__device__ int   g_off[NODES + 1];
__device__ int   g_cur[NODES];
__device__ float g_dinv[NODES];
__device__ int   g_aggv[NSB];
__device__ volatile int g_flag[NSB];
__device__ int2  g_csr[NE];                 // {src, float_as_int(norm)}
__device__ float g_hw[NODES * HID];
__device__ float g_agg[NODES * HID];
__device__ float g_stats[3 * 2 * HID];      // per layer: [0:128) sum, [128:256) sumsq
__device__ float g_base[HID];
__device__ float g_we[HID];
// pre-split weights, row-major [K][N] bf16: slots 0..2 = conv layers, 3 = l1w rows 0..127
__device__ __nv_bfloat16 g_bhi[4 * 16384];
__device__ __nv_bfloat16 g_blo[4 * 16384];

// ---------------- cp.async helpers ----------------
__device__ __forceinline__ void cpasync16(void* smem_ptr, const void* gptr) {
    unsigned s = (unsigned)__cvta_generic_to_shared(smem_ptr);
    asm volatile("cp.async.cg.shared.global [%0], [%1], 16;"
                 :: "r"(s), "l"(gptr) : "memory");
}
__device__ __forceinline__ void cpasync_commit() {
    asm volatile("cp.async.commit_group;" ::: "memory");
}
__device__ __forceinline__ void cpasync_wait_all() {
    asm volatile("cp.async.wait_group 0;" ::: "memory");
}

// ---------------- init ----------------
__global__ void zero_init_kernel(float* out) {
    int i = blockIdx.x * blockDim.x + threadIdx.x;
    if (i < NODES) { g_deg[i] = 0.f; g_cnt[i] = 0; g_cur[i] = 0; }
    if (i < NPART) out[i] = 0.f;
    if (i < 3 * 2 * HID) g_stats[i] = 0.f;
    if (i < NSB) g_flag[i] = 0;
}

// ---------------- degree + count ----------------
__global__ void deg_count_kernel(const int* __restrict__ ei,
                                 const float* __restrict__ ew) {
    int e = blockIdx.x * blockDim.x + threadIdx.x;
    if (e >= NE) return;
    int dst = ei[NE + e];
    atomicAdd(&g_deg[dst], ew[e]);
    atomicAdd(&g_cnt[dst], 1);
}

// ---------------- single-kernel scan (decoupled lookback) + dinv fused ----------------
__global__ __launch_bounds__(SBLK) void scan_kernel2() {
    __shared__ int ws[SBLK / 32];
    __shared__ int s_prefix;
    int t = threadIdx.x, lane = t & 31, w = t >> 5;
    int bid = blockIdx.x;
    int i = bid * SBLK + t;
    int v = (i < NODES) ? g_cnt[i] : 0;
    if (i < NODES) g_dinv[i] = rsqrtf(g_deg[i] + 1.0f);

    int inc = v;
    #pragma unroll
    for (int o = 1; o < 32; o <<= 1) {
        int u = __shfl_up_sync(0xffffffffu, inc, o);
        if (lane >= o) inc += u;
    }
    if (lane == 31) ws[w] = inc;
    __syncthreads();

    if (w == 0 && lane < SBLK / 32) {
        int x = ws[lane];
        int xi = x;
        #pragma unroll
        for (int o = 1; o < 16; o <<= 1) {
            int u = __shfl_up_sync(0x0000ffffu, xi, o);
            if (lane >= o) xi += u;
        }
        ws[lane] = xi - x;
        if (lane == SBLK / 32 - 1) {
            g_aggv[bid] = xi;
            __threadfence();
            g_flag[bid] = 1;
        }
    }
    __syncthreads();

    if (w == 0) {
        int sum = 0;
        for (int base = 0; base < bid; base += 32) {
            int p = base + lane;
            int a = 0;
            if (p < bid) {
                while (g_flag[p] == 0) { }
                __threadfence();
                a = g_aggv[p];
            }
            #pragma unroll
            for (int o = 16; o; o >>= 1) a += __shfl_down_sync(0xffffffffu, a, o);
            if (lane == 0) sum += a;
        }
        if (lane == 0) s_prefix = sum;
    }
    __syncthreads();

    int pref = s_prefix;
    if (i < NODES) g_off[i] = pref + ws[w] + inc - v;
    if (bid == NSB - 1 && t == SBLK - 1) g_off[NODES] = pref + ws[w] + inc;
}

// ---------------- CSR fill (interleaved) ----------------
__global__ void csr_fill_kernel(const int* __restrict__ ei,
                                const float* __restrict__ ew) {
    int e = blockIdx.x * blockDim.x + threadIdx.x;
    if (e >= NE) return;
    int src = ei[e];
    int dst = ei[NE + e];
    int pos = g_off[dst] + atomicAdd(&g_cur[dst], 1);
    float norm = g_dinv[src] * ew[e] * g_dinv[dst];
    g_csr[pos] = make_int2(src, __float_as_int(norm));
}

// ---------------- W pre-split: conv layers 0..2 + l1w rows 0..127 into slot 3 ----------------
__global__ void bsplit_kernel(const float* __restrict__ conv_w,
                              const float* __restrict__ l1w) {
    int idx = blockIdx.x * blockDim.x + threadIdx.x;
    if (idx >= 4 * 16384) return;
    int L = idx >> 14;
    int rem = idx & 16383;
    float wv = (L < 3) ? conv_w[(size_t)L * 16384 + rem] : l1w[rem];
    __nv_bfloat16 h = __float2bfloat16(wv);
    float res = wv - __bfloat162float(h);
    g_bhi[idx] = h;
    g_blo[idx] = __float2bfloat16(res);
}

// ==================== WMMA bf16x3 GEMM: g_hw = act(A) @ W + bias ====================
#define LDM 136
#define A_TILE (128 * LDM * 2)          // 34816
#define B_CHUNK (32 * LDM * 2)          // 8704
#define TG_SMEM (2 * A_TILE + 4 * B_CHUNK + 1536)   // 105984
__global__ __launch_bounds__(256, 2)
void tgemm_kernel(const float* __restrict__ A, const float* __restrict__ bias,
                  int wsel, int bnlayer, int nrows)
{
    extern __shared__ char dsm[];
    __nv_bfloat16* Ah = (__nv_bfloat16*)dsm;
    __nv_bfloat16* Al = (__nv_bfloat16*)(dsm + A_TILE);
    __nv_bfloat16* Bh[2] = { (__nv_bfloat16*)(dsm + 2 * A_TILE),
                             (__nv_bfloat16*)(dsm + 2 * A_TILE + B_CHUNK) };
    __nv_bfloat16* Bl[2] = { (__nv_bfloat16*)(dsm + 2 * A_TILE + 2 * B_CHUNK),
                             (__nv_bfloat16*)(dsm + 2 * A_TILE + 3 * B_CHUNK) };
    float* smean  = (float*)(dsm + 2 * A_TILE + 4 * B_CHUNK);
    float* sscale = (float*)(dsm + 2 * A_TILE + 4 * B_CHUNK + 512);
    float* sbias  = (float*)(dsm + 2 * A_TILE + 4 * B_CHUNK + 1024);

    int tid = threadIdx.x;
    int wid = tid >> 5;
    int warp_m = wid >> 1;
    int warp_n = wid & 1;
    int row0 = blockIdx.x * 128;
    const bool bn = (bnlayer >= 0);
    const float* __restrict__ src = bn ? (const float*)g_agg : A;
    const char* bhg = (const char*)(g_bhi + (size_t)wsel * 16384);
    const char* blg = (const char*)(g_blo + (size_t)wsel * 16384);

    if (tid < HID) {
        if (bn) {
            float m = g_stats[bnlayer * 256 + tid] * (1.0f / NODES);
            float v = g_stats[bnlayer * 256 + HID + tid] * (1.0f / NODES) - m * m;
            smean[tid]  = m;
            sscale[tid] = rsqrtf(v + BN_EPS);
        }
        sbias[tid] = bias[tid];
    }

    // B chunk 0 in flight
    #pragma unroll
    for (int it = 0; it < 2; it++) {
        int gg = tid + it * 256;
        int k = gg >> 4, seg = gg & 15;
        cpasync16((char*)Bh[0] + k * (LDM * 2) + seg * 16, bhg + k * 256 + seg * 16);
        cpasync16((char*)Bl[0] + k * (LDM * 2) + seg * 16, blg + k * 256 + seg * 16);
    }
    cpasync_commit();
    __syncthreads();

    // stage full A: fp32 -> BN+ReLU -> hi/lo split
    #pragma unroll 4
    for (int it = 0; it < 16; it++) {
        int idx4 = tid + it * 256;
        int r = idx4 >> 5, k4 = idx4 & 31;
        float4 v = make_float4(0.f, 0.f, 0.f, 0.f);
        int row = row0 + r;
        if (row < nrows)
            v = *(const float4*)(src + (size_t)row * HID + k4 * 4);
        float f[4] = { v.x, v.y, v.z, v.w };
        if (bn) {
            int c0 = k4 * 4;
            #pragma unroll
            for (int j = 0; j < 4; j++)
                f[j] = fmaxf((f[j] - smean[c0 + j]) * sscale[c0 + j], 0.f);
        }
        ushort4 hv, lv;
        unsigned short* hp = (unsigned short*)&hv;
        unsigned short* lp = (unsigned short*)&lv;
        #pragma unroll
        for (int j = 0; j < 4; j++) {
            __nv_bfloat16 h = __float2bfloat16(f[j]);
            float res = f[j] - __bfloat162float(h);
            __nv_bfloat16 l = __float2bfloat16(res);
            hp[j] = *(unsigned short*)&h;
            lp[j] = *(unsigned short*)&l;
        }
        unsigned off = (unsigned)r * LDM + k4 * 4;
        *(ushort4*)(Ah + off) = hv;
        *(ushort4*)(Al + off) = lv;
    }

    wmma::fragment<wmma::accumulator, 16, 16, 16, float> acc[2][4];
    #pragma unroll
    for (int i = 0; i < 2; i++)
        #pragma unroll
        for (int j = 0; j < 4; j++)
            wmma::fill_fragment(acc[i][j], 0.0f);

    #pragma unroll 1
    for (int c = 0; c < 4; c++) {
        cpasync_wait_all();
        __syncthreads();
        int nb = (c + 1) & 1;
        if (c + 1 < 4) {
            #pragma unroll
            for (int it = 0; it < 2; it++) {
                int gg = tid + it * 256;
                int k = gg >> 4, seg = gg & 15;
                cpasync16((char*)Bh[nb] + k * (LDM * 2) + seg * 16,
                          bhg + ((c + 1) * 32 + k) * 256 + seg * 16);
                cpasync16((char*)Bl[nb] + k * (LDM * 2) + seg * 16,
                          blg + ((c + 1) * 32 + k) * 256 + seg * 16);
            }
            cpasync_commit();
        }
        const __nv_bfloat16* bh_s = Bh[c & 1];
        const __nv_bfloat16* bl_s = Bl[c & 1];
        #pragma unroll
        for (int k16 = 0; k16 < 2; k16++) {
            int ks = k16 * 16;
            int kg = c * 32 + ks;
            wmma::fragment<wmma::matrix_b, 16, 16, 16, __nv_bfloat16, wmma::row_major> bh[4], bl[4];
            #pragma unroll
            for (int j = 0; j < 4; j++) {
                int c0 = warp_n * 64 + j * 16;
                wmma::load_matrix_sync(bh[j], bh_s + (size_t)ks * LDM + c0, LDM);
                wmma::load_matrix_sync(bl[j], bl_s + (size_t)ks * LDM + c0, LDM);
            }
            #pragma unroll
            for (int i = 0; i < 2; i++) {
                int r0 = warp_m * 32 + i * 16;
                wmma::fragment<wmma::matrix_a, 16, 16, 16, __nv_bfloat16, wmma::row_major> ah, al;
                wmma::load_matrix_sync(ah, Ah + (size_t)r0 * LDM + kg, LDM);
                wmma::load_matrix_sync(al, Al + (size_t)r0 * LDM + kg, LDM);
                #pragma unroll
                for (int j = 0; j < 4; j++) {
                    wmma::mma_sync(acc[i][j], ah, bh[j], acc[i][j]);
                    wmma::mma_sync(acc[i][j], ah, bl[j], acc[i][j]);
                    wmma::mma_sync(acc[i][j], al, bh[j], acc[i][j]);
                }
            }
        }
        __syncthreads();
    }

    float* fout = (float*)dsm;
    #pragma unroll
    for (int i = 0; i < 2; i++)
        #pragma unroll
        for (int j = 0; j < 4; j++) {
            int r0 = warp_m * 32 + i * 16;
            int c0 = warp_n * 64 + j * 16;
            wmma::store_matrix_sync(fout + (size_t)r0 * LDM + c0, acc[i][j],
                                    LDM, wmma::mem_row_major);
        }
    __syncthreads();

    #pragma unroll 4
    for (int it = 0; it < 16; it++) {
        int idx4 = tid + it * 256;
        int r = idx4 >> 5, c4 = idx4 & 31;
        int row = row0 + r;
        if (row < nrows) {
            const float* s = fout + (size_t)r * LDM + c4 * 4;
            float4 ov = make_float4(s[0] + sbias[c4 * 4 + 0],
                                    s[1] + sbias[c4 * 4 + 1],
                                    s[2] + sbias[c4 * 4 + 2],
                                    s[3] + sbias[c4 * 4 + 3]);
            *(float4*)(g_hw + (size_t)row * HID + c4 * 4) = ov;
        }
    }
}

// ---------------- aggregation (warp per node, gather unrolled x4) + BN stats ----------------
__global__ __launch_bounds__(256) void agg_kernel(int layer) {
    __shared__ float bsum[HID];
    __shared__ float bss[HID];
    int tid = threadIdx.x;
    for (int i = tid; i < HID; i += blockDim.x) { bsum[i] = 0.f; bss[i] = 0.f; }
    __syncthreads();

    int lane = tid & 31;
    int wglobal = (blockIdx.x * blockDim.x + tid) >> 5;
    int nwarps  = (gridDim.x * blockDim.x) >> 5;

    float ls0 = 0.f, ls1 = 0.f, ls2 = 0.f, ls3 = 0.f;
    float lq0 = 0.f, lq1 = 0.f, lq2 = 0.f, lq3 = 0.f;

    for (int n = wglobal; n < NODES; n += nwarps) {
        float dv = g_dinv[n];
        float sn = dv * dv;
        float4 a = ((const float4*)(g_hw + (size_t)n * HID))[lane];
        float4 acc = make_float4(a.x * sn, a.y * sn, a.z * sn, a.w * sn);
        int beg = g_off[n], end = g_off[n + 1];
        int i = beg;
        for (; i + 4 <= end; i += 4) {
            int2 e0 = g_csr[i],     e1 = g_csr[i + 1];
            int2 e2 = g_csr[i + 2], e3 = g_csr[i + 3];
            float w0 = __int_as_float(e0.y), w1 = __int_as_float(e1.y);
            float w2 = __int_as_float(e2.y), w3 = __int_as_float(e3.y);
            float4 v0 = ((const float4*)(g_hw + (size_t)e0.x * HID))[lane];
            float4 v1 = ((const float4*)(g_hw + (size_t)e1.x * HID))[lane];
            float4 v2 = ((const float4*)(g_hw + (size_t)e2.x * HID))[lane];
            float4 v3 = ((const float4*)(g_hw + (size_t)e3.x * HID))[lane];
            acc.x += w0 * v0.x + w1 * v1.x + w2 * v2.x + w3 * v3.x;
            acc.y += w0 * v0.y + w1 * v1.y + w2 * v2.y + w3 * v3.y;
            acc.z += w0 * v0.z + w1 * v1.z + w2 * v2.z + w3 * v3.z;
            acc.w += w0 * v0.w + w1 * v1.w + w2 * v2.w + w3 * v3.w;
        }
        for (; i + 2 <= end; i += 2) {
            int2 e0 = g_csr[i], e1 = g_csr[i + 1];
            float w0 = __int_as_float(e0.y), w1 = __int_as_float(e1.y);
            float4 v0 = ((const float4*)(g_hw + (size_t)e0.x * HID))[lane];
            float4 v1 = ((const float4*)(g_hw + (size_t)e1.x * HID))[lane];
            acc.x += w0 * v0.x + w1 * v1.x;
            acc.y += w0 * v0.y + w1 * v1.y;
            acc.z += w0 * v0.z + w1 * v1.z;
            acc.w += w0 * v0.w + w1 * v1.w;
        }
        if (i < end) {
            int2 e0 = g_csr[i];
            float w = __int_as_float(e0.y);
            float4 v = ((const float4*)(g_hw + (size_t)e0.x * HID))[lane];
            acc.x += w * v.x; acc.y += w * v.y;
            acc.z += w * v.z; acc.w += w * v.w;
        }
        ((float4*)(g_agg + (size_t)n * HID))[lane] = acc;
        ls0 += acc.x; ls1 += acc.y; ls2 += acc.z; ls3 += acc.w;
        lq0 += acc.x * acc.x; lq1 += acc.y * acc.y;
        lq2 += acc.z * acc.z; lq3 += acc.w * acc.w;
    }
    int c = lane * 4;
    atomicAdd(&bsum[c + 0], ls0); atomicAdd(&bsum[c + 1], ls1);
    atomicAdd(&bsum[c + 2], ls2); atomicAdd(&bsum[c + 3], ls3);
    atomicAdd(&bss[c + 0], lq0);  atomicAdd(&bss[c + 1], lq1);
    atomicAdd(&bss[c + 2], lq2);  atomicAdd(&bss[c + 3], lq3);
    __syncthreads();
    for (int i = tid; i < HID; i += blockDim.x) {
        atomicAdd(&g_stats[layer * 256 + i],       bsum[i]);
        atomicAdd(&g_stats[layer * 256 + HID + i], bss[i]);
    }
}

// ---------------- prep split ----------------
__global__ void prep_we_kernel(const float* __restrict__ l1w) {
    int j = threadIdx.x;
    float we = 0.f;
    #pragma unroll 8
    for (int k = 2 * HID; k < 4 * HID; k++)
        we += l1w[(size_t)k * HID + j];
    g_we[j] = we;
}

__global__ void prep_base_kernel(const float* __restrict__ l1w,
                                 const float* __restrict__ l1b,
                                 const int* __restrict__ curr) {
    __shared__ float xs[HID];
    int j = threadIdx.x;
    int c = *curr;
    float m = g_stats[2 * 256 + j] * (1.0f / NODES);
    float v = g_stats[2 * 256 + HID + j] * (1.0f / NODES) - m * m;
    float sc = rsqrtf(v + BN_EPS);
    xs[j] = fmaxf((g_agg[(size_t)c * HID + j] - m) * sc, 0.f);
    __syncthreads();
    float acc = 0.f;
    #pragma unroll 8
    for (int k = 0; k < HID; k++)
        acc += xs[k] * l1w[(size_t)(HID + k) * HID + j];
    g_base[j] = l1b[j] + acc;
}

// ==================== WMMA scoring: BN+ReLU on A (writes h) + bf16x3 GEMM + pooling ====================
// smem: Ah/Al + 4 B chunks + scalars (smean,sscale,sbase,swe,sw2,sarr,pp)
#define SC_SMEM (2 * A_TILE + 4 * B_CHUNK + 3200)   // 107648
__global__ __launch_bounds__(256, 2)
void score_kernel(const float* __restrict__ l2w, const float* __restrict__ l2b,
                  const float* __restrict__ ecn, const float* __restrict__ parts,
                  float* __restrict__ h, float* __restrict__ out)
{
    extern __shared__ char dsm[];
    __nv_bfloat16* Ah = (__nv_bfloat16*)dsm;
    __nv_bfloat16* Al = (__nv_bfloat16*)(dsm + A_TILE);
    __nv_bfloat16* Bh[2] = { (__nv_bfloat16*)(dsm + 2 * A_TILE),
                             (__nv_bfloat16*)(dsm + 2 * A_TILE + B_CHUNK) };
    __nv_bfloat16* Bl[2] = { (__nv_bfloat16*)(dsm + 2 * A_TILE + 2 * B_CHUNK),
                             (__nv_bfloat16*)(dsm + 2 * A_TILE + 3 * B_CHUNK) };
    char* sc = dsm + 2 * A_TILE + 4 * B_CHUNK;
    float* smean  = (float*)(sc);
    float* sscale = (float*)(sc + 512);
    float* sbase  = (float*)(sc + 1024);
    float* swe    = (float*)(sc + 1536);
    float* sw2    = (float*)(sc + 2048);
    float* sarr   = (float*)(sc + 2560);
    float* pp     = (float*)(sc + 3072);   // 32 floats

    int tid = threadIdx.x;
    int wid = tid >> 5;
    int warp_m = wid >> 1;
    int warp_n = wid & 1;
    int row0 = blockIdx.x * 128;
    const char* bhg = (const char*)(g_bhi + (size_t)3 * 16384);
    const char* blg = (const char*)(g_blo + (size_t)3 * 16384);

    if (tid < HID) {
        float m = g_stats[2 * 256 + tid] * (1.0f / NODES);
        float v = g_stats[2 * 256 + HID + tid] * (1.0f / NODES) - m * m;
        smean[tid]  = m;
        sscale[tid] = rsqrtf(v + BN_EPS);
        sbase[tid]  = g_base[tid];
        swe[tid]    = g_we[tid];
        sw2[tid]    = l2w[tid];
    }

    // B chunk 0 in flight
    #pragma unroll
    for (int it = 0; it < 2; it++) {
        int gg = tid + it * 256;
        int k = gg >> 4, seg = gg & 15;
        cpasync16((char*)Bh[0] + k * (LDM * 2) + seg * 16, bhg + k * 256 + seg * 16);
        cpasync16((char*)Bl[0] + k * (LDM * 2) + seg * 16, blg + k * 256 + seg * 16);
    }
    cpasync_commit();
    __syncthreads();

    // stage A: BN+ReLU, write h, split hi/lo
    #pragma unroll 4
    for (int it = 0; it < 16; it++) {
        int idx4 = tid + it * 256;
        int r = idx4 >> 5, k4 = idx4 & 31;
        float4 v = make_float4(0.f, 0.f, 0.f, 0.f);
        int row = row0 + r;
        float f[4] = { 0.f, 0.f, 0.f, 0.f };
        if (row < NODES) {
            v = *(const float4*)(g_agg + (size_t)row * HID + k4 * 4);
            int c0 = k4 * 4;
            f[0] = fmaxf((v.x - smean[c0 + 0]) * sscale[c0 + 0], 0.f);
            f[1] = fmaxf((v.y - smean[c0 + 1]) * sscale[c0 + 1], 0.f);
            f[2] = fmaxf((v.z - smean[c0 + 2]) * sscale[c0 + 2], 0.f);
            f[3] = fmaxf((v.w - smean[c0 + 3]) * sscale[c0 + 3], 0.f);
            *(float4*)(h + (size_t)row * HID + c0) = make_float4(f[0], f[1], f[2], f[3]);
        }
        ushort4 hv, lv;
        unsigned short* hp = (unsigned short*)&hv;
        unsigned short* lp = (unsigned short*)&lv;
        #pragma unroll
        for (int j = 0; j < 4; j++) {
            __nv_bfloat16 hh = __float2bfloat16(f[j]);
            float res = f[j] - __bfloat162float(hh);
            __nv_bfloat16 ll = __float2bfloat16(res);
            hp[j] = *(unsigned short*)&hh;
            lp[j] = *(unsigned short*)&ll;
        }
        unsigned off = (unsigned)r * LDM + k4 * 4;
        *(ushort4*)(Ah + off) = hv;
        *(ushort4*)(Al + off) = lv;
    }

    wmma::fragment<wmma::accumulator, 16, 16, 16, float> acc[2][4];
    #pragma unroll
    for (int i = 0; i < 2; i++)
        #pragma unroll
        for (int j = 0; j < 4; j++)
            wmma::fill_fragment(acc[i][j], 0.0f);

    #pragma unroll 1
    for (int c = 0; c < 4; c++) {
        cpasync_wait_all();
        __syncthreads();
        int nb = (c + 1) & 1;
        if (c + 1 < 4) {
            #pragma unroll
            for (int it = 0; it < 2; it++) {
                int gg = tid + it * 256;
                int k = gg >> 4, seg = gg & 15;
                cpasync16((char*)Bh[nb] + k * (LDM * 2) + seg * 16,
                          bhg + ((c + 1) * 32 + k) * 256 + seg * 16);
                cpasync16((char*)Bl[nb] + k * (LDM * 2) + seg * 16,
                          blg + ((c + 1) * 32 + k) * 256 + seg * 16);
            }
            cpasync_commit();
        }
        const __nv_bfloat16* bh_s = Bh[c & 1];
        const __nv_bfloat16* bl_s = Bl[c & 1];
        #pragma unroll
        for (int k16 = 0; k16 < 2; k16++) {
            int ks = k16 * 16;
            int kg = c * 32 + ks;
            wmma::fragment<wmma::matrix_b, 16, 16, 16, __nv_bfloat16, wmma::row_major> bh[4], bl[4];
            #pragma unroll
            for (int j = 0; j < 4; j++) {
                int c0 = warp_n * 64 + j * 16;
                wmma::load_matrix_sync(bh[j], bh_s + (size_t)ks * LDM + c0, LDM);
                wmma::load_matrix_sync(bl[j], bl_s + (size_t)ks * LDM + c0, LDM);
            }
            #pragma unroll
            for (int i = 0; i < 2; i++) {
                int r0 = warp_m * 32 + i * 16;
                wmma::fragment<wmma::matrix_a, 16, 16, 16, __nv_bfloat16, wmma::row_major> ah, al;
                wmma::load_matrix_sync(ah, Ah + (size_t)r0 * LDM + kg, LDM);
                wmma::load_matrix_sync(al, Al + (size_t)r0 * LDM + kg, LDM);
                #pragma unroll
                for (int j = 0; j < 4; j++) {
                    wmma::mma_sync(acc[i][j], ah, bh[j], acc[i][j]);
                    wmma::mma_sync(acc[i][j], ah, bl[j], acc[i][j]);
                    wmma::mma_sync(acc[i][j], al, bh[j], acc[i][j]);
                }
            }
        }
        __syncthreads();
    }

    float* fout = (float*)dsm;
    #pragma unroll
    for (int i = 0; i < 2; i++)
        #pragma unroll
        for (int j = 0; j < 4; j++) {
            int r0 = warp_m * 32 + i * 16;
            int c0 = warp_n * 64 + j * 16;
            wmma::store_matrix_sync(fout + (size_t)r0 * LDM + c0, acc[i][j],
                                    LDM, wmma::mem_row_major);
        }
    __syncthreads();

    // epilogue: one row per thread (tid < 128)
    float b2 = l2b[0];
    if (tid < 128) {
        int row = row0 + tid;
        float e = (row < NODES) ? ecn[row] : 0.f;
        const float* fr = fout + (size_t)tid * LDM;
        float s = 0.f;
        #pragma unroll 8
        for (int j = 0; j < HID; j++) {
            float t = fr[j] + sbase[j] + e * swe[j];
            s += fmaxf(t, 0.f) * sw2[j];
        }
        sarr[tid] = (row < NODES) ? (s + b2) : 0.f;
    }
    if (tid < NPART) pp[tid] = 0.f;
    __syncthreads();

    int p = tid & 31, g = tid >> 5;   // 8 groups x 16 rows
    float psum = 0.f;
    for (int r = g * 16; r < g * 16 + 16; r++) {
        int row = row0 + r;
        if (row < NODES) psum += sarr[r] * parts[(size_t)row * NPART + p];
    }
    atomicAdd(&pp[p], psum);
    __syncthreads();
    if (tid < NPART) atomicAdd(&out[tid], pp[tid]);
}

// ---------------- launcher ----------------
extern "C" void kernel_launch(void* const* d_in, const int* in_sizes, int n_in,
                              void* d_out, int out_size) {
    const float* x      = (const float*)d_in[0];
    const int*   ei     = (const int*)d_in[1];
    const float* ew     = (const float*)d_in[2];
    const float* parts  = (const float*)d_in[3];
    const float* ecn    = (const float*)d_in[5];
    const float* conv_w = (const float*)d_in[6];
    const float* conv_b = (const float*)d_in[7];
    const float* l1w    = (const float*)d_in[8];
    const float* l1b    = (const float*)d_in[9];
    const float* l2w    = (const float*)d_in[10];
    const float* l2b    = (const float*)d_in[11];
    const int*   curr   = (const int*)d_in[12];

    float* out = (float*)d_out;          // [0:32) partition scores
    float* h   = out + NPART;            // [32 : 32+N*H) final h

    cudaFuncSetAttribute(tgemm_kernel,
                         cudaFuncAttributeMaxDynamicSharedMemorySize, TG_SMEM);
    cudaFuncSetAttribute(score_kernel,
                         cudaFuncAttributeMaxDynamicSharedMemorySize, SC_SMEM);

    int agg_blocks = 1184;
    {
        int dev = 0, sms = 0, maxb = 0;
        if (cudaGetDevice(&dev) == cudaSuccess &&
            cudaDeviceGetAttribute(&sms, cudaDevAttrMultiProcessorCount, dev) == cudaSuccess &&
            cudaOccupancyMaxActiveBlocksPerMultiprocessor(&maxb, agg_kernel, 256, 0) == cudaSuccess &&
            sms > 0 && maxb > 0) {
            agg_blocks = sms * maxb;
        }
    }

    cudaStream_t sG;
    cudaStreamCreateWithFlags(&sG, cudaStreamNonBlocking);
    cudaEvent_t evFork, evJoin;
    cudaEventCreateWithFlags(&evFork, cudaEventDisableTiming);
    cudaEventCreateWithFlags(&evJoin, cudaEventDisableTiming);

    const int gemm_blocks = (NODES + 127) / 128;   // 391

    cudaEventRecord(evFork, 0);
    cudaStreamWaitEvent(sG, evFork, 0);

    // default stream: CSR build chain
    zero_init_kernel<<<(NODES + 255) / 256, 256>>>(out);          // 1
    deg_count_kernel<<<(NE + 255) / 256, 256>>>(ei, ew);          // 2
    // sG: weight split + gemm0 + we-sums
    bsplit_kernel<<<256, 256, 0, sG>>>(conv_w, l1w);              // 3
    tgemm_kernel<<<gemm_blocks, 256, TG_SMEM, sG>>>(x, conv_b, 0, -1, NODES); // 4 <- ncu
    prep_we_kernel<<<1, 128, 0, sG>>>(l1w);                       // 5
    scan_kernel2<<<NSB, SBLK>>>();                                // 6
    csr_fill_kernel<<<(NE + 255) / 256, 256>>>(ei, ew);           // 7

    cudaEventRecord(evJoin, sG);
    cudaStreamWaitEvent(0, evJoin, 0);

    agg_kernel<<<agg_blocks, 256>>>(0);
    tgemm_kernel<<<gemm_blocks, 256, TG_SMEM>>>(x, conv_b + HID, 1, 0, NODES);
    agg_kernel<<<agg_blocks, 256>>>(1);
    tgemm_kernel<<<gemm_blocks, 256, TG_SMEM>>>(x, conv_b + 2 * HID, 2, 1, NODES);
    agg_kernel<<<agg_blocks, 256>>>(2);

    prep_base_kernel<<<1, 128>>>(l1w, l1b, curr);
    score_kernel<<<gemm_blocks, 256, SC_SMEM>>>(l2w, l2b, ecn, parts, h, out);
}

// round 17
// speedup vs baseline: 1.1621x; 1.0060x over previous
#include <cuda_runtime.h>
#include <cuda_bf16.h>
#include <mma.h>

#define NODES 50000
#define NE    800000
#define HID   128
#define NPART 32
#define BN_EPS 1e-5f
#define SBLK  512
#define NSB   ((NODES + SBLK - 1) / SBLK)   // 98

typedef unsigned long long ull;
using namespace nvcuda;

// ---------------- scratch (device globals; no runtime alloc) ----------------
__device__ float g_deg[NODES];
__device__ int   g_cnt[NODES];
__device__ int   g_off[NODES + 1];
__device__ int   g_cur[NODES];
__device__ float g_dinv[NODES];
__device__ int   g_aggv[NSB];
__device__ volatile int g_flag[NSB];
__device__ int   g_done;
__device__ int2  g_csr[NE];                 // {src, float_as_int(norm)}
__device__ float g_hw[NODES * HID];
__device__ float g_agg[NODES * HID];
__device__ float g_stats[3 * 2 * HID];      // per layer: [0:128) sum, [128:256) sumsq
__device__ float g_base[HID];
__device__ float g_we[HID];
// pre-split weights, row-major [K][N] bf16: slots 0..2 = conv layers, 3 = l1w rows 0..127
__device__ __nv_bfloat16 g_bhi[4 * 16384];
__device__ __nv_bfloat16 g_blo[4 * 16384];

// ---------------- cp.async helpers ----------------
__device__ __forceinline__ void cpasync16(void* smem_ptr, const void* gptr) {
    unsigned s = (unsigned)__cvta_generic_to_shared(smem_ptr);
    asm volatile("cp.async.cg.shared.global [%0], [%1], 16;"
                 :: "r"(s), "l"(gptr) : "memory");
}
__device__ __forceinline__ void cpasync_commit() {
    asm volatile("cp.async.commit_group;" ::: "memory");
}
__device__ __forceinline__ void cpasync_wait_all() {
    asm volatile("cp.async.wait_group 0;" ::: "memory");
}

// ---------------- init ----------------
__global__ void zero_init_kernel(float* out) {
    int i = blockIdx.x * blockDim.x + threadIdx.x;
    if (i < NODES) { g_deg[i] = 0.f; g_cnt[i] = 0; g_cur[i] = 0; }
    if (i < NPART) out[i] = 0.f;
    if (i < 3 * 2 * HID) g_stats[i] = 0.f;
    if (i < NSB) g_flag[i] = 0;
    if (i == 0) g_done = 0;
}

// ---------------- degree + count ----------------
__global__ void deg_count_kernel(const int* __restrict__ ei,
                                 const float* __restrict__ ew) {
    int e = blockIdx.x * blockDim.x + threadIdx.x;
    if (e >= NE) return;
    int dst = ei[NE + e];
    atomicAdd(&g_deg[dst], ew[e]);
    atomicAdd(&g_cnt[dst], 1);
}

// ---------------- single-kernel scan (decoupled lookback) + dinv fused ----------------
__global__ __launch_bounds__(SBLK) void scan_kernel2() {
    __shared__ int ws[SBLK / 32];
    __shared__ int s_prefix;
    int t = threadIdx.x, lane = t & 31, w = t >> 5;
    int bid = blockIdx.x;
    int i = bid * SBLK + t;
    int v = (i < NODES) ? g_cnt[i] : 0;
    if (i < NODES) g_dinv[i] = rsqrtf(g_deg[i] + 1.0f);

    int inc = v;
    #pragma unroll
    for (int o = 1; o < 32; o <<= 1) {
        int u = __shfl_up_sync(0xffffffffu, inc, o);
        if (lane >= o) inc += u;
    }
    if (lane == 31) ws[w] = inc;
    __syncthreads();

    if (w == 0 && lane < SBLK / 32) {
        int x = ws[lane];
        int xi = x;
        #pragma unroll
        for (int o = 1; o < 16; o <<= 1) {
            int u = __shfl_up_sync(0x0000ffffu, xi, o);
            if (lane >= o) xi += u;
        }
        ws[lane] = xi - x;
        if (lane == SBLK / 32 - 1) {
            g_aggv[bid] = xi;
            __threadfence();
            g_flag[bid] = 1;
        }
    }
    __syncthreads();

    if (w == 0) {
        int sum = 0;
        for (int base = 0; base < bid; base += 32) {
            int p = base + lane;
            int a = 0;
            if (p < bid) {
                while (g_flag[p] == 0) { }
                __threadfence();
                a = g_aggv[p];
            }
            #pragma unroll
            for (int o = 16; o; o >>= 1) a += __shfl_down_sync(0xffffffffu, a, o);
            if (lane == 0) sum += a;
        }
        if (lane == 0) s_prefix = sum;
    }
    __syncthreads();

    int pref = s_prefix;
    if (i < NODES) g_off[i] = pref + ws[w] + inc - v;
    if (bid == NSB - 1 && t == SBLK - 1) g_off[NODES] = pref + ws[w] + inc;
}

// ---------------- CSR fill (interleaved) ----------------
__global__ void csr_fill_kernel(const int* __restrict__ ei,
                                const float* __restrict__ ew) {
    int e = blockIdx.x * blockDim.x + threadIdx.x;
    if (e >= NE) return;
    int src = ei[e];
    int dst = ei[NE + e];
    int pos = g_off[dst] + atomicAdd(&g_cur[dst], 1);
    float norm = g_dinv[src] * ew[e] * g_dinv[dst];
    g_csr[pos] = make_int2(src, __float_as_int(norm));
}

// ---------------- W pre-split: conv layers 0..2 + l1w rows 0..127 into slot 3 ----------------
__global__ void bsplit_kernel(const float* __restrict__ conv_w,
                              const float* __restrict__ l1w) {
    int idx = blockIdx.x * blockDim.x + threadIdx.x;
    if (idx >= 4 * 16384) return;
    int L = idx >> 14;
    int rem = idx & 16383;
    float wv = (L < 3) ? conv_w[(size_t)L * 16384 + rem] : l1w[rem];
    __nv_bfloat16 h = __float2bfloat16(wv);
    float res = wv - __bfloat162float(h);
    g_bhi[idx] = h;
    g_blo[idx] = __float2bfloat16(res);
}

// ==================== WMMA bf16x3 GEMM: g_hw = act(A) @ W + bias ====================
#define LDM 136
#define A_TILE (128 * LDM * 2)          // 34816
#define B_CHUNK (32 * LDM * 2)          // 8704
#define TG_SMEM (2 * A_TILE + 4 * B_CHUNK + 1536)   // 105984
__global__ __launch_bounds__(256, 2)
void tgemm_kernel(const float* __restrict__ A, const float* __restrict__ bias,
                  int wsel, int bnlayer, int nrows)
{
    extern __shared__ char dsm[];
    __nv_bfloat16* Ah = (__nv_bfloat16*)dsm;
    __nv_bfloat16* Al = (__nv_bfloat16*)(dsm + A_TILE);
    __nv_bfloat16* Bh[2] = { (__nv_bfloat16*)(dsm + 2 * A_TILE),
                             (__nv_bfloat16*)(dsm + 2 * A_TILE + B_CHUNK) };
    __nv_bfloat16* Bl[2] = { (__nv_bfloat16*)(dsm + 2 * A_TILE + 2 * B_CHUNK),
                             (__nv_bfloat16*)(dsm + 2 * A_TILE + 3 * B_CHUNK) };
    float* smean  = (float*)(dsm + 2 * A_TILE + 4 * B_CHUNK);
    float* sscale = (float*)(dsm + 2 * A_TILE + 4 * B_CHUNK + 512);
    float* sbias  = (float*)(dsm + 2 * A_TILE + 4 * B_CHUNK + 1024);

    int tid = threadIdx.x;
    int wid = tid >> 5;
    int warp_m = wid >> 1;
    int warp_n = wid & 1;
    int row0 = blockIdx.x * 128;
    const bool bn = (bnlayer >= 0);
    const float* __restrict__ src = bn ? (const float*)g_agg : A;
    const char* bhg = (const char*)(g_bhi + (size_t)wsel * 16384);
    const char* blg = (const char*)(g_blo + (size_t)wsel * 16384);

    if (tid < HID) {
        if (bn) {
            float m = g_stats[bnlayer * 256 + tid] * (1.0f / NODES);
            float v = g_stats[bnlayer * 256 + HID + tid] * (1.0f / NODES) - m * m;
            smean[tid]  = m;
            sscale[tid] = rsqrtf(v + BN_EPS);
        }
        sbias[tid] = bias[tid];
    }

    #pragma unroll
    for (int it = 0; it < 2; it++) {
        int gg = tid + it * 256;
        int k = gg >> 4, seg = gg & 15;
        cpasync16((char*)Bh[0] + k * (LDM * 2) + seg * 16, bhg + k * 256 + seg * 16);
        cpasync16((char*)Bl[0] + k * (LDM * 2) + seg * 16, blg + k * 256 + seg * 16);
    }
    cpasync_commit();
    __syncthreads();

    #pragma unroll 4
    for (int it = 0; it < 16; it++) {
        int idx4 = tid + it * 256;
        int r = idx4 >> 5, k4 = idx4 & 31;
        float4 v = make_float4(0.f, 0.f, 0.f, 0.f);
        int row = row0 + r;
        if (row < nrows)
            v = *(const float4*)(src + (size_t)row * HID + k4 * 4);
        float f[4] = { v.x, v.y, v.z, v.w };
        if (bn) {
            int c0 = k4 * 4;
            #pragma unroll
            for (int j = 0; j < 4; j++)
                f[j] = fmaxf((f[j] - smean[c0 + j]) * sscale[c0 + j], 0.f);
        }
        ushort4 hv, lv;
        unsigned short* hp = (unsigned short*)&hv;
        unsigned short* lp = (unsigned short*)&lv;
        #pragma unroll
        for (int j = 0; j < 4; j++) {
            __nv_bfloat16 h = __float2bfloat16(f[j]);
            float res = f[j] - __bfloat162float(h);
            __nv_bfloat16 l = __float2bfloat16(res);
            hp[j] = *(unsigned short*)&h;
            lp[j] = *(unsigned short*)&l;
        }
        unsigned off = (unsigned)r * LDM + k4 * 4;
        *(ushort4*)(Ah + off) = hv;
        *(ushort4*)(Al + off) = lv;
    }

    wmma::fragment<wmma::accumulator, 16, 16, 16, float> acc[2][4];
    #pragma unroll
    for (int i = 0; i < 2; i++)
        #pragma unroll
        for (int j = 0; j < 4; j++)
            wmma::fill_fragment(acc[i][j], 0.0f);

    #pragma unroll 1
    for (int c = 0; c < 4; c++) {
        cpasync_wait_all();
        __syncthreads();
        int nb = (c + 1) & 1;
        if (c + 1 < 4) {
            #pragma unroll
            for (int it = 0; it < 2; it++) {
                int gg = tid + it * 256;
                int k = gg >> 4, seg = gg & 15;
                cpasync16((char*)Bh[nb] + k * (LDM * 2) + seg * 16,
                          bhg + ((c + 1) * 32 + k) * 256 + seg * 16);
                cpasync16((char*)Bl[nb] + k * (LDM * 2) + seg * 16,
                          blg + ((c + 1) * 32 + k) * 256 + seg * 16);
            }
            cpasync_commit();
        }
        const __nv_bfloat16* bh_s = Bh[c & 1];
        const __nv_bfloat16* bl_s = Bl[c & 1];
        #pragma unroll
        for (int k16 = 0; k16 < 2; k16++) {
            int ks = k16 * 16;
            int kg = c * 32 + ks;
            wmma::fragment<wmma::matrix_b, 16, 16, 16, __nv_bfloat16, wmma::row_major> bh[4], bl[4];
            #pragma unroll
            for (int j = 0; j < 4; j++) {
                int c0 = warp_n * 64 + j * 16;
                wmma::load_matrix_sync(bh[j], bh_s + (size_t)ks * LDM + c0, LDM);
                wmma::load_matrix_sync(bl[j], bl_s + (size_t)ks * LDM + c0, LDM);
            }
            #pragma unroll
            for (int i = 0; i < 2; i++) {
                int r0 = warp_m * 32 + i * 16;
                wmma::fragment<wmma::matrix_a, 16, 16, 16, __nv_bfloat16, wmma::row_major> ah, al;
                wmma::load_matrix_sync(ah, Ah + (size_t)r0 * LDM + kg, LDM);
                wmma::load_matrix_sync(al, Al + (size_t)r0 * LDM + kg, LDM);
                #pragma unroll
                for (int j = 0; j < 4; j++) {
                    wmma::mma_sync(acc[i][j], ah, bh[j], acc[i][j]);
                    wmma::mma_sync(acc[i][j], ah, bl[j], acc[i][j]);
                    wmma::mma_sync(acc[i][j], al, bh[j], acc[i][j]);
                }
            }
        }
        __syncthreads();
    }

    float* fout = (float*)dsm;
    #pragma unroll
    for (int i = 0; i < 2; i++)
        #pragma unroll
        for (int j = 0; j < 4; j++) {
            int r0 = warp_m * 32 + i * 16;
            int c0 = warp_n * 64 + j * 16;
            wmma::store_matrix_sync(fout + (size_t)r0 * LDM + c0, acc[i][j],
                                    LDM, wmma::mem_row_major);
        }
    __syncthreads();

    #pragma unroll 4
    for (int it = 0; it < 16; it++) {
        int idx4 = tid + it * 256;
        int r = idx4 >> 5, c4 = idx4 & 31;
        int row = row0 + r;
        if (row < nrows) {
            const float* s = fout + (size_t)r * LDM + c4 * 4;
            float4 ov = make_float4(s[0] + sbias[c4 * 4 + 0],
                                    s[1] + sbias[c4 * 4 + 1],
                                    s[2] + sbias[c4 * 4 + 2],
                                    s[3] + sbias[c4 * 4 + 3]);
            *(float4*)(g_hw + (size_t)row * HID + c4 * 4) = ov;
        }
    }
}

// ---------------- aggregation + BN stats; layer 2 folds prep_base (last block) ----------------
__global__ __launch_bounds__(256) void agg_kernel(int layer,
                                                  const float* __restrict__ l1w,
                                                  const float* __restrict__ l1b,
                                                  const int* __restrict__ curr) {
    __shared__ float bsum[HID];
    __shared__ float bss[HID];
    __shared__ int s_last;
    int tid = threadIdx.x;
    for (int i = tid; i < HID; i += blockDim.x) { bsum[i] = 0.f; bss[i] = 0.f; }
    __syncthreads();

    int lane = tid & 31;
    int wglobal = (blockIdx.x * blockDim.x + tid) >> 5;
    int nwarps  = (gridDim.x * blockDim.x) >> 5;

    float ls0 = 0.f, ls1 = 0.f, ls2 = 0.f, ls3 = 0.f;
    float lq0 = 0.f, lq1 = 0.f, lq2 = 0.f, lq3 = 0.f;

    for (int n = wglobal; n < NODES; n += nwarps) {
        float dv = g_dinv[n];
        float sn = dv * dv;
        float4 a = ((const float4*)(g_hw + (size_t)n * HID))[lane];
        float4 acc = make_float4(a.x * sn, a.y * sn, a.z * sn, a.w * sn);
        int beg = g_off[n], end = g_off[n + 1];
        int i = beg;
        for (; i + 4 <= end; i += 4) {
            int2 e0 = g_csr[i],     e1 = g_csr[i + 1];
            int2 e2 = g_csr[i + 2], e3 = g_csr[i + 3];
            float w0 = __int_as_float(e0.y), w1 = __int_as_float(e1.y);
            float w2 = __int_as_float(e2.y), w3 = __int_as_float(e3.y);
            float4 v0 = ((const float4*)(g_hw + (size_t)e0.x * HID))[lane];
            float4 v1 = ((const float4*)(g_hw + (size_t)e1.x * HID))[lane];
            float4 v2 = ((const float4*)(g_hw + (size_t)e2.x * HID))[lane];
            float4 v3 = ((const float4*)(g_hw + (size_t)e3.x * HID))[lane];
            acc.x += w0 * v0.x + w1 * v1.x + w2 * v2.x + w3 * v3.x;
            acc.y += w0 * v0.y + w1 * v1.y + w2 * v2.y + w3 * v3.y;
            acc.z += w0 * v0.z + w1 * v1.z + w2 * v2.z + w3 * v3.z;
            acc.w += w0 * v0.w + w1 * v1.w + w2 * v2.w + w3 * v3.w;
        }
        for (; i + 2 <= end; i += 2) {
            int2 e0 = g_csr[i], e1 = g_csr[i + 1];
            float w0 = __int_as_float(e0.y), w1 = __int_as_float(e1.y);
            float4 v0 = ((const float4*)(g_hw + (size_t)e0.x * HID))[lane];
            float4 v1 = ((const float4*)(g_hw + (size_t)e1.x * HID))[lane];
            acc.x += w0 * v0.x + w1 * v1.x;
            acc.y += w0 * v0.y + w1 * v1.y;
            acc.z += w0 * v0.z + w1 * v1.z;
            acc.w += w0 * v0.w + w1 * v1.w;
        }
        if (i < end) {
            int2 e0 = g_csr[i];
            float w = __int_as_float(e0.y);
            float4 v = ((const float4*)(g_hw + (size_t)e0.x * HID))[lane];
            acc.x += w * v.x; acc.y += w * v.y;
            acc.z += w * v.z; acc.w += w * v.w;
        }
        ((float4*)(g_agg + (size_t)n * HID))[lane] = acc;
        ls0 += acc.x; ls1 += acc.y; ls2 += acc.z; ls3 += acc.w;
        lq0 += acc.x * acc.x; lq1 += acc.y * acc.y;
        lq2 += acc.z * acc.z; lq3 += acc.w * acc.w;
    }
    int c = lane * 4;
    atomicAdd(&bsum[c + 0], ls0); atomicAdd(&bsum[c + 1], ls1);
    atomicAdd(&bsum[c + 2], ls2); atomicAdd(&bsum[c + 3], ls3);
    atomicAdd(&bss[c + 0], lq0);  atomicAdd(&bss[c + 1], lq1);
    atomicAdd(&bss[c + 2], lq2);  atomicAdd(&bss[c + 3], lq3);
    __syncthreads();
    for (int i = tid; i < HID; i += blockDim.x) {
        atomicAdd(&g_stats[layer * 256 + i],       bsum[i]);
        atomicAdd(&g_stats[layer * 256 + HID + i], bss[i]);
    }

    // ---- layer 2: last block computes g_base inline (replaces prep_base) ----
    if (layer == 2) {
        __threadfence();
        if (tid == 0) s_last = (atomicAdd(&g_done, 1) == (int)gridDim.x - 1);
        __syncthreads();
        if (s_last) {
            __shared__ float xs[HID];
            if (tid < HID) {
                int cn = *curr;
                float m = g_stats[2 * 256 + tid] * (1.0f / NODES);
                float v = g_stats[2 * 256 + HID + tid] * (1.0f / NODES) - m * m;
                float sc = rsqrtf(v + BN_EPS);
                xs[tid] = fmaxf((g_agg[(size_t)cn * HID + tid] - m) * sc, 0.f);
            }
            __syncthreads();
            if (tid < HID) {
                float acc = l1b[tid];
                #pragma unroll 8
                for (int k = 0; k < HID; k++)
                    acc += xs[k] * l1w[(size_t)(HID + k) * HID + tid];
                g_base[tid] = acc;
            }
        }
    }
}

// ---------------- prep_we: no dependencies -> overlapped early on sG ----------------
__global__ void prep_we_kernel(const float* __restrict__ l1w) {
    int j = threadIdx.x;
    float we = 0.f;
    #pragma unroll 8
    for (int k = 2 * HID; k < 4 * HID; k++)
        we += l1w[(size_t)k * HID + j];
    g_we[j] = we;
}

// ==================== WMMA scoring: BN+ReLU on A (writes h) + bf16x3 GEMM + pooling ====================
#define SC_SMEM (2 * A_TILE + 4 * B_CHUNK + 3200)   // 107648
__global__ __launch_bounds__(256, 2)
void score_kernel(const float* __restrict__ l2w, const float* __restrict__ l2b,
                  const float* __restrict__ ecn, const float* __restrict__ parts,
                  float* __restrict__ h, float* __restrict__ out)
{
    extern __shared__ char dsm[];
    __nv_bfloat16* Ah = (__nv_bfloat16*)dsm;
    __nv_bfloat16* Al = (__nv_bfloat16*)(dsm + A_TILE);
    __nv_bfloat16* Bh[2] = { (__nv_bfloat16*)(dsm + 2 * A_TILE),
                             (__nv_bfloat16*)(dsm + 2 * A_TILE + B_CHUNK) };
    __nv_bfloat16* Bl[2] = { (__nv_bfloat16*)(dsm + 2 * A_TILE + 2 * B_CHUNK),
                             (__nv_bfloat16*)(dsm + 2 * A_TILE + 3 * B_CHUNK) };
    char* sc = dsm + 2 * A_TILE + 4 * B_CHUNK;
    float* smean  = (float*)(sc);
    float* sscale = (float*)(sc + 512);
    float* sbase  = (float*)(sc + 1024);
    float* swe    = (float*)(sc + 1536);
    float* sw2    = (float*)(sc + 2048);
    float* sarr   = (float*)(sc + 2560);
    float* pp     = (float*)(sc + 3072);

    int tid = threadIdx.x;
    int wid = tid >> 5;
    int warp_m = wid >> 1;
    int warp_n = wid & 1;
    int row0 = blockIdx.x * 128;
    const char* bhg = (const char*)(g_bhi + (size_t)3 * 16384);
    const char* blg = (const char*)(g_blo + (size_t)3 * 16384);

    if (tid < HID) {
        float m = g_stats[2 * 256 + tid] * (1.0f / NODES);
        float v = g_stats[2 * 256 + HID + tid] * (1.0f / NODES) - m * m;
        smean[tid]  = m;
        sscale[tid] = rsqrtf(v + BN_EPS);
        sbase[tid]  = g_base[tid];
        swe[tid]    = g_we[tid];
        sw2[tid]    = l2w[tid];
    }

    #pragma unroll
    for (int it = 0; it < 2; it++) {
        int gg = tid + it * 256;
        int k = gg >> 4, seg = gg & 15;
        cpasync16((char*)Bh[0] + k * (LDM * 2) + seg * 16, bhg + k * 256 + seg * 16);
        cpasync16((char*)Bl[0] + k * (LDM * 2) + seg * 16, blg + k * 256 + seg * 16);
    }
    cpasync_commit();
    __syncthreads();

    #pragma unroll 4
    for (int it = 0; it < 16; it++) {
        int idx4 = tid + it * 256;
        int r = idx4 >> 5, k4 = idx4 & 31;
        float4 v = make_float4(0.f, 0.f, 0.f, 0.f);
        int row = row0 + r;
        float f[4] = { 0.f, 0.f, 0.f, 0.f };
        if (row < NODES) {
            v = *(const float4*)(g_agg + (size_t)row * HID + k4 * 4);
            int c0 = k4 * 4;
            f[0] = fmaxf((v.x - smean[c0 + 0]) * sscale[c0 + 0], 0.f);
            f[1] = fmaxf((v.y - smean[c0 + 1]) * sscale[c0 + 1], 0.f);
            f[2] = fmaxf((v.z - smean[c0 + 2]) * sscale[c0 + 2], 0.f);
            f[3] = fmaxf((v.w - smean[c0 + 3]) * sscale[c0 + 3], 0.f);
            *(float4*)(h + (size_t)row * HID + c0) = make_float4(f[0], f[1], f[2], f[3]);
        }
        ushort4 hv, lv;
        unsigned short* hp = (unsigned short*)&hv;
        unsigned short* lp = (unsigned short*)&lv;
        #pragma unroll
        for (int j = 0; j < 4; j++) {
            __nv_bfloat16 hh = __float2bfloat16(f[j]);
            float res = f[j] - __bfloat162float(hh);
            __nv_bfloat16 ll = __float2bfloat16(res);
            hp[j] = *(unsigned short*)&hh;
            lp[j] = *(unsigned short*)&ll;
        }
        unsigned off = (unsigned)r * LDM + k4 * 4;
        *(ushort4*)(Ah + off) = hv;
        *(ushort4*)(Al + off) = lv;
    }

    wmma::fragment<wmma::accumulator, 16, 16, 16, float> acc[2][4];
    #pragma unroll
    for (int i = 0; i < 2; i++)
        #pragma unroll
        for (int j = 0; j < 4; j++)
            wmma::fill_fragment(acc[i][j], 0.0f);

    #pragma unroll 1
    for (int c = 0; c < 4; c++) {
        cpasync_wait_all();
        __syncthreads();
        int nb = (c + 1) & 1;
        if (c + 1 < 4) {
            #pragma unroll
            for (int it = 0; it < 2; it++) {
                int gg = tid + it * 256;
                int k = gg >> 4, seg = gg & 15;
                cpasync16((char*)Bh[nb] + k * (LDM * 2) + seg * 16,
                          bhg + ((c + 1) * 32 + k) * 256 + seg * 16);
                cpasync16((char*)Bl[nb] + k * (LDM * 2) + seg * 16,
                          blg + ((c + 1) * 32 + k) * 256 + seg * 16);
            }
            cpasync_commit();
        }
        const __nv_bfloat16* bh_s = Bh[c & 1];
        const __nv_bfloat16* bl_s = Bl[c & 1];
        #pragma unroll
        for (int k16 = 0; k16 < 2; k16++) {
            int ks = k16 * 16;
            int kg = c * 32 + ks;
            wmma::fragment<wmma::matrix_b, 16, 16, 16, __nv_bfloat16, wmma::row_major> bh[4], bl[4];
            #pragma unroll
            for (int j = 0; j < 4; j++) {
                int c0 = warp_n * 64 + j * 16;
                wmma::load_matrix_sync(bh[j], bh_s + (size_t)ks * LDM + c0, LDM);
                wmma::load_matrix_sync(bl[j], bl_s + (size_t)ks * LDM + c0, LDM);
            }
            #pragma unroll
            for (int i = 0; i < 2; i++) {
                int r0 = warp_m * 32 + i * 16;
                wmma::fragment<wmma::matrix_a, 16, 16, 16, __nv_bfloat16, wmma::row_major> ah, al;
                wmma::load_matrix_sync(ah, Ah + (size_t)r0 * LDM + kg, LDM);
                wmma::load_matrix_sync(al, Al + (size_t)r0 * LDM + kg, LDM);
                #pragma unroll
                for (int j = 0; j < 4; j++) {
                    wmma::mma_sync(acc[i][j], ah, bh[j], acc[i][j]);
                    wmma::mma_sync(acc[i][j], ah, bl[j], acc[i][j]);
                    wmma::mma_sync(acc[i][j], al, bh[j], acc[i][j]);
                }
            }
        }
        __syncthreads();
    }

    float* fout = (float*)dsm;
    #pragma unroll
    for (int i = 0; i < 2; i++)
        #pragma unroll
        for (int j = 0; j < 4; j++) {
            int r0 = warp_m * 32 + i * 16;
            int c0 = warp_n * 64 + j * 16;
            wmma::store_matrix_sync(fout + (size_t)r0 * LDM + c0, acc[i][j],
                                    LDM, wmma::mem_row_major);
        }
    __syncthreads();

    float b2 = l2b[0];
    if (tid < 128) {
        int row = row0 + tid;
        float e = (row < NODES) ? ecn[row] : 0.f;
        const float* fr = fout + (size_t)tid * LDM;
        float s = 0.f;
        #pragma unroll 8
        for (int j = 0; j < HID; j++) {
            float t = fr[j] + sbase[j] + e * swe[j];
            s += fmaxf(t, 0.f) * sw2[j];
        }
        sarr[tid] = (row < NODES) ? (s + b2) : 0.f;
    }
    if (tid < NPART) pp[tid] = 0.f;
    __syncthreads();

    int p = tid & 31, g = tid >> 5;
    float psum = 0.f;
    for (int r = g * 16; r < g * 16 + 16; r++) {
        int row = row0 + r;
        if (row < NODES) psum += sarr[r] * parts[(size_t)row * NPART + p];
    }
    atomicAdd(&pp[p], psum);
    __syncthreads();
    if (tid < NPART) atomicAdd(&out[tid], pp[tid]);
}

// ---------------- launcher ----------------
extern "C" void kernel_launch(void* const* d_in, const int* in_sizes, int n_in,
                              void* d_out, int out_size) {
    const float* x      = (const float*)d_in[0];
    const int*   ei     = (const int*)d_in[1];
    const float* ew     = (const float*)d_in[2];
    const float* parts  = (const float*)d_in[3];
    const float* ecn    = (const float*)d_in[5];
    const float* conv_w = (const float*)d_in[6];
    const float* conv_b = (const float*)d_in[7];
    const float* l1w    = (const float*)d_in[8];
    const float* l1b    = (const float*)d_in[9];
    const float* l2w    = (const float*)d_in[10];
    const float* l2b    = (const float*)d_in[11];
    const int*   curr   = (const int*)d_in[12];

    float* out = (float*)d_out;          // [0:32) partition scores
    float* h   = out + NPART;            // [32 : 32+N*H) final h

    cudaFuncSetAttribute(tgemm_kernel,
                         cudaFuncAttributeMaxDynamicSharedMemorySize, TG_SMEM);
    cudaFuncSetAttribute(score_kernel,
                         cudaFuncAttributeMaxDynamicSharedMemorySize, SC_SMEM);

    int agg_blocks = 1184;
    {
        int dev = 0, sms = 0, maxb = 0;
        if (cudaGetDevice(&dev) == cudaSuccess &&
            cudaDeviceGetAttribute(&sms, cudaDevAttrMultiProcessorCount, dev) == cudaSuccess &&
            cudaOccupancyMaxActiveBlocksPerMultiprocessor(&maxb, agg_kernel, 256, 0) == cudaSuccess &&
            sms > 0 && maxb > 0) {
            agg_blocks = sms * maxb;
        }
    }

    cudaStream_t sG;
    cudaStreamCreateWithFlags(&sG, cudaStreamNonBlocking);
    cudaEvent_t evFork, evJoin;
    cudaEventCreateWithFlags(&evFork, cudaEventDisableTiming);
    cudaEventCreateWithFlags(&evJoin, cudaEventDisableTiming);

    const int gemm_blocks = (NODES + 127) / 128;   // 391

    cudaEventRecord(evFork, 0);
    cudaStreamWaitEvent(sG, evFork, 0);

    // default stream: CSR build chain
    zero_init_kernel<<<(NODES + 255) / 256, 256>>>(out);          // 1
    deg_count_kernel<<<(NE + 255) / 256, 256>>>(ei, ew);          // 2
    // sG: weight split + gemm0 + we-sums
    bsplit_kernel<<<256, 256, 0, sG>>>(conv_w, l1w);              // 3
    tgemm_kernel<<<gemm_blocks, 256, TG_SMEM, sG>>>(x, conv_b, 0, -1, NODES); // 4 <- ncu
    prep_we_kernel<<<1, 128, 0, sG>>>(l1w);                       // 5
    scan_kernel2<<<NSB, SBLK>>>();                                // 6
    csr_fill_kernel<<<(NE + 255) / 256, 256>>>(ei, ew);           // 7

    cudaEventRecord(evJoin, sG);
    cudaStreamWaitEvent(0, evJoin, 0);

    agg_kernel<<<agg_blocks, 256>>>(0, l1w, l1b, curr);
    tgemm_kernel<<<gemm_blocks, 256, TG_SMEM>>>(x, conv_b + HID, 1, 0, NODES);
    agg_kernel<<<agg_blocks, 256>>>(1, l1w, l1b, curr);
    tgemm_kernel<<<gemm_blocks, 256, TG_SMEM>>>(x, conv_b + 2 * HID, 2, 1, NODES);
    agg_kernel<<<agg_blocks, 256>>>(2, l1w, l1b, curr);   // folds prep_base in last block

    score_kernel<<<gemm_blocks, 256, SC_SMEM>>>(l2w, l2b, ecn, parts, h, out);
}